// round 1
// baseline (speedup 1.0000x reference)
#include <cuda_runtime.h>

#define DIM 512
#define THREE_DIM 1536
#define NPIX 1024
#define BATCH 8
#define HEADS 8
#define HD 64
#define SMOOTHF 1e-4f
#define BN_EPSF 1e-5f

// ---------------- scratch (static __device__, no allocation) ----------------
__device__ float g_Wt[9 * DIM * THREE_DIM];        // [kpos*512+ci][co]  (28.3 MB)
__device__ float g_WoutT[DIM * DIM];               // [ci][co]
__device__ float g_qkv[BATCH * THREE_DIM * NPIX];  // (50.3 MB)
__device__ float g_invqn[BATCH * HEADS * NPIX];
__device__ float g_invkn[BATCH * HEADS * NPIX];
__device__ float g_attnout[BATCH * DIM * NPIX];    // (16.8 MB)
__device__ float g_conv2[BATCH * DIM * NPIX];      // (16.8 MB)
__device__ float g_scale[DIM];
__device__ float g_shift[DIM];

// ---------------- weight transposes -----------------------------------------
__global__ void k_transpose_wqkv(const float* __restrict__ W) {
    int idx = blockIdx.x * 256 + threadIdx.x;
    if (idx >= THREE_DIM * DIM * 9) return;
    int co = idx / (DIM * 9);
    int rem = idx - co * (DIM * 9);
    int ci = rem / 9;
    int kpos = rem - ci * 9;
    g_Wt[(kpos * DIM + ci) * THREE_DIM + co] = W[idx];
}

__global__ void k_transpose_wout(const float* __restrict__ W) {
    int idx = blockIdx.x * 256 + threadIdx.x;
    if (idx >= DIM * DIM) return;
    int co = idx >> 9, ci = idx & 511;
    g_WoutT[ci * DIM + co] = W[idx];
}

// ---------------- conv 3x3 as GEMM: qkv[b][co][p] ----------------------------
// C[1536,1024] = Wt[4608,1536]^T * im2col(x)[4608,1024] per batch.
// 128x128 tile, BK=8, 256 threads, 8x8 microtile.
__global__ __launch_bounds__(256) void k_conv3x3(const float* __restrict__ x) {
    __shared__ float As[8][128];
    __shared__ float Bs[8][128];
    int b = blockIdx.z;
    int co0 = blockIdx.y * 128;
    int p0 = blockIdx.x * 128;
    int tid = threadIdx.x;
    int tx = tid & 15, ty = tid >> 4;
    int lr = tid >> 5;            // 0..7   (k row)
    int lc = (tid & 31) << 2;     // 0..124 (col, float4)
    const float* xb = x + b * DIM * NPIX;

    float acc[8][8];
#pragma unroll
    for (int i = 0; i < 8; i++)
#pragma unroll
        for (int j = 0; j < 8; j++) acc[i][j] = 0.f;

    for (int kt = 0; kt < 9 * DIM; kt += 8) {
        int kpos = kt >> 9;
        int kh = kpos / 3 - 1;
        int kw = kpos - (kpos / 3) * 3 - 1;
        int ci0 = kt & (DIM - 1);
        // A tile (coalesced)
        *(float4*)&As[lr][lc] = *(const float4*)&g_Wt[(kt + lr) * THREE_DIM + co0 + lc];
        // B tile: shifted x with zero padding
        {
            const float* xc = xb + (ci0 + lr) * NPIX;
#pragma unroll
            for (int u = 0; u < 4; u++) {
                int p = p0 + lc + u;
                int h = (p >> 5) + kh;
                int w = (p & 31) + kw;
                float v = 0.f;
                if ((unsigned)h < 32u && (unsigned)w < 32u) v = xc[(h << 5) + w];
                Bs[lr][lc + u] = v;
            }
        }
        __syncthreads();
#pragma unroll
        for (int kk = 0; kk < 8; kk++) {
            float a[8], bb[8];
            *(float4*)&a[0]  = *(const float4*)&As[kk][ty * 8];
            *(float4*)&a[4]  = *(const float4*)&As[kk][ty * 8 + 4];
            *(float4*)&bb[0] = *(const float4*)&Bs[kk][tx * 8];
            *(float4*)&bb[4] = *(const float4*)&Bs[kk][tx * 8 + 4];
#pragma unroll
            for (int i = 0; i < 8; i++)
#pragma unroll
                for (int j = 0; j < 8; j++)
                    acc[i][j] = fmaf(a[i], bb[j], acc[i][j]);
        }
        __syncthreads();
    }
    float* out = g_qkv + ((size_t)b * THREE_DIM + co0) * NPIX + p0;
#pragma unroll
    for (int i = 0; i < 8; i++) {
        float4 v0 = make_float4(acc[i][0], acc[i][1], acc[i][2], acc[i][3]);
        float4 v1 = make_float4(acc[i][4], acc[i][5], acc[i][6], acc[i][7]);
        *(float4*)&out[(ty * 8 + i) * NPIX + tx * 8]     = v0;
        *(float4*)&out[(ty * 8 + i) * NPIX + tx * 8 + 4] = v1;
    }
}

// ---------------- q/k inverse norms ------------------------------------------
__global__ void k_norms(void) {
    int idx = blockIdx.x * 256 + threadIdx.x;   // (b*8+g)*1024 + i
    int i = idx & 1023;
    int bg = idx >> 10;
    int b = bg >> 3, g = bg & 7;
    const float* qp = g_qkv + ((size_t)b * THREE_DIM + g * HD) * NPIX + i;
    const float* kp = qp + (size_t)DIM * NPIX;
    float sq = 0.f, sk = 0.f;
#pragma unroll 8
    for (int d = 0; d < HD; d++) {
        float vq = qp[d * NPIX]; sq = fmaf(vq, vq, sq);
        float vk = kp[d * NPIX]; sk = fmaf(vk, vk, sk);
    }
    g_invqn[idx] = rsqrtf(sq + SMOOTHF);
    g_invkn[idx] = rsqrtf(sk + SMOOTHF);
}

// ---------------- fused attention --------------------------------------------
// Per (b, g): O[i][d] = sum_j (q_i.k_j) / (qn_i*kn_j + eps) * v[j][d]
// 1/(a+eps) ~= t - eps*t^2, t = (1/qn)(1/kn)  (error ~1e-12, a >> eps here)
#define ATT_SMEM_BYTES ((4096 + 4096 + 64 * 65 + 4096 + 64 + 64) * 4)
__global__ __launch_bounds__(256) void k_attn(void) {
    extern __shared__ float sm[];
    float* Qs  = sm;               // [64][64]  d-major
    float* Ks  = Qs + 4096;        // [64][64]  d-major
    float* Vs  = Ks + 4096;        // [64][65]  d-major, padded
    float* Ss  = Vs + 64 * 65;     // [64][64]  i-major
    float* iqn = Ss + 4096;        // [64]
    float* ikn = iqn + 64;         // [64]

    int tid = threadIdx.x;
    int i0 = blockIdx.x * 64;
    int g = blockIdx.y;
    int b = blockIdx.z;
    int tx = tid & 15, ty = tid >> 4;

    const float* qbase = g_qkv + ((size_t)b * THREE_DIM + g * HD) * NPIX;
    const float* kbase = qbase + (size_t)DIM * NPIX;
    const float* vbase = qbase + (size_t)2 * DIM * NPIX;
    const float* iqg = g_invqn + ((b * 8 + g) << 10);
    const float* ikg = g_invkn + ((b * 8 + g) << 10);

#pragma unroll
    for (int u = 0; u < 16; u++) {
        int idx = tid + u * 256;
        int d = idx >> 6, ii = idx & 63;
        Qs[idx] = qbase[d * NPIX + i0 + ii];
    }
    if (tid < 64) iqn[tid] = iqg[i0 + tid];

    float oacc[4][4];
#pragma unroll
    for (int r = 0; r < 4; r++)
#pragma unroll
        for (int c = 0; c < 4; c++) oacc[r][c] = 0.f;

    for (int jt = 0; jt < 16; jt++) {
        int j0 = jt * 64;
        __syncthreads();   // protects Ks/Vs/Ss reuse from previous iteration (and Qs load on jt=0)
#pragma unroll
        for (int u = 0; u < 16; u++) {
            int idx = tid + u * 256;
            int d = idx >> 6, jj = idx & 63;
            Ks[idx] = kbase[d * NPIX + j0 + jj];
            Vs[d * 65 + jj] = vbase[d * NPIX + j0 + jj];
        }
        if (tid < 64) ikn[tid] = ikg[j0 + tid];
        __syncthreads();

        // S = Q^T K  (k = d = 64)
        float s[4][4];
#pragma unroll
        for (int r = 0; r < 4; r++)
#pragma unroll
            for (int c = 0; c < 4; c++) s[r][c] = 0.f;
#pragma unroll 8
        for (int d = 0; d < 64; d++) {
            float a[4], bb[4];
            *(float4*)a  = *(const float4*)&Qs[d * 64 + ty * 4];
            *(float4*)bb = *(const float4*)&Ks[d * 64 + tx * 4];
#pragma unroll
            for (int r = 0; r < 4; r++)
#pragma unroll
                for (int c = 0; c < 4; c++)
                    s[r][c] = fmaf(a[r], bb[c], s[r][c]);
        }
        // scale and stage S
        float iq[4], ik[4];
#pragma unroll
        for (int r = 0; r < 4; r++) iq[r] = iqn[ty * 4 + r];
#pragma unroll
        for (int c = 0; c < 4; c++) ik[c] = ikn[tx * 4 + c];
#pragma unroll
        for (int r = 0; r < 4; r++)
#pragma unroll
            for (int c = 0; c < 4; c++) {
                float t = iq[r] * ik[c];
                float u = s[r][c] * t;
                Ss[(ty * 4 + r) * 64 + tx * 4 + c] = fmaf(-SMOOTHF * t, u, u);
            }
        __syncthreads();

        // O[i][dd] += S[i][j] * Vs[dd][j]
#pragma unroll 4
        for (int j = 0; j < 64; j++) {
            float a[4], bb[4];
#pragma unroll
            for (int r = 0; r < 4; r++) a[r] = Ss[(ty * 4 + r) * 64 + j];
#pragma unroll
            for (int c = 0; c < 4; c++) bb[c] = Vs[(tx * 4 + c) * 65 + j];
#pragma unroll
            for (int r = 0; r < 4; r++)
#pragma unroll
                for (int c = 0; c < 4; c++)
                    oacc[r][c] = fmaf(a[r], bb[c], oacc[r][c]);
        }
    }

    // stage O through smem for coalesced global writes (reuse Vs)
    __syncthreads();
#pragma unroll
    for (int r = 0; r < 4; r++)
#pragma unroll
        for (int c = 0; c < 4; c++)
            Vs[(4 * tx + c) * 65 + 4 * ty + r] = oacc[r][c];
    __syncthreads();
    float* outb = g_attnout + ((size_t)b * DIM + g * HD) * NPIX + i0;
#pragma unroll
    for (int u = 0; u < 16; u++) {
        int idx = tid + u * 256;
        int dd = idx >> 6, ii = idx & 63;
        outb[dd * NPIX + ii] = Vs[dd * 65 + ii];
    }
}

// ---------------- conv 1x1 as GEMM -------------------------------------------
__global__ __launch_bounds__(256) void k_conv1x1(void) {
    __shared__ float As[8][128];
    __shared__ float Bs[8][128];
    int b = blockIdx.z;
    int co0 = blockIdx.y * 128;
    int p0 = blockIdx.x * 128;
    int tid = threadIdx.x;
    int tx = tid & 15, ty = tid >> 4;
    int lr = tid >> 5, lc = (tid & 31) << 2;
    const float* Bbase = g_attnout + (size_t)b * DIM * NPIX;

    float acc[8][8];
#pragma unroll
    for (int i = 0; i < 8; i++)
#pragma unroll
        for (int j = 0; j < 8; j++) acc[i][j] = 0.f;

    for (int k0 = 0; k0 < DIM; k0 += 8) {
        *(float4*)&As[lr][lc] = *(const float4*)&g_WoutT[(k0 + lr) * DIM + co0 + lc];
        *(float4*)&Bs[lr][lc] = *(const float4*)&Bbase[(k0 + lr) * NPIX + p0 + lc];
        __syncthreads();
#pragma unroll
        for (int kk = 0; kk < 8; kk++) {
            float a[8], bb[8];
            *(float4*)&a[0]  = *(const float4*)&As[kk][ty * 8];
            *(float4*)&a[4]  = *(const float4*)&As[kk][ty * 8 + 4];
            *(float4*)&bb[0] = *(const float4*)&Bs[kk][tx * 8];
            *(float4*)&bb[4] = *(const float4*)&Bs[kk][tx * 8 + 4];
#pragma unroll
            for (int i = 0; i < 8; i++)
#pragma unroll
                for (int j = 0; j < 8; j++)
                    acc[i][j] = fmaf(a[i], bb[j], acc[i][j]);
        }
        __syncthreads();
    }
    float* out = g_conv2 + ((size_t)b * DIM + co0) * NPIX + p0;
#pragma unroll
    for (int i = 0; i < 8; i++) {
        float4 v0 = make_float4(acc[i][0], acc[i][1], acc[i][2], acc[i][3]);
        float4 v1 = make_float4(acc[i][4], acc[i][5], acc[i][6], acc[i][7]);
        *(float4*)&out[(ty * 8 + i) * NPIX + tx * 8]     = v0;
        *(float4*)&out[(ty * 8 + i) * NPIX + tx * 8 + 4] = v1;
    }
}

// ---------------- BN statistics ----------------------------------------------
__global__ void k_bnstats(const float* __restrict__ gamma,
                          const float* __restrict__ beta) {
    int c = blockIdx.x;
    int tid = threadIdx.x;
    float s = 0.f, s2 = 0.f;
    for (int b = 0; b < BATCH; b++) {
        const float* p = g_conv2 + ((size_t)b * DIM + c) * NPIX;
        for (int i = tid; i < NPIX; i += 256) {
            float v = p[i];
            s += v;
            s2 = fmaf(v, v, s2);
        }
    }
#pragma unroll
    for (int off = 16; off; off >>= 1) {
        s  += __shfl_down_sync(0xffffffffu, s, off);
        s2 += __shfl_down_sync(0xffffffffu, s2, off);
    }
    __shared__ float sh[16];
    int w = tid >> 5, l = tid & 31;
    if (l == 0) { sh[w] = s; sh[w + 8] = s2; }
    __syncthreads();
    if (tid == 0) {
        float ts = 0.f, ts2 = 0.f;
#pragma unroll
        for (int i = 0; i < 8; i++) { ts += sh[i]; ts2 += sh[i + 8]; }
        float mean = ts * (1.f / 8192.f);
        float var = ts2 * (1.f / 8192.f) - mean * mean;
        float rstd = rsqrtf(var + BN_EPSF);
        float sc = gamma[c] * rstd;
        g_scale[c] = sc;
        g_shift[c] = beta[c] - mean * sc;
    }
}

// ---------------- BN apply + ReLU --------------------------------------------
__global__ void k_bn_relu(float* __restrict__ out) {
    int idx = blockIdx.x * 256 + threadIdx.x;
    if (idx >= BATCH * DIM * NPIX) return;
    int c = (idx >> 10) & 511;
    float v = fmaf(g_conv2[idx], g_scale[c], g_shift[c]);
    out[idx] = v > 0.f ? v : 0.f;
}

// ---------------- launch ------------------------------------------------------
extern "C" void kernel_launch(void* const* d_in, const int* in_sizes, int n_in,
                              void* d_out, int out_size) {
    const float* x      = (const float*)d_in[0];
    const float* W_qkv  = (const float*)d_in[1];
    const float* W_out  = (const float*)d_in[2];
    const float* gamma  = (const float*)d_in[3];
    const float* beta   = (const float*)d_in[4];
    float* out = (float*)d_out;

    k_transpose_wqkv<<<(THREE_DIM * DIM * 9 + 255) / 256, 256>>>(W_qkv);
    k_transpose_wout<<<(DIM * DIM + 255) / 256, 256>>>(W_out);
    k_conv3x3<<<dim3(8, 12, BATCH), 256>>>(x);
    k_norms<<<(BATCH * HEADS * NPIX) / 256, 256>>>();
    cudaFuncSetAttribute(k_attn, cudaFuncAttributeMaxDynamicSharedMemorySize,
                         ATT_SMEM_BYTES);
    k_attn<<<dim3(16, HEADS, BATCH), 256, ATT_SMEM_BYTES>>>();
    k_conv1x1<<<dim3(8, 4, BATCH), 256>>>();
    k_bnstats<<<DIM, 256>>>(gamma, beta);
    k_bn_relu<<<(BATCH * DIM * NPIX + 255) / 256, 256>>>(out);
}

// round 7
// speedup vs baseline: 2.5084x; 2.5084x over previous
#include <cuda_runtime.h>
#include <cuda_bf16.h>
#include <cstdint>

#define DIM 512
#define THREE_DIM 1536
#define NPIX 1024
#define BATCH 8
#define HEADS 8
#define HD 64
#define SMOOTHF 1e-4f
#define BN_EPSF 1e-5f

// ---------------- scratch (static __device__, no allocation) ----------------
__device__ float g_qkv[BATCH * THREE_DIM * NPIX];   // [b][c3][p]
__device__ float g_WoutT[DIM * DIM];                // [ci][co]
__device__ float g_invqn[BATCH * HEADS * NPIX];
__device__ float g_invkn[BATCH * HEADS * NPIX];
__device__ float g_attnout[BATCH * DIM * NPIX];
__device__ float g_conv2[BATCH * DIM * NPIX];
__device__ float g_scale[DIM];
__device__ float g_shift[DIM];
// bf16 split operands for conv3x3
__device__ __nv_bfloat16 g_xThi[BATCH * NPIX * DIM];        // [b][p][ci]
__device__ __nv_bfloat16 g_xTlo[BATCH * NPIX * DIM];
__device__ __nv_bfloat16 g_Wrhi[9 * THREE_DIM * DIM];       // [kpos][co][ci]
__device__ __nv_bfloat16 g_Wrlo[9 * THREE_DIM * DIM];

// ---------------- helpers ----------------------------------------------------
__device__ __forceinline__ uint32_t s2u(const void* p) {
    uint32_t a;
    asm("{ .reg .u64 t; cvta.to.shared.u64 t, %1; cvt.u32.u64 %0, t; }"
        : "=r"(a) : "l"(p));
    return a;
}
__device__ __forceinline__ void cp_async16(uint32_t saddr, const void* gaddr, int sz) {
    asm volatile("cp.async.cg.shared.global [%0], [%1], 16, %2;"
                 :: "r"(saddr), "l"(gaddr), "r"(sz));
}
__device__ __forceinline__ void cp_commit() {
    asm volatile("cp.async.commit_group;" ::: "memory");
}
__device__ __forceinline__ void cp_wait0() {
    asm volatile("cp.async.wait_group 0;" ::: "memory");
}
__device__ __forceinline__ void ldsm_x4(uint32_t* r, uint32_t addr) {
    asm volatile("ldmatrix.sync.aligned.m8n8.x4.shared.b16 {%0,%1,%2,%3}, [%4];"
                 : "=r"(r[0]), "=r"(r[1]), "=r"(r[2]), "=r"(r[3]) : "r"(addr));
}
__device__ __forceinline__ void mma_bf16(float* d, const uint32_t* a,
                                         const uint32_t* b) {
    asm volatile(
        "mma.sync.aligned.m16n8k16.row.col.f32.bf16.bf16.f32 "
        "{%0,%1,%2,%3}, {%4,%5,%6,%7}, {%8,%9}, {%0,%1,%2,%3};"
        : "+f"(d[0]), "+f"(d[1]), "+f"(d[2]), "+f"(d[3])
        : "r"(a[0]), "r"(a[1]), "r"(a[2]), "r"(a[3]), "r"(b[0]), "r"(b[1]));
}

// ---------------- prep: x -> [b][p][ci] bf16 hi/lo ----------------------------
__global__ void k_prep_x(const float* __restrict__ x) {
    __shared__ float t[32][33];
    int b = blockIdx.z, c0 = blockIdx.y * 32, p0 = blockIdx.x * 32;
    int tx = threadIdx.x, ty = threadIdx.y;  // 32 x 8
    const float* xb = x + ((size_t)b * DIM + c0) * NPIX + p0;
#pragma unroll
    for (int u = 0; u < 4; u++) t[ty + u * 8][tx] = xb[(ty + u * 8) * NPIX + tx];
    __syncthreads();
    size_t ob = ((size_t)b * NPIX + p0) * DIM + c0;
#pragma unroll
    for (int u = 0; u < 4; u++) {
        int p = ty + u * 8;
        float v = t[tx][p];
        __nv_bfloat16 hi = __float2bfloat16(v);
        __nv_bfloat16 lo = __float2bfloat16(v - __bfloat162float(hi));
        g_xThi[ob + (size_t)p * DIM + tx] = hi;
        g_xTlo[ob + (size_t)p * DIM + tx] = lo;
    }
}

// ---------------- prep: W_qkv -> [kpos][co][ci] bf16 hi/lo --------------------
__global__ void k_prep_w(const float* __restrict__ W) {
    __shared__ float s[4608];
    int co = blockIdx.x;
    const float* wr = W + (size_t)co * 4608;
    for (int i = threadIdx.x; i < 4608; i += 256) s[i] = wr[i];
    __syncthreads();
    for (int kpos = 0; kpos < 9; kpos++) {
        size_t ob = ((size_t)kpos * THREE_DIM + co) * DIM;
        for (int ci = threadIdx.x; ci < DIM; ci += 256) {
            float v = s[ci * 9 + kpos];
            __nv_bfloat16 hi = __float2bfloat16(v);
            g_Wrhi[ob + ci] = hi;
            g_Wrlo[ob + ci] = __float2bfloat16(v - __bfloat162float(hi));
        }
    }
}

__global__ void k_transpose_wout(const float* __restrict__ W) {
    int idx = blockIdx.x * 256 + threadIdx.x;
    if (idx >= DIM * DIM) return;
    int co = idx >> 9, ci = idx & 511;
    g_WoutT[ci * DIM + co] = W[idx];
}

// ---------------- conv3x3 via mma.sync bf16 (fallback HMMA path) -------------
// D[p 128][co 128] = sum over (kpos, ci) A[p][k] * B[co][k]; bf16 split, 3 terms.
// Tiles: BM=128(p) BN=128(co) BK=64. 8 warps: wm in {0,1} (64 rows), wn in
// {0..3} (32 cols). Stage = 4 sub-tiles (Ahi, Alo, Bhi, Blo), each 128x128B,
// 16B chunks xor-swizzled by row for conflict-free ldmatrix.
#define STAGE_BYTES 65536
#define OFF_AHI 0
#define OFF_ALO 16384
#define OFF_BHI 32768
#define OFF_BLO 49152
#define CONV_SMEM (2 * STAGE_BYTES)

__global__ __launch_bounds__(256) void k_conv3x3_mma(void) {
    extern __shared__ char smem[];
    const uint32_t sb = s2u(smem);
    const int tid = threadIdx.x;
    const int wid = tid >> 5, lane = tid & 31;
    const int b = blockIdx.z, co0 = blockIdx.y * 128, p0 = blockIdx.x * 128;
    const int wm = wid & 1, wn = wid >> 1;

    float acc[4][4][4];
#pragma unroll
    for (int i = 0; i < 4; i++)
#pragma unroll
        for (int j = 0; j < 4; j++)
#pragma unroll
            for (int q = 0; q < 4; q++) acc[i][j][q] = 0.f;

    // ---- async tile loader for chunk c into buffer buf ----
    auto issue = [&](int c, int buf) {
        int kpos = c >> 3, ci0 = (c & 7) << 6;
        int kh = kpos / 3 - 1, kw = kpos % 3 - 1;
        uint32_t S = sb + buf * STAGE_BYTES;
#pragma unroll
        for (int u = 0; u < 4; u++) {
            int unit = tid + u * 256;            // 0..1023
            int row = unit >> 3, ch = unit & 7;  // 128 rows x 8 chunks(16B)
            int sw = row * 128 + ((ch ^ (row & 7)) << 4);
            // A rows: output pixel p0+row shifted by (kh,kw)
            int p = p0 + row;
            int h = (p >> 5) + kh, w = (p & 31) + kw;
            bool valid = ((unsigned)h < 32u) && ((unsigned)w < 32u);
            size_t offA = valid
                ? (((((size_t)b << 10) + ((h << 5) + w)) << 9) + ci0 + (ch << 3))
                : 0;
            int sz = valid ? 16 : 0;
            cp_async16(S + OFF_AHI + sw, (const char*)g_xThi + offA * 2, sz);
            cp_async16(S + OFF_ALO + sw, (const char*)g_xTlo + offA * 2, sz);
            // B rows: co0+row
            size_t offB = (((size_t)kpos * THREE_DIM + co0 + row) << 9) + ci0 + (ch << 3);
            cp_async16(S + OFF_BHI + sw, (const char*)g_Wrhi + offB * 2, 16);
            cp_async16(S + OFF_BLO + sw, (const char*)g_Wrlo + offB * 2, 16);
        }
        cp_commit();
    };

    issue(0, 0);
    for (int c = 0; c < 72; c++) {
        int buf = c & 1;
        cp_wait0();
        __syncthreads();
        if (c + 1 < 72) issue(c + 1, buf ^ 1);

        uint32_t S = sb + buf * STAGE_BYTES;
        // precomputed per-lane pieces
        int rowA_lo = wm * 64 + (lane & 15);     // + mi*16
        int kc8A = lane >> 4;                    // 0/1
        int rowB_lo = wn * 32 + ((lane >> 4) << 3) + (lane & 7);  // + t*16
        int kc8B = (lane >> 3) & 1;
#pragma unroll
        for (int k16 = 0; k16 < 4; k16++) {
            uint32_t ah[4][4], al[4][4], bh[2][4], bl[2][4];
#pragma unroll
            for (int mi = 0; mi < 4; mi++) {
                int row = rowA_lo + mi * 16;
                int ch = k16 * 2 + kc8A;
                uint32_t ad = S + row * 128 + ((ch ^ (row & 7)) << 4);
                ldsm_x4(ah[mi], ad + OFF_AHI);
                ldsm_x4(al[mi], ad + OFF_ALO);
            }
#pragma unroll
            for (int t = 0; t < 2; t++) {
                int row = rowB_lo + t * 16;
                int ch = k16 * 2 + kc8B;
                uint32_t ad = S + row * 128 + ((ch ^ (row & 7)) << 4);
                ldsm_x4(bh[t], ad + OFF_BHI);
                ldsm_x4(bl[t], ad + OFF_BLO);
            }
#pragma unroll
            for (int mi = 0; mi < 4; mi++)
#pragma unroll
                for (int nj = 0; nj < 4; nj++) {
                    const uint32_t* bhf = &bh[nj >> 1][(nj & 1) * 2];
                    const uint32_t* blf = &bl[nj >> 1][(nj & 1) * 2];
                    mma_bf16(acc[mi][nj], ah[mi], bhf);   // hi*hi
                    mma_bf16(acc[mi][nj], ah[mi], blf);   // hi*lo
                    mma_bf16(acc[mi][nj], al[mi], bhf);   // lo*hi
                }
        }
    }
    __syncthreads();

    // ---- epilogue: frags -> smem T[p][co] (pad 132) -> g_qkv[co][p] ----------
    float* T = (float*)smem;
#pragma unroll
    for (int mi = 0; mi < 4; mi++)
#pragma unroll
        for (int nj = 0; nj < 4; nj++) {
            int row = wm * 64 + mi * 16 + (lane >> 2);
            int col = wn * 32 + nj * 8 + (lane & 3) * 2;
            T[row * 132 + col]           = acc[mi][nj][0];
            T[row * 132 + col + 1]       = acc[mi][nj][1];
            T[(row + 8) * 132 + col]     = acc[mi][nj][2];
            T[(row + 8) * 132 + col + 1] = acc[mi][nj][3];
        }
    __syncthreads();
    float* outbase = g_qkv + ((size_t)b * THREE_DIM + co0) * NPIX + p0;
#pragma unroll
    for (int t = 0; t < 16; t++) {
        int cc = wid + t * 8;          // co row within tile
        float4 v;
        v.x = T[(lane * 4 + 0) * 132 + cc];
        v.y = T[(lane * 4 + 1) * 132 + cc];
        v.z = T[(lane * 4 + 2) * 132 + cc];
        v.w = T[(lane * 4 + 3) * 132 + cc];
        *(float4*)(outbase + (size_t)cc * NPIX + lane * 4) = v;
    }
}

// ---------------- q/k inverse norms (unchanged, passing) ----------------------
__global__ void k_norms(void) {
    int idx = blockIdx.x * 256 + threadIdx.x;
    int i = idx & 1023;
    int bg = idx >> 10;
    int b = bg >> 3, g = bg & 7;
    const float* qp = g_qkv + ((size_t)b * THREE_DIM + g * HD) * NPIX + i;
    const float* kp = qp + (size_t)DIM * NPIX;
    float sq = 0.f, sk = 0.f;
#pragma unroll 8
    for (int d = 0; d < HD; d++) {
        float vq = qp[d * NPIX]; sq = fmaf(vq, vq, sq);
        float vk = kp[d * NPIX]; sk = fmaf(vk, vk, sk);
    }
    g_invqn[idx] = rsqrtf(sq + SMOOTHF);
    g_invkn[idx] = rsqrtf(sk + SMOOTHF);
}

// ---------------- fused attention (unchanged, passing) ------------------------
#define ATT_SMEM_BYTES ((4096 + 4096 + 64 * 65 + 4096 + 64 + 64) * 4)
__global__ __launch_bounds__(256) void k_attn(void) {
    extern __shared__ float sm[];
    float* Qs  = sm;
    float* Ks  = Qs + 4096;
    float* Vs  = Ks + 4096;
    float* Ss  = Vs + 64 * 65;
    float* iqn = Ss + 4096;
    float* ikn = iqn + 64;

    int tid = threadIdx.x;
    int i0 = blockIdx.x * 64;
    int g = blockIdx.y;
    int b = blockIdx.z;
    int tx = tid & 15, ty = tid >> 4;

    const float* qbase = g_qkv + ((size_t)b * THREE_DIM + g * HD) * NPIX;
    const float* kbase = qbase + (size_t)DIM * NPIX;
    const float* vbase = qbase + (size_t)2 * DIM * NPIX;
    const float* iqg = g_invqn + ((b * 8 + g) << 10);
    const float* ikg = g_invkn + ((b * 8 + g) << 10);

#pragma unroll
    for (int u = 0; u < 16; u++) {
        int idx = tid + u * 256;
        int d = idx >> 6, ii = idx & 63;
        Qs[idx] = qbase[d * NPIX + i0 + ii];
    }
    if (tid < 64) iqn[tid] = iqg[i0 + tid];

    float oacc[4][4];
#pragma unroll
    for (int r = 0; r < 4; r++)
#pragma unroll
        for (int c = 0; c < 4; c++) oacc[r][c] = 0.f;

    for (int jt = 0; jt < 16; jt++) {
        int j0 = jt * 64;
        __syncthreads();
#pragma unroll
        for (int u = 0; u < 16; u++) {
            int idx = tid + u * 256;
            int d = idx >> 6, jj = idx & 63;
            Ks[idx] = kbase[d * NPIX + j0 + jj];
            Vs[d * 65 + jj] = vbase[d * NPIX + j0 + jj];
        }
        if (tid < 64) ikn[tid] = ikg[j0 + tid];
        __syncthreads();

        float s[4][4];
#pragma unroll
        for (int r = 0; r < 4; r++)
#pragma unroll
            for (int c = 0; c < 4; c++) s[r][c] = 0.f;
#pragma unroll 8
        for (int d = 0; d < 64; d++) {
            float a[4], bb[4];
            *(float4*)a  = *(const float4*)&Qs[d * 64 + ty * 4];
            *(float4*)bb = *(const float4*)&Ks[d * 64 + tx * 4];
#pragma unroll
            for (int r = 0; r < 4; r++)
#pragma unroll
                for (int c = 0; c < 4; c++)
                    s[r][c] = fmaf(a[r], bb[c], s[r][c]);
        }
        float iq[4], ik[4];
#pragma unroll
        for (int r = 0; r < 4; r++) iq[r] = iqn[ty * 4 + r];
#pragma unroll
        for (int c = 0; c < 4; c++) ik[c] = ikn[tx * 4 + c];
#pragma unroll
        for (int r = 0; r < 4; r++)
#pragma unroll
            for (int c = 0; c < 4; c++) {
                float t = iq[r] * ik[c];
                float u = s[r][c] * t;
                Ss[(ty * 4 + r) * 64 + tx * 4 + c] = fmaf(-SMOOTHF * t, u, u);
            }
        __syncthreads();

#pragma unroll 4
        for (int j = 0; j < 64; j++) {
            float a[4], bb[4];
#pragma unroll
            for (int r = 0; r < 4; r++) a[r] = Ss[(ty * 4 + r) * 64 + j];
#pragma unroll
            for (int c = 0; c < 4; c++) bb[c] = Vs[(tx * 4 + c) * 65 + j];
#pragma unroll
            for (int r = 0; r < 4; r++)
#pragma unroll
                for (int c = 0; c < 4; c++)
                    oacc[r][c] = fmaf(a[r], bb[c], oacc[r][c]);
        }
    }

    __syncthreads();
#pragma unroll
    for (int r = 0; r < 4; r++)
#pragma unroll
        for (int c = 0; c < 4; c++)
            Vs[(4 * tx + c) * 65 + 4 * ty + r] = oacc[r][c];
    __syncthreads();
    float* outb = g_attnout + ((size_t)b * DIM + g * HD) * NPIX + i0;
#pragma unroll
    for (int u = 0; u < 16; u++) {
        int idx = tid + u * 256;
        int dd = idx >> 6, ii = idx & 63;
        outb[dd * NPIX + ii] = Vs[dd * 65 + ii];
    }
}

// ---------------- conv 1x1 (unchanged, passing) -------------------------------
__global__ __launch_bounds__(256) void k_conv1x1(void) {
    __shared__ float As[8][128];
    __shared__ float Bs[8][128];
    int b = blockIdx.z;
    int co0 = blockIdx.y * 128;
    int p0 = blockIdx.x * 128;
    int tid = threadIdx.x;
    int tx = tid & 15, ty = tid >> 4;
    int lr = tid >> 5, lc = (tid & 31) << 2;
    const float* Bbase = g_attnout + (size_t)b * DIM * NPIX;

    float acc[8][8];
#pragma unroll
    for (int i = 0; i < 8; i++)
#pragma unroll
        for (int j = 0; j < 8; j++) acc[i][j] = 0.f;

    for (int k0 = 0; k0 < DIM; k0 += 8) {
        *(float4*)&As[lr][lc] = *(const float4*)&g_WoutT[(k0 + lr) * DIM + co0 + lc];
        *(float4*)&Bs[lr][lc] = *(const float4*)&Bbase[(k0 + lr) * NPIX + p0 + lc];
        __syncthreads();
#pragma unroll
        for (int kk = 0; kk < 8; kk++) {
            float a[8], bb[8];
            *(float4*)&a[0]  = *(const float4*)&As[kk][ty * 8];
            *(float4*)&a[4]  = *(const float4*)&As[kk][ty * 8 + 4];
            *(float4*)&bb[0] = *(const float4*)&Bs[kk][tx * 8];
            *(float4*)&bb[4] = *(const float4*)&Bs[kk][tx * 8 + 4];
#pragma unroll
            for (int i = 0; i < 8; i++)
#pragma unroll
                for (int j = 0; j < 8; j++)
                    acc[i][j] = fmaf(a[i], bb[j], acc[i][j]);
        }
        __syncthreads();
    }
    float* out = g_conv2 + ((size_t)b * DIM + co0) * NPIX + p0;
#pragma unroll
    for (int i = 0; i < 8; i++) {
        float4 v0 = make_float4(acc[i][0], acc[i][1], acc[i][2], acc[i][3]);
        float4 v1 = make_float4(acc[i][4], acc[i][5], acc[i][6], acc[i][7]);
        *(float4*)&out[(ty * 8 + i) * NPIX + tx * 8]     = v0;
        *(float4*)&out[(ty * 8 + i) * NPIX + tx * 8 + 4] = v1;
    }
}

// ---------------- BN statistics (unchanged) -----------------------------------
__global__ void k_bnstats(const float* __restrict__ gamma,
                          const float* __restrict__ beta) {
    int c = blockIdx.x;
    int tid = threadIdx.x;
    float s = 0.f, s2 = 0.f;
    for (int b = 0; b < BATCH; b++) {
        const float* p = g_conv2 + ((size_t)b * DIM + c) * NPIX;
        for (int i = tid; i < NPIX; i += 256) {
            float v = p[i];
            s += v;
            s2 = fmaf(v, v, s2);
        }
    }
#pragma unroll
    for (int off = 16; off; off >>= 1) {
        s  += __shfl_down_sync(0xffffffffu, s, off);
        s2 += __shfl_down_sync(0xffffffffu, s2, off);
    }
    __shared__ float sh[16];
    int w = tid >> 5, l = tid & 31;
    if (l == 0) { sh[w] = s; sh[w + 8] = s2; }
    __syncthreads();
    if (tid == 0) {
        float ts = 0.f, ts2 = 0.f;
#pragma unroll
        for (int i = 0; i < 8; i++) { ts += sh[i]; ts2 += sh[i + 8]; }
        float mean = ts * (1.f / 8192.f);
        float var = ts2 * (1.f / 8192.f) - mean * mean;
        float rstd = rsqrtf(var + BN_EPSF);
        float sc = gamma[c] * rstd;
        g_scale[c] = sc;
        g_shift[c] = beta[c] - mean * sc;
    }
}

// ---------------- BN apply + ReLU (unchanged) ---------------------------------
__global__ void k_bn_relu(float* __restrict__ out) {
    int idx = blockIdx.x * 256 + threadIdx.x;
    if (idx >= BATCH * DIM * NPIX) return;
    int c = (idx >> 10) & 511;
    float v = fmaf(g_conv2[idx], g_scale[c], g_shift[c]);
    out[idx] = v > 0.f ? v : 0.f;
}

// ---------------- launch ------------------------------------------------------
extern "C" void kernel_launch(void* const* d_in, const int* in_sizes, int n_in,
                              void* d_out, int out_size) {
    const float* x      = (const float*)d_in[0];
    const float* W_qkv  = (const float*)d_in[1];
    const float* W_out  = (const float*)d_in[2];
    const float* gamma  = (const float*)d_in[3];
    const float* beta   = (const float*)d_in[4];
    float* out = (float*)d_out;

    k_prep_x<<<dim3(32, 16, BATCH), dim3(32, 8)>>>(x);
    k_prep_w<<<THREE_DIM, 256>>>(W_qkv);
    k_transpose_wout<<<(DIM * DIM + 255) / 256, 256>>>(W_out);

    cudaFuncSetAttribute(k_conv3x3_mma, cudaFuncAttributeMaxDynamicSharedMemorySize,
                         CONV_SMEM);
    k_conv3x3_mma<<<dim3(8, 12, BATCH), 256, CONV_SMEM>>>();

    k_norms<<<(BATCH * HEADS * NPIX) / 256, 256>>>();
    cudaFuncSetAttribute(k_attn, cudaFuncAttributeMaxDynamicSharedMemorySize,
                         ATT_SMEM_BYTES);
    k_attn<<<dim3(16, HEADS, BATCH), 256, ATT_SMEM_BYTES>>>();
    k_conv1x1<<<dim3(8, 4, BATCH), 256>>>();
    k_bnstats<<<DIM, 256>>>(gamma, beta);
    k_bn_relu<<<(BATCH * DIM * NPIX + 255) / 256, 256>>>(out);
}

// round 8
// speedup vs baseline: 3.2505x; 1.2958x over previous
#include <cuda_runtime.h>
#include <cuda_bf16.h>
#include <cstdint>

#define DIM 512
#define THREE_DIM 1536
#define NPIX 1024
#define BATCH 8
#define HEADS 8
#define HD 64
#define SMOOTHF 1e-4f
#define BN_EPSF 1e-5f

// ---------------- scratch (static __device__, no allocation) ----------------
__device__ float g_qkv[BATCH * THREE_DIM * NPIX];   // [b][c3][p]
__device__ float g_invqn[BATCH * HEADS * NPIX];
__device__ float g_invkn[BATCH * HEADS * NPIX];
__device__ float g_conv2[BATCH * NPIX * DIM];       // [b][p][c]  (NEW layout)
__device__ float g_scale[DIM];
__device__ float g_shift[DIM];
__device__ float g_part[2][64][DIM];                // BN partial sums
// bf16 split operands for conv3x3
__device__ __nv_bfloat16 g_xThi[BATCH * NPIX * DIM];        // [b][p][ci]
__device__ __nv_bfloat16 g_xTlo[BATCH * NPIX * DIM];
__device__ __nv_bfloat16 g_Wrhi[9 * THREE_DIM * DIM];       // [kpos][co][ci]
__device__ __nv_bfloat16 g_Wrlo[9 * THREE_DIM * DIM];
// bf16 split operands for attention (normalized q,k; raw v transposed)
__device__ __nv_bfloat16 g_qhi[64 * NPIX * HD];     // [bg][n][d]  (q * invqn)
__device__ __nv_bfloat16 g_qlo[64 * NPIX * HD];
__device__ __nv_bfloat16 g_khi[64 * NPIX * HD];     // [bg][n][d]  (k * invkn)
__device__ __nv_bfloat16 g_klo[64 * NPIX * HD];
__device__ __nv_bfloat16 g_vThi[64 * HD * NPIX];    // [bg][d][n]
__device__ __nv_bfloat16 g_vTlo[64 * HD * NPIX];
// attention output (conv1x1 A operand), bf16 split
__device__ __nv_bfloat16 g_Ahi[BATCH * NPIX * DIM]; // [b][p][c]
__device__ __nv_bfloat16 g_Alo[BATCH * NPIX * DIM];
// conv1x1 weights split
__device__ __nv_bfloat16 g_w2hi[DIM * DIM];         // [co][ci]
__device__ __nv_bfloat16 g_w2lo[DIM * DIM];

// ---------------- helpers ----------------------------------------------------
__device__ __forceinline__ uint32_t s2u(const void* p) {
    uint32_t a;
    asm("{ .reg .u64 t; cvta.to.shared.u64 t, %1; cvt.u32.u64 %0, t; }"
        : "=r"(a) : "l"(p));
    return a;
}
__device__ __forceinline__ void cp_async16(uint32_t saddr, const void* gaddr, int sz) {
    asm volatile("cp.async.cg.shared.global [%0], [%1], 16, %2;"
                 :: "r"(saddr), "l"(gaddr), "r"(sz));
}
__device__ __forceinline__ void cp_commit() {
    asm volatile("cp.async.commit_group;" ::: "memory");
}
__device__ __forceinline__ void cp_wait0() {
    asm volatile("cp.async.wait_group 0;" ::: "memory");
}
__device__ __forceinline__ void ldsm_x4(uint32_t* r, uint32_t addr) {
    asm volatile("ldmatrix.sync.aligned.m8n8.x4.shared.b16 {%0,%1,%2,%3}, [%4];"
                 : "=r"(r[0]), "=r"(r[1]), "=r"(r[2]), "=r"(r[3]) : "r"(addr));
}
__device__ __forceinline__ void mma_bf16(float* d, const uint32_t* a,
                                         const uint32_t* b) {
    asm volatile(
        "mma.sync.aligned.m16n8k16.row.col.f32.bf16.bf16.f32 "
        "{%0,%1,%2,%3}, {%4,%5,%6,%7}, {%8,%9}, {%0,%1,%2,%3};"
        : "+f"(d[0]), "+f"(d[1]), "+f"(d[2]), "+f"(d[3])
        : "r"(a[0]), "r"(a[1]), "r"(a[2]), "r"(a[3]), "r"(b[0]), "r"(b[1]));
}
__device__ __forceinline__ uint32_t pack_bf16x2(float a, float b) {
    __nv_bfloat162 h = __floats2bfloat162_rn(a, b);
    return *(uint32_t*)&h;
}

// ---------------- prep: x -> [b][p][ci] bf16 hi/lo ----------------------------
__global__ void k_prep_x(const float* __restrict__ x) {
    __shared__ float t[32][33];
    int b = blockIdx.z, c0 = blockIdx.y * 32, p0 = blockIdx.x * 32;
    int tx = threadIdx.x, ty = threadIdx.y;  // 32 x 8
    const float* xb = x + ((size_t)b * DIM + c0) * NPIX + p0;
#pragma unroll
    for (int u = 0; u < 4; u++) t[ty + u * 8][tx] = xb[(ty + u * 8) * NPIX + tx];
    __syncthreads();
    size_t ob = ((size_t)b * NPIX + p0) * DIM + c0;
#pragma unroll
    for (int u = 0; u < 4; u++) {
        int p = ty + u * 8;
        float v = t[tx][p];
        __nv_bfloat16 hi = __float2bfloat16(v);
        __nv_bfloat16 lo = __float2bfloat16(v - __bfloat162float(hi));
        g_xThi[ob + (size_t)p * DIM + tx] = hi;
        g_xTlo[ob + (size_t)p * DIM + tx] = lo;
    }
}

// ---------------- prep: W_qkv -> [kpos][co][ci] bf16 hi/lo --------------------
__global__ void k_prep_w(const float* __restrict__ W) {
    __shared__ float s[4608];
    int co = blockIdx.x;
    const float* wr = W + (size_t)co * 4608;
    for (int i = threadIdx.x; i < 4608; i += 256) s[i] = wr[i];
    __syncthreads();
    for (int kpos = 0; kpos < 9; kpos++) {
        size_t ob = ((size_t)kpos * THREE_DIM + co) * DIM;
        for (int ci = threadIdx.x; ci < DIM; ci += 256) {
            float v = s[ci * 9 + kpos];
            __nv_bfloat16 hi = __float2bfloat16(v);
            g_Wrhi[ob + ci] = hi;
            g_Wrlo[ob + ci] = __float2bfloat16(v - __bfloat162float(hi));
        }
    }
}

// ---------------- prep: W_out split ([co][ci], no transpose) ------------------
__global__ void k_split_wout(const float* __restrict__ W) {
    int idx = blockIdx.x * 256 + threadIdx.x;
    if (idx >= DIM * DIM) return;
    float v = W[idx];
    __nv_bfloat16 hi = __float2bfloat16(v);
    g_w2hi[idx] = hi;
    g_w2lo[idx] = __float2bfloat16(v - __bfloat162float(hi));
}

// ---------------- conv3x3 via mma.sync bf16 (unchanged, passing) --------------
#define STAGE_BYTES 65536
#define OFF_AHI 0
#define OFF_ALO 16384
#define OFF_BHI 32768
#define OFF_BLO 49152
#define CONV_SMEM (2 * STAGE_BYTES)

__global__ __launch_bounds__(256) void k_conv3x3_mma(void) {
    extern __shared__ char smem[];
    const uint32_t sb = s2u(smem);
    const int tid = threadIdx.x;
    const int wid = tid >> 5, lane = tid & 31;
    const int b = blockIdx.z, co0 = blockIdx.y * 128, p0 = blockIdx.x * 128;
    const int wm = wid & 1, wn = wid >> 1;

    float acc[4][4][4];
#pragma unroll
    for (int i = 0; i < 4; i++)
#pragma unroll
        for (int j = 0; j < 4; j++)
#pragma unroll
            for (int q = 0; q < 4; q++) acc[i][j][q] = 0.f;

    auto issue = [&](int c, int buf) {
        int kpos = c >> 3, ci0 = (c & 7) << 6;
        int kh = kpos / 3 - 1, kw = kpos % 3 - 1;
        uint32_t S = sb + buf * STAGE_BYTES;
#pragma unroll
        for (int u = 0; u < 4; u++) {
            int unit = tid + u * 256;
            int row = unit >> 3, ch = unit & 7;
            int sw = row * 128 + ((ch ^ (row & 7)) << 4);
            int p = p0 + row;
            int h = (p >> 5) + kh, w = (p & 31) + kw;
            bool valid = ((unsigned)h < 32u) && ((unsigned)w < 32u);
            size_t offA = valid
                ? (((((size_t)b << 10) + ((h << 5) + w)) << 9) + ci0 + (ch << 3))
                : 0;
            int sz = valid ? 16 : 0;
            cp_async16(S + OFF_AHI + sw, (const char*)g_xThi + offA * 2, sz);
            cp_async16(S + OFF_ALO + sw, (const char*)g_xTlo + offA * 2, sz);
            size_t offB = (((size_t)kpos * THREE_DIM + co0 + row) << 9) + ci0 + (ch << 3);
            cp_async16(S + OFF_BHI + sw, (const char*)g_Wrhi + offB * 2, 16);
            cp_async16(S + OFF_BLO + sw, (const char*)g_Wrlo + offB * 2, 16);
        }
        cp_commit();
    };

    issue(0, 0);
    for (int c = 0; c < 72; c++) {
        int buf = c & 1;
        cp_wait0();
        __syncthreads();
        if (c + 1 < 72) issue(c + 1, buf ^ 1);

        uint32_t S = sb + buf * STAGE_BYTES;
        int rowA_lo = wm * 64 + (lane & 15);
        int kc8A = lane >> 4;
        int rowB_lo = wn * 32 + ((lane >> 4) << 3) + (lane & 7);
        int kc8B = (lane >> 3) & 1;
#pragma unroll
        for (int k16 = 0; k16 < 4; k16++) {
            uint32_t ah[4][4], al[4][4], bh[2][4], bl[2][4];
#pragma unroll
            for (int mi = 0; mi < 4; mi++) {
                int row = rowA_lo + mi * 16;
                int ch = k16 * 2 + kc8A;
                uint32_t ad = S + row * 128 + ((ch ^ (row & 7)) << 4);
                ldsm_x4(ah[mi], ad + OFF_AHI);
                ldsm_x4(al[mi], ad + OFF_ALO);
            }
#pragma unroll
            for (int t = 0; t < 2; t++) {
                int row = rowB_lo + t * 16;
                int ch = k16 * 2 + kc8B;
                uint32_t ad = S + row * 128 + ((ch ^ (row & 7)) << 4);
                ldsm_x4(bh[t], ad + OFF_BHI);
                ldsm_x4(bl[t], ad + OFF_BLO);
            }
#pragma unroll
            for (int mi = 0; mi < 4; mi++)
#pragma unroll
                for (int nj = 0; nj < 4; nj++) {
                    const uint32_t* bhf = &bh[nj >> 1][(nj & 1) * 2];
                    const uint32_t* blf = &bl[nj >> 1][(nj & 1) * 2];
                    mma_bf16(acc[mi][nj], ah[mi], bhf);
                    mma_bf16(acc[mi][nj], ah[mi], blf);
                    mma_bf16(acc[mi][nj], al[mi], bhf);
                }
        }
    }
    __syncthreads();

    float* T = (float*)smem;
#pragma unroll
    for (int mi = 0; mi < 4; mi++)
#pragma unroll
        for (int nj = 0; nj < 4; nj++) {
            int row = wm * 64 + mi * 16 + (lane >> 2);
            int col = wn * 32 + nj * 8 + (lane & 3) * 2;
            T[row * 132 + col]           = acc[mi][nj][0];
            T[row * 132 + col + 1]       = acc[mi][nj][1];
            T[(row + 8) * 132 + col]     = acc[mi][nj][2];
            T[(row + 8) * 132 + col + 1] = acc[mi][nj][3];
        }
    __syncthreads();
    float* outbase = g_qkv + ((size_t)b * THREE_DIM + co0) * NPIX + p0;
#pragma unroll
    for (int t = 0; t < 16; t++) {
        int cc = wid + t * 8;
        float4 v;
        v.x = T[(lane * 4 + 0) * 132 + cc];
        v.y = T[(lane * 4 + 1) * 132 + cc];
        v.z = T[(lane * 4 + 2) * 132 + cc];
        v.w = T[(lane * 4 + 3) * 132 + cc];
        *(float4*)(outbase + (size_t)cc * NPIX + lane * 4) = v;
    }
}

// ---------------- q/k inverse norms ------------------------------------------
__global__ void k_norms(void) {
    int idx = blockIdx.x * 256 + threadIdx.x;
    int i = idx & 1023;
    int bg = idx >> 10;
    int b = bg >> 3, g = bg & 7;
    const float* qp = g_qkv + ((size_t)b * THREE_DIM + g * HD) * NPIX + i;
    const float* kp = qp + (size_t)DIM * NPIX;
    float sq = 0.f, sk = 0.f;
#pragma unroll 8
    for (int d = 0; d < HD; d++) {
        float vq = qp[d * NPIX]; sq = fmaf(vq, vq, sq);
        float vk = kp[d * NPIX]; sk = fmaf(vk, vk, sk);
    }
    g_invqn[idx] = rsqrtf(sq + SMOOTHF);
    g_invkn[idx] = rsqrtf(sk + SMOOTHF);
}

// ---------------- split q,k: normalize + transpose [d][n]->[n][d] + bf16 split
__global__ void k_split_qkv(void) {
    __shared__ float t[32][33];
    int n0 = blockIdx.x * 32, d0 = blockIdx.y * 32, bg = blockIdx.z;
    int b = bg >> 3, g = bg & 7;
    int tx = threadIdx.x, ty = threadIdx.y;  // 32 x 8
    const float* srcq = g_qkv + ((size_t)b * THREE_DIM + g * HD + d0) * NPIX + n0;
    // ---- q ----
#pragma unroll
    for (int u = 0; u < 4; u++)
        t[ty + u * 8][tx] = srcq[(size_t)(ty + u * 8) * NPIX + tx];
    __syncthreads();
#pragma unroll
    for (int u = 0; u < 4; u++) {
        int nl = ty + u * 8;
        int n = n0 + nl;
        float iv = g_invqn[((size_t)bg << 10) + n];
        float v = t[tx][nl] * iv;
        __nv_bfloat16 hi = __float2bfloat16(v);
        size_t o = (((size_t)bg << 10) + n) * HD + d0 + tx;
        g_qhi[o] = hi;
        g_qlo[o] = __float2bfloat16(v - __bfloat162float(hi));
    }
    __syncthreads();
    // ---- k ----
    const float* srck = srcq + (size_t)DIM * NPIX;
#pragma unroll
    for (int u = 0; u < 4; u++)
        t[ty + u * 8][tx] = srck[(size_t)(ty + u * 8) * NPIX + tx];
    __syncthreads();
#pragma unroll
    for (int u = 0; u < 4; u++) {
        int nl = ty + u * 8;
        int n = n0 + nl;
        float iv = g_invkn[((size_t)bg << 10) + n];
        float v = t[tx][nl] * iv;
        __nv_bfloat16 hi = __float2bfloat16(v);
        size_t o = (((size_t)bg << 10) + n) * HD + d0 + tx;
        g_khi[o] = hi;
        g_klo[o] = __float2bfloat16(v - __bfloat162float(hi));
    }
}

// ---------------- split v (keeps [d][n] layout) -------------------------------
__global__ void k_split_v(void) {
    int idx = blockIdx.x * 256 + threadIdx.x;   // 64*64*1024 total
    int bg = idx >> 16;
    int rem = idx & 65535;
    int d = rem >> 10, n = rem & 1023;
    int b = bg >> 3, g = bg & 7;
    float v = g_qkv[((size_t)b * THREE_DIM + 2 * DIM + g * HD + d) * NPIX + n];
    __nv_bfloat16 hi = __float2bfloat16(v);
    size_t o = ((size_t)bg * HD + d) * NPIX + n;
    g_vThi[o] = hi;
    g_vTlo[o] = __float2bfloat16(v - __bfloat162float(hi));
}

// ---------------- attention via mma.sync bf16 ---------------------------------
// Per (b,g,i-tile 128): S = Q̂ K̂^T (u = s*t), corrected u-eps*t*u, re-split to
// bf16, O += S_bf16 * V^T. j-tiles of 64, double-buffered K/V.
#define ATN_QHI 0
#define ATN_QLO 16384
#define ATN_K(buf)  (32768 + (buf) * 16384)   // Khi +0, Klo +8192
#define ATN_VT(buf) (65536 + (buf) * 16384)   // VThi +0, VTlo +8192
#define ATN_SHI 98304
#define ATN_SLO 114688
#define ATN_IQ 131072
#define ATN_IK 131584                          // + buf*256
#define ATN_SMEM 132096

__global__ __launch_bounds__(256, 1) void k_attn_mma(void) {
    extern __shared__ char smem[];
    const uint32_t sb = s2u(smem);
    const int tid = threadIdx.x, wid = tid >> 5, lane = tid & 31;
    const int i0 = blockIdx.x * 128;
    const int g = blockIdx.y, b = blockIdx.z;
    const int bg = b * 8 + g;
    const int wm = wid & 3, wn = wid >> 2;

    // ---- load Q tile (128 x 64, hi/lo) + iq ----
#pragma unroll
    for (int u = 0; u < 4; u++) {
        int unit = tid + u * 256;            // 1024: 128 rows x 8 ch
        int row = unit >> 3, ch = unit & 7;
        int sw = row * 128 + ((ch ^ (row & 7)) << 4);
        size_t go = (((size_t)bg << 10) + i0 + row) * 128 + ch * 16;
        cp_async16(sb + ATN_QHI + sw, (const char*)g_qhi + go, 16);
        cp_async16(sb + ATN_QLO + sw, (const char*)g_qlo + go, 16);
    }
    if (tid < 128)
        ((float*)(smem + ATN_IQ))[tid] = g_invqn[((size_t)bg << 10) + i0 + tid];
    cp_commit();

    auto issueKV = [&](int j0, int buf) {
#pragma unroll
        for (int u = 0; u < 8; u++) {
            int unit = tid + u * 256;        // 2048: 4 tensors x 64 rows x 8 ch
            int sel = unit >> 9;
            int r2 = (unit >> 3) & 63, ch = unit & 7;
            int sw = r2 * 128 + ((ch ^ (r2 & 7)) << 4);
            uint32_t dst;
            const char* src;
            if (sel == 0) {
                dst = sb + ATN_K(buf) + sw;
                src = (const char*)g_khi + (((size_t)bg << 10) + j0 + r2) * 128 + ch * 16;
            } else if (sel == 1) {
                dst = sb + ATN_K(buf) + 8192 + sw;
                src = (const char*)g_klo + (((size_t)bg << 10) + j0 + r2) * 128 + ch * 16;
            } else if (sel == 2) {
                dst = sb + ATN_VT(buf) + sw;
                src = (const char*)g_vThi + (((size_t)bg * HD + r2) * NPIX + j0) * 2 + ch * 16;
            } else {
                dst = sb + ATN_VT(buf) + 8192 + sw;
                src = (const char*)g_vTlo + (((size_t)bg * HD + r2) * NPIX + j0) * 2 + ch * 16;
            }
            cp_async16(dst, src, 16);
        }
        if (tid < 64)
            ((float*)(smem + ATN_IK + buf * 256))[tid] =
                g_invkn[((size_t)bg << 10) + j0 + tid];
        cp_commit();
    };
    issueKV(0, 0);

    float acco[2][4][4];
#pragma unroll
    for (int i = 0; i < 2; i++)
#pragma unroll
        for (int j = 0; j < 4; j++)
#pragma unroll
            for (int q = 0; q < 4; q++) acco[i][j][q] = 0.f;

    for (int jt = 0; jt < 16; jt++) {
        int buf = jt & 1;
        cp_wait0();
        __syncthreads();
        if (jt < 15) issueKV((jt + 1) * 64, buf ^ 1);

        // ---- S phase: S(128x64) = Q(128x64) . K^T ----
        float s[2][4][4];
#pragma unroll
        for (int i = 0; i < 2; i++)
#pragma unroll
            for (int j = 0; j < 4; j++)
#pragma unroll
                for (int q = 0; q < 4; q++) s[i][j][q] = 0.f;
        {
            uint32_t Qh = sb + ATN_QHI, Ql = sb + ATN_QLO;
            uint32_t Kh = sb + ATN_K(buf), Kl = Kh + 8192;
#pragma unroll
            for (int k16 = 0; k16 < 4; k16++) {
                uint32_t ah[2][4], al[2][4], bh[2][4], bl[2][4];
#pragma unroll
                for (int mi = 0; mi < 2; mi++) {
                    int row = wm * 32 + mi * 16 + (lane & 15);
                    int ch = k16 * 2 + (lane >> 4);
                    uint32_t ad = row * 128 + ((ch ^ (row & 7)) << 4);
                    ldsm_x4(ah[mi], Qh + ad);
                    ldsm_x4(al[mi], Ql + ad);
                }
#pragma unroll
                for (int t = 0; t < 2; t++) {
                    int row = wn * 32 + t * 16 + ((lane >> 4) << 3) + (lane & 7);
                    int ch = k16 * 2 + ((lane >> 3) & 1);
                    uint32_t ad = row * 128 + ((ch ^ (row & 7)) << 4);
                    ldsm_x4(bh[t], Kh + ad);
                    ldsm_x4(bl[t], Kl + ad);
                }
#pragma unroll
                for (int mi = 0; mi < 2; mi++)
#pragma unroll
                    for (int nj = 0; nj < 4; nj++) {
                        const uint32_t* bhf = &bh[nj >> 1][(nj & 1) * 2];
                        const uint32_t* blf = &bl[nj >> 1][(nj & 1) * 2];
                        mma_bf16(s[mi][nj], ah[mi], bhf);
                        mma_bf16(s[mi][nj], ah[mi], blf);
                        mma_bf16(s[mi][nj], al[mi], bhf);
                    }
            }
        }
        // ---- correction + re-split S into smem ----
        {
            const float* IQ = (const float*)(smem + ATN_IQ);
            const float* IK = (const float*)(smem + ATN_IK + buf * 256);
#pragma unroll
            for (int mi = 0; mi < 2; mi++) {
                int r0 = wm * 32 + mi * 16 + (lane >> 2);
                float iq0 = IQ[r0], iq1 = IQ[r0 + 8];
#pragma unroll
                for (int nj = 0; nj < 4; nj++) {
                    int col = wn * 32 + nj * 8 + (lane & 3) * 2;
                    float ik0 = IK[col], ik1 = IK[col + 1];
                    float* u = s[mi][nj];
                    float t00 = iq0 * ik0, t01 = iq0 * ik1;
                    float t10 = iq1 * ik0, t11 = iq1 * ik1;
                    float v0 = fmaf(-SMOOTHF * t00, u[0], u[0]);
                    float v1 = fmaf(-SMOOTHF * t01, u[1], u[1]);
                    float v2 = fmaf(-SMOOTHF * t10, u[2], u[2]);
                    float v3 = fmaf(-SMOOTHF * t11, u[3], u[3]);
                    // split + store (2 bf16 per u32)
                    __nv_bfloat162 h01 = __floats2bfloat162_rn(v0, v1);
                    float r0f = v0 - __bfloat162float(h01.x);
                    float r1f = v1 - __bfloat162float(h01.y);
                    __nv_bfloat162 h23 = __floats2bfloat162_rn(v2, v3);
                    float r2f = v2 - __bfloat162float(h23.x);
                    float r3f = v3 - __bfloat162float(h23.y);
                    int bo = col * 2;
                    int ch = bo >> 4, wi = bo & 15;
                    int a0 = r0 * 128 + ((ch ^ (r0 & 7)) << 4) + wi;
                    int a1 = (r0 + 8) * 128 + ((ch ^ ((r0 + 8) & 7)) << 4) + wi;
                    *(uint32_t*)(smem + ATN_SHI + a0) = *(uint32_t*)&h01;
                    *(uint32_t*)(smem + ATN_SHI + a1) = *(uint32_t*)&h23;
                    *(uint32_t*)(smem + ATN_SLO + a0) = pack_bf16x2(r0f, r1f);
                    *(uint32_t*)(smem + ATN_SLO + a1) = pack_bf16x2(r2f, r3f);
                }
            }
        }
        __syncthreads();
        // ---- O phase: O(128x64) += S(128x64) . V^T(64x64) ----
        {
            uint32_t Sh = sb + ATN_SHI, Sl = sb + ATN_SLO;
            uint32_t Vh = sb + ATN_VT(buf), Vl = Vh + 8192;
#pragma unroll
            for (int k16 = 0; k16 < 4; k16++) {
                uint32_t ah[2][4], al[2][4], bh[2][4], bl[2][4];
#pragma unroll
                for (int mi = 0; mi < 2; mi++) {
                    int row = wm * 32 + mi * 16 + (lane & 15);
                    int ch = k16 * 2 + (lane >> 4);
                    uint32_t ad = row * 128 + ((ch ^ (row & 7)) << 4);
                    ldsm_x4(ah[mi], Sh + ad);
                    ldsm_x4(al[mi], Sl + ad);
                }
#pragma unroll
                for (int t = 0; t < 2; t++) {
                    int row = wn * 32 + t * 16 + ((lane >> 4) << 3) + (lane & 7);
                    int ch = k16 * 2 + ((lane >> 3) & 1);
                    uint32_t ad = row * 128 + ((ch ^ (row & 7)) << 4);
                    ldsm_x4(bh[t], Vh + ad);
                    ldsm_x4(bl[t], Vl + ad);
                }
#pragma unroll
                for (int mi = 0; mi < 2; mi++)
#pragma unroll
                    for (int nj = 0; nj < 4; nj++) {
                        const uint32_t* bhf = &bh[nj >> 1][(nj & 1) * 2];
                        const uint32_t* blf = &bl[nj >> 1][(nj & 1) * 2];
                        mma_bf16(acco[mi][nj], ah[mi], bhf);
                        mma_bf16(acco[mi][nj], ah[mi], blf);
                        mma_bf16(acco[mi][nj], al[mi], bhf);
                    }
            }
        }
    }
    // ---- epilogue: O -> bf16 hi/lo at [b][p][c] ----
#pragma unroll
    for (int mi = 0; mi < 2; mi++)
#pragma unroll
        for (int nj = 0; nj < 4; nj++) {
            int row = wm * 32 + mi * 16 + (lane >> 2);
            int col = g * HD + wn * 32 + nj * 8 + (lane & 3) * 2;
            float* u = acco[mi][nj];
            __nv_bfloat162 h01 = __floats2bfloat162_rn(u[0], u[1]);
            __nv_bfloat162 h23 = __floats2bfloat162_rn(u[2], u[3]);
            size_t o0 = (((size_t)b << 10) + i0 + row) * DIM + col;
            size_t o1 = (((size_t)b << 10) + i0 + row + 8) * DIM + col;
            *(uint32_t*)((char*)g_Ahi + o0 * 2) = *(uint32_t*)&h01;
            *(uint32_t*)((char*)g_Ahi + o1 * 2) = *(uint32_t*)&h23;
            *(uint32_t*)((char*)g_Alo + o0 * 2) =
                pack_bf16x2(u[0] - __bfloat162float(h01.x),
                            u[1] - __bfloat162float(h01.y));
            *(uint32_t*)((char*)g_Alo + o1 * 2) =
                pack_bf16x2(u[2] - __bfloat162float(h23.x),
                            u[3] - __bfloat162float(h23.y));
        }
}

// ---------------- conv1x1 via mma.sync bf16 -----------------------------------
// C[p 128][co 128] = A[p][ci] . W[co][ci], K=512 in 8 chunks of 64.
__global__ __launch_bounds__(256) void k_conv1x1_mma(void) {
    extern __shared__ char smem[];
    const uint32_t sb = s2u(smem);
    const int tid = threadIdx.x;
    const int wid = tid >> 5, lane = tid & 31;
    const int b = blockIdx.z, co0 = blockIdx.y * 128, p0 = blockIdx.x * 128;
    const int wm = wid & 1, wn = wid >> 1;

    float acc[4][4][4];
#pragma unroll
    for (int i = 0; i < 4; i++)
#pragma unroll
        for (int j = 0; j < 4; j++)
#pragma unroll
            for (int q = 0; q < 4; q++) acc[i][j][q] = 0.f;

    auto issue = [&](int c, int buf) {
        int ci0 = c << 6;
        uint32_t S = sb + buf * STAGE_BYTES;
#pragma unroll
        for (int u = 0; u < 4; u++) {
            int unit = tid + u * 256;
            int row = unit >> 3, ch = unit & 7;
            int sw = row * 128 + ((ch ^ (row & 7)) << 4);
            size_t offA = ((((size_t)b << 10) + p0 + row) << 9) + ci0 + (ch << 3);
            cp_async16(S + OFF_AHI + sw, (const char*)g_Ahi + offA * 2, 16);
            cp_async16(S + OFF_ALO + sw, (const char*)g_Alo + offA * 2, 16);
            size_t offB = (((size_t)co0 + row) << 9) + ci0 + (ch << 3);
            cp_async16(S + OFF_BHI + sw, (const char*)g_w2hi + offB * 2, 16);
            cp_async16(S + OFF_BLO + sw, (const char*)g_w2lo + offB * 2, 16);
        }
        cp_commit();
    };

    issue(0, 0);
    for (int c = 0; c < 8; c++) {
        int buf = c & 1;
        cp_wait0();
        __syncthreads();
        if (c + 1 < 8) issue(c + 1, buf ^ 1);

        uint32_t S = sb + buf * STAGE_BYTES;
        int rowA_lo = wm * 64 + (lane & 15);
        int kc8A = lane >> 4;
        int rowB_lo = wn * 32 + ((lane >> 4) << 3) + (lane & 7);
        int kc8B = (lane >> 3) & 1;
#pragma unroll
        for (int k16 = 0; k16 < 4; k16++) {
            uint32_t ah[4][4], al[4][4], bh[2][4], bl[2][4];
#pragma unroll
            for (int mi = 0; mi < 4; mi++) {
                int row = rowA_lo + mi * 16;
                int ch = k16 * 2 + kc8A;
                uint32_t ad = S + row * 128 + ((ch ^ (row & 7)) << 4);
                ldsm_x4(ah[mi], ad + OFF_AHI);
                ldsm_x4(al[mi], ad + OFF_ALO);
            }
#pragma unroll
            for (int t = 0; t < 2; t++) {
                int row = rowB_lo + t * 16;
                int ch = k16 * 2 + kc8B;
                uint32_t ad = S + row * 128 + ((ch ^ (row & 7)) << 4);
                ldsm_x4(bh[t], ad + OFF_BHI);
                ldsm_x4(bl[t], ad + OFF_BLO);
            }
#pragma unroll
            for (int mi = 0; mi < 4; mi++)
#pragma unroll
                for (int nj = 0; nj < 4; nj++) {
                    const uint32_t* bhf = &bh[nj >> 1][(nj & 1) * 2];
                    const uint32_t* blf = &bl[nj >> 1][(nj & 1) * 2];
                    mma_bf16(acc[mi][nj], ah[mi], bhf);
                    mma_bf16(acc[mi][nj], ah[mi], blf);
                    mma_bf16(acc[mi][nj], al[mi], bhf);
                }
        }
    }
    // direct write C[p][co] to g_conv2 [b][p][c]
#pragma unroll
    for (int mi = 0; mi < 4; mi++)
#pragma unroll
        for (int nj = 0; nj < 4; nj++) {
            int row = wm * 64 + mi * 16 + (lane >> 2);
            int col = wn * 32 + nj * 8 + (lane & 3) * 2;
            float* u = acc[mi][nj];
            size_t o0 = (((size_t)b << 10) + p0 + row) * DIM + co0 + col;
            size_t o1 = o0 + 8 * DIM;
            *(float2*)(g_conv2 + o0) = make_float2(u[0], u[1]);
            *(float2*)(g_conv2 + o1) = make_float2(u[2], u[3]);
        }
}

// ---------------- BN partial sums ([b][p][c] layout, deterministic) -----------
__global__ void k_bnpartial(void) {
    int z = blockIdx.x;          // 64 blocks, each 128 rows of (b*p)
    int t = threadIdx.x;         // 256: channels t and t+256
    const float* base = g_conv2 + (size_t)z * 128 * DIM;
    float s1 = 0.f, q1 = 0.f, s2 = 0.f, q2 = 0.f;
    for (int r = 0; r < 128; r++) {
        float a = base[r * DIM + t];
        float c = base[r * DIM + t + 256];
        s1 += a; q1 = fmaf(a, a, q1);
        s2 += c; q2 = fmaf(c, c, q2);
    }
    g_part[0][z][t] = s1;
    g_part[1][z][t] = q1;
    g_part[0][z][t + 256] = s2;
    g_part[1][z][t + 256] = q2;
}

__global__ void k_bnfinal(const float* __restrict__ gamma,
                          const float* __restrict__ beta) {
    int c = threadIdx.x;  // 512 threads
    float s = 0.f, s2 = 0.f;
    for (int i = 0; i < 64; i++) { s += g_part[0][i][c]; s2 += g_part[1][i][c]; }
    float mean = s * (1.f / 8192.f);
    float var = s2 * (1.f / 8192.f) - mean * mean;
    float rstd = rsqrtf(var + BN_EPSF);
    float sc = gamma[c] * rstd;
    g_scale[c] = sc;
    g_shift[c] = beta[c] - mean * sc;
}

// ---------------- BN apply + ReLU + transpose [b][p][c] -> out[b][c][p] -------
__global__ void k_bn_relu_t(float* __restrict__ out) {
    __shared__ float t[32][33];
    int p0 = blockIdx.x * 32, c0 = blockIdx.y * 32, b = blockIdx.z;
    int tx = threadIdx.x, ty = threadIdx.y;  // 32 x 8
#pragma unroll
    for (int u = 0; u < 4; u++) {
        int p = p0 + ty + u * 8;
        t[ty + u * 8][tx] = g_conv2[(((size_t)b << 10) + p) * DIM + c0 + tx];
    }
    __syncthreads();
#pragma unroll
    for (int u = 0; u < 4; u++) {
        int c = c0 + ty + u * 8;
        float v = fmaf(t[tx][ty + u * 8], g_scale[c], g_shift[c]);
        out[((size_t)b * DIM + c) * NPIX + p0 + tx] = v > 0.f ? v : 0.f;
    }
}

// ---------------- launch ------------------------------------------------------
extern "C" void kernel_launch(void* const* d_in, const int* in_sizes, int n_in,
                              void* d_out, int out_size) {
    const float* x      = (const float*)d_in[0];
    const float* W_qkv  = (const float*)d_in[1];
    const float* W_out  = (const float*)d_in[2];
    const float* gamma  = (const float*)d_in[3];
    const float* beta   = (const float*)d_in[4];
    float* out = (float*)d_out;

    k_prep_x<<<dim3(32, 16, BATCH), dim3(32, 8)>>>(x);
    k_prep_w<<<THREE_DIM, 256>>>(W_qkv);
    k_split_wout<<<(DIM * DIM + 255) / 256, 256>>>(W_out);

    cudaFuncSetAttribute(k_conv3x3_mma, cudaFuncAttributeMaxDynamicSharedMemorySize,
                         CONV_SMEM);
    k_conv3x3_mma<<<dim3(8, 12, BATCH), 256, CONV_SMEM>>>();

    k_norms<<<(BATCH * HEADS * NPIX) / 256, 256>>>();
    k_split_qkv<<<dim3(32, 2, 64), dim3(32, 8)>>>();
    k_split_v<<<(64 * HD * NPIX) / 256, 256>>>();

    cudaFuncSetAttribute(k_attn_mma, cudaFuncAttributeMaxDynamicSharedMemorySize,
                         ATN_SMEM);
    k_attn_mma<<<dim3(8, HEADS, BATCH), 256, ATN_SMEM>>>();

    cudaFuncSetAttribute(k_conv1x1_mma, cudaFuncAttributeMaxDynamicSharedMemorySize,
                         CONV_SMEM);
    k_conv1x1_mma<<<dim3(8, 4, BATCH), 256, CONV_SMEM>>>();

    k_bnpartial<<<64, 256>>>();
    k_bnfinal<<<1, DIM>>>(gamma, beta);
    k_bn_relu_t<<<dim3(32, 16, BATCH), dim3(32, 8)>>>(out);
}

// round 9
// speedup vs baseline: 3.4970x; 1.0759x over previous
#include <cuda_runtime.h>
#include <cuda_bf16.h>
#include <cstdint>

#define DIM 512
#define THREE_DIM 1536
#define NPIX 1024
#define BATCH 8
#define HEADS 8
#define HD 64
#define SMOOTHF 1e-4f
#define BN_EPSF 1e-5f

// ---------------- scratch (static __device__, no allocation) ----------------
__device__ float g_qkv[BATCH * THREE_DIM * NPIX];   // [b][c3][p]
__device__ float g_invqn[BATCH * HEADS * NPIX];
__device__ float g_invkn[BATCH * HEADS * NPIX];
__device__ float g_conv2[BATCH * NPIX * DIM];       // [b][p][c]
__device__ float g_scale[DIM];
__device__ float g_shift[DIM];
__device__ float g_part[2][64][DIM];                // BN partial sums
// bf16 split operands for conv3x3
__device__ __nv_bfloat16 g_xThi[BATCH * NPIX * DIM];        // [b][p][ci]
__device__ __nv_bfloat16 g_xTlo[BATCH * NPIX * DIM];
__device__ __nv_bfloat16 g_Wrhi[9 * THREE_DIM * DIM];       // [kpos][co][ci]
__device__ __nv_bfloat16 g_Wrlo[9 * THREE_DIM * DIM];
// bf16 split operands for attention (normalized q,k; raw v transposed)
__device__ __nv_bfloat16 g_qhi[64 * NPIX * HD];     // [bg][n][d]  (q * invqn)
__device__ __nv_bfloat16 g_qlo[64 * NPIX * HD];
__device__ __nv_bfloat16 g_khi[64 * NPIX * HD];     // [bg][n][d]  (k * invkn)
__device__ __nv_bfloat16 g_klo[64 * NPIX * HD];
__device__ __nv_bfloat16 g_vThi[64 * HD * NPIX];    // [bg][d][n]
__device__ __nv_bfloat16 g_vTlo[64 * HD * NPIX];
// attention output (conv1x1 A operand), bf16 split
__device__ __nv_bfloat16 g_Ahi[BATCH * NPIX * DIM]; // [b][p][c]
__device__ __nv_bfloat16 g_Alo[BATCH * NPIX * DIM];
// conv1x1 weights split
__device__ __nv_bfloat16 g_w2hi[DIM * DIM];         // [co][ci]
__device__ __nv_bfloat16 g_w2lo[DIM * DIM];

// ---------------- helpers ----------------------------------------------------
__device__ __forceinline__ uint32_t s2u(const void* p) {
    uint32_t a;
    asm("{ .reg .u64 t; cvta.to.shared.u64 t, %1; cvt.u32.u64 %0, t; }"
        : "=r"(a) : "l"(p));
    return a;
}
__device__ __forceinline__ void cp_async16(uint32_t saddr, const void* gaddr, int sz) {
    asm volatile("cp.async.cg.shared.global [%0], [%1], 16, %2;"
                 :: "r"(saddr), "l"(gaddr), "r"(sz));
}
__device__ __forceinline__ void cp_commit() {
    asm volatile("cp.async.commit_group;" ::: "memory");
}
__device__ __forceinline__ void cp_wait0() {
    asm volatile("cp.async.wait_group 0;" ::: "memory");
}
__device__ __forceinline__ void ldsm_x4(uint32_t* r, uint32_t addr) {
    asm volatile("ldmatrix.sync.aligned.m8n8.x4.shared.b16 {%0,%1,%2,%3}, [%4];"
                 : "=r"(r[0]), "=r"(r[1]), "=r"(r[2]), "=r"(r[3]) : "r"(addr));
}
__device__ __forceinline__ void mma_bf16(float* d, const uint32_t* a,
                                         const uint32_t* b) {
    asm volatile(
        "mma.sync.aligned.m16n8k16.row.col.f32.bf16.bf16.f32 "
        "{%0,%1,%2,%3}, {%4,%5,%6,%7}, {%8,%9}, {%0,%1,%2,%3};"
        : "+f"(d[0]), "+f"(d[1]), "+f"(d[2]), "+f"(d[3])
        : "r"(a[0]), "r"(a[1]), "r"(a[2]), "r"(a[3]), "r"(b[0]), "r"(b[1]));
}
__device__ __forceinline__ uint32_t pack_bf16x2(float a, float b) {
    __nv_bfloat162 h = __floats2bfloat162_rn(a, b);
    return *(uint32_t*)&h;
}

// ---------------- prep: x -> [b][p][ci] bf16 hi/lo ----------------------------
__global__ void k_prep_x(const float* __restrict__ x) {
    __shared__ float t[32][33];
    int b = blockIdx.z, c0 = blockIdx.y * 32, p0 = blockIdx.x * 32;
    int tx = threadIdx.x, ty = threadIdx.y;  // 32 x 8
    const float* xb = x + ((size_t)b * DIM + c0) * NPIX + p0;
#pragma unroll
    for (int u = 0; u < 4; u++) t[ty + u * 8][tx] = xb[(ty + u * 8) * NPIX + tx];
    __syncthreads();
    size_t ob = ((size_t)b * NPIX + p0) * DIM + c0;
#pragma unroll
    for (int u = 0; u < 4; u++) {
        int p = ty + u * 8;
        float v = t[tx][p];
        __nv_bfloat16 hi = __float2bfloat16(v);
        __nv_bfloat16 lo = __float2bfloat16(v - __bfloat162float(hi));
        g_xThi[ob + (size_t)p * DIM + tx] = hi;
        g_xTlo[ob + (size_t)p * DIM + tx] = lo;
    }
}

// ---------------- prep: W_qkv -> [kpos][co][ci] bf16 hi/lo --------------------
__global__ void k_prep_w(const float* __restrict__ W) {
    __shared__ float s[4608];
    int co = blockIdx.x;
    const float* wr = W + (size_t)co * 4608;
    for (int i = threadIdx.x; i < 4608; i += 256) s[i] = wr[i];
    __syncthreads();
    for (int kpos = 0; kpos < 9; kpos++) {
        size_t ob = ((size_t)kpos * THREE_DIM + co) * DIM;
        for (int ci = threadIdx.x; ci < DIM; ci += 256) {
            float v = s[ci * 9 + kpos];
            __nv_bfloat16 hi = __float2bfloat16(v);
            g_Wrhi[ob + ci] = hi;
            g_Wrlo[ob + ci] = __float2bfloat16(v - __bfloat162float(hi));
        }
    }
}

// ---------------- prep: W_out split ([co][ci], no transpose) ------------------
__global__ void k_split_wout(const float* __restrict__ W) {
    int idx = blockIdx.x * 256 + threadIdx.x;
    if (idx >= DIM * DIM) return;
    float v = W[idx];
    __nv_bfloat16 hi = __float2bfloat16(v);
    g_w2hi[idx] = hi;
    g_w2lo[idx] = __float2bfloat16(v - __bfloat162float(hi));
}

// ---------------- conv3x3 via mma.sync bf16, BM=128 BN=64, 2 CTAs/SM ----------
// Stage: Ahi 16K | Alo 16K | Bhi 8K | Blo 8K = 48KB; double buffered = 96KB.
#define C3_OFF_AHI 0
#define C3_OFF_ALO 16384
#define C3_OFF_BHI 32768
#define C3_OFF_BLO 40960
#define C3_STAGE 49152
#define C3_SMEM (2 * C3_STAGE)

__global__ __launch_bounds__(256, 2) void k_conv3x3_mma(void) {
    extern __shared__ char smem[];
    const uint32_t sb = s2u(smem);
    const int tid = threadIdx.x;
    const int wid = tid >> 5, lane = tid & 31;
    const int b = blockIdx.z, co0 = blockIdx.y * 64, p0 = blockIdx.x * 128;
    const int wm = wid >> 1, wn = wid & 1;   // 4 x 2 warps, 32x32 tiles

    float acc[2][4][4];
#pragma unroll
    for (int i = 0; i < 2; i++)
#pragma unroll
        for (int j = 0; j < 4; j++)
#pragma unroll
            for (int q = 0; q < 4; q++) acc[i][j][q] = 0.f;

    auto issue = [&](int c, int buf) {
        int kpos = c >> 3, ci0 = (c & 7) << 6;
        int kh = kpos / 3 - 1, kw = kpos % 3 - 1;
        uint32_t S = sb + buf * C3_STAGE;
#pragma unroll
        for (int u = 0; u < 12; u++) {
            int unit = tid + u * 256;            // 0..3071
            if (unit < 2048) {
                // A: sel 0=hi 1=lo, 128 rows x 8 ch
                int sel = unit >> 10;
                int row = (unit >> 3) & 127, ch = unit & 7;
                int sw = row * 128 + ((ch ^ (row & 7)) << 4);
                int p = p0 + row;
                int h = (p >> 5) + kh, w = (p & 31) + kw;
                bool valid = ((unsigned)h < 32u) && ((unsigned)w < 32u);
                size_t offA = valid
                    ? (((((size_t)b << 10) + ((h << 5) + w)) << 9) + ci0 + (ch << 3))
                    : 0;
                int sz = valid ? 16 : 0;
                const char* src = sel ? (const char*)g_xTlo : (const char*)g_xThi;
                cp_async16(S + (sel ? C3_OFF_ALO : C3_OFF_AHI) + sw,
                           src + offA * 2, sz);
            } else {
                // B: sel 0=hi 1=lo, 64 rows x 8 ch
                int v2 = unit - 2048;
                int sel = v2 >> 9;
                int row = (v2 >> 3) & 63, ch = v2 & 7;
                int sw = row * 128 + ((ch ^ (row & 7)) << 4);
                size_t offB = (((size_t)kpos * THREE_DIM + co0 + row) << 9)
                              + ci0 + (ch << 3);
                const char* src = sel ? (const char*)g_Wrlo : (const char*)g_Wrhi;
                cp_async16(S + (sel ? C3_OFF_BLO : C3_OFF_BHI) + sw,
                           src + offB * 2, 16);
            }
        }
        cp_commit();
    };

    issue(0, 0);
    for (int c = 0; c < 72; c++) {
        int buf = c & 1;
        cp_wait0();
        __syncthreads();
        if (c + 1 < 72) issue(c + 1, buf ^ 1);

        uint32_t S = sb + buf * C3_STAGE;
        int rowA_lo = wm * 32 + (lane & 15);
        int kc8A = lane >> 4;
        int rowB_lo = wn * 32 + ((lane >> 4) << 3) + (lane & 7);
        int kc8B = (lane >> 3) & 1;
#pragma unroll
        for (int k16 = 0; k16 < 4; k16++) {
            uint32_t ah[2][4], al[2][4], bh[2][4], bl[2][4];
#pragma unroll
            for (int mi = 0; mi < 2; mi++) {
                int row = rowA_lo + mi * 16;
                int ch = k16 * 2 + kc8A;
                uint32_t ad = S + row * 128 + ((ch ^ (row & 7)) << 4);
                ldsm_x4(ah[mi], ad + C3_OFF_AHI);
                ldsm_x4(al[mi], ad + C3_OFF_ALO);
            }
#pragma unroll
            for (int t = 0; t < 2; t++) {
                int row = rowB_lo + t * 16;
                int ch = k16 * 2 + kc8B;
                uint32_t ad = S + row * 128 + ((ch ^ (row & 7)) << 4);
                ldsm_x4(bh[t], ad + C3_OFF_BHI);
                ldsm_x4(bl[t], ad + C3_OFF_BLO);
            }
#pragma unroll
            for (int mi = 0; mi < 2; mi++)
#pragma unroll
                for (int nj = 0; nj < 4; nj++) {
                    const uint32_t* bhf = &bh[nj >> 1][(nj & 1) * 2];
                    const uint32_t* blf = &bl[nj >> 1][(nj & 1) * 2];
                    mma_bf16(acc[mi][nj], ah[mi], bhf);
                    mma_bf16(acc[mi][nj], ah[mi], blf);
                    mma_bf16(acc[mi][nj], al[mi], bhf);
                }
        }
    }
    __syncthreads();

    // epilogue: frags -> smem T[p 128][co 64+pad4] -> g_qkv[co][p]
    float* T = (float*)smem;
#pragma unroll
    for (int mi = 0; mi < 2; mi++)
#pragma unroll
        for (int nj = 0; nj < 4; nj++) {
            int row = wm * 32 + mi * 16 + (lane >> 2);
            int col = wn * 32 + nj * 8 + (lane & 3) * 2;
            T[row * 68 + col]          = acc[mi][nj][0];
            T[row * 68 + col + 1]      = acc[mi][nj][1];
            T[(row + 8) * 68 + col]     = acc[mi][nj][2];
            T[(row + 8) * 68 + col + 1] = acc[mi][nj][3];
        }
    __syncthreads();
    float* outbase = g_qkv + ((size_t)b * THREE_DIM + co0) * NPIX + p0;
#pragma unroll
    for (int t = 0; t < 8; t++) {
        int cc = wid * 8 + t;
        float4 v;
        v.x = T[(lane * 4 + 0) * 68 + cc];
        v.y = T[(lane * 4 + 1) * 68 + cc];
        v.z = T[(lane * 4 + 2) * 68 + cc];
        v.w = T[(lane * 4 + 3) * 68 + cc];
        *(float4*)(outbase + (size_t)cc * NPIX + lane * 4) = v;
    }
}

// ---------------- q/k inverse norms ------------------------------------------
__global__ void k_norms(void) {
    int idx = blockIdx.x * 256 + threadIdx.x;
    int i = idx & 1023;
    int bg = idx >> 10;
    int b = bg >> 3, g = bg & 7;
    const float* qp = g_qkv + ((size_t)b * THREE_DIM + g * HD) * NPIX + i;
    const float* kp = qp + (size_t)DIM * NPIX;
    float sq = 0.f, sk = 0.f;
#pragma unroll 8
    for (int d = 0; d < HD; d++) {
        float vq = qp[d * NPIX]; sq = fmaf(vq, vq, sq);
        float vk = kp[d * NPIX]; sk = fmaf(vk, vk, sk);
    }
    g_invqn[idx] = rsqrtf(sq + SMOOTHF);
    g_invkn[idx] = rsqrtf(sk + SMOOTHF);
}

// ---------------- split q,k: normalize + transpose [d][n]->[n][d] + bf16 split
__global__ void k_split_qkv(void) {
    __shared__ float t[32][33];
    int n0 = blockIdx.x * 32, d0 = blockIdx.y * 32, bg = blockIdx.z;
    int b = bg >> 3, g = bg & 7;
    int tx = threadIdx.x, ty = threadIdx.y;  // 32 x 8
    const float* srcq = g_qkv + ((size_t)b * THREE_DIM + g * HD + d0) * NPIX + n0;
    // ---- q ----
#pragma unroll
    for (int u = 0; u < 4; u++)
        t[ty + u * 8][tx] = srcq[(size_t)(ty + u * 8) * NPIX + tx];
    __syncthreads();
#pragma unroll
    for (int u = 0; u < 4; u++) {
        int nl = ty + u * 8;
        int n = n0 + nl;
        float iv = g_invqn[((size_t)bg << 10) + n];
        float v = t[tx][nl] * iv;
        __nv_bfloat16 hi = __float2bfloat16(v);
        size_t o = (((size_t)bg << 10) + n) * HD + d0 + tx;
        g_qhi[o] = hi;
        g_qlo[o] = __float2bfloat16(v - __bfloat162float(hi));
    }
    __syncthreads();
    // ---- k ----
    const float* srck = srcq + (size_t)DIM * NPIX;
#pragma unroll
    for (int u = 0; u < 4; u++)
        t[ty + u * 8][tx] = srck[(size_t)(ty + u * 8) * NPIX + tx];
    __syncthreads();
#pragma unroll
    for (int u = 0; u < 4; u++) {
        int nl = ty + u * 8;
        int n = n0 + nl;
        float iv = g_invkn[((size_t)bg << 10) + n];
        float v = t[tx][nl] * iv;
        __nv_bfloat16 hi = __float2bfloat16(v);
        size_t o = (((size_t)bg << 10) + n) * HD + d0 + tx;
        g_khi[o] = hi;
        g_klo[o] = __float2bfloat16(v - __bfloat162float(hi));
    }
}

// ---------------- split v (keeps [d][n] layout) -------------------------------
__global__ void k_split_v(void) {
    int idx = blockIdx.x * 256 + threadIdx.x;   // 64*64*1024 total
    int bg = idx >> 16;
    int rem = idx & 65535;
    int d = rem >> 10, n = rem & 1023;
    int b = bg >> 3, g = bg & 7;
    float v = g_qkv[((size_t)b * THREE_DIM + 2 * DIM + g * HD + d) * NPIX + n];
    __nv_bfloat16 hi = __float2bfloat16(v);
    size_t o = ((size_t)bg * HD + d) * NPIX + n;
    g_vThi[o] = hi;
    g_vTlo[o] = __float2bfloat16(v - __bfloat162float(hi));
}

// ---------------- attention via mma.sync bf16 (unchanged, passing) ------------
#define ATN_QHI 0
#define ATN_QLO 16384
#define ATN_K(buf)  (32768 + (buf) * 16384)   // Khi +0, Klo +8192
#define ATN_VT(buf) (65536 + (buf) * 16384)   // VThi +0, VTlo +8192
#define ATN_SHI 98304
#define ATN_SLO 114688
#define ATN_IQ 131072
#define ATN_IK 131584                          // + buf*256
#define ATN_SMEM 132096

__global__ __launch_bounds__(256, 1) void k_attn_mma(void) {
    extern __shared__ char smem[];
    const uint32_t sb = s2u(smem);
    const int tid = threadIdx.x, wid = tid >> 5, lane = tid & 31;
    const int i0 = blockIdx.x * 128;
    const int g = blockIdx.y, b = blockIdx.z;
    const int bg = b * 8 + g;
    const int wm = wid & 3, wn = wid >> 2;

#pragma unroll
    for (int u = 0; u < 4; u++) {
        int unit = tid + u * 256;
        int row = unit >> 3, ch = unit & 7;
        int sw = row * 128 + ((ch ^ (row & 7)) << 4);
        size_t go = (((size_t)bg << 10) + i0 + row) * 128 + ch * 16;
        cp_async16(sb + ATN_QHI + sw, (const char*)g_qhi + go, 16);
        cp_async16(sb + ATN_QLO + sw, (const char*)g_qlo + go, 16);
    }
    if (tid < 128)
        ((float*)(smem + ATN_IQ))[tid] = g_invqn[((size_t)bg << 10) + i0 + tid];
    cp_commit();

    auto issueKV = [&](int j0, int buf) {
#pragma unroll
        for (int u = 0; u < 8; u++) {
            int unit = tid + u * 256;
            int sel = unit >> 9;
            int r2 = (unit >> 3) & 63, ch = unit & 7;
            int sw = r2 * 128 + ((ch ^ (r2 & 7)) << 4);
            uint32_t dst;
            const char* src;
            if (sel == 0) {
                dst = sb + ATN_K(buf) + sw;
                src = (const char*)g_khi + (((size_t)bg << 10) + j0 + r2) * 128 + ch * 16;
            } else if (sel == 1) {
                dst = sb + ATN_K(buf) + 8192 + sw;
                src = (const char*)g_klo + (((size_t)bg << 10) + j0 + r2) * 128 + ch * 16;
            } else if (sel == 2) {
                dst = sb + ATN_VT(buf) + sw;
                src = (const char*)g_vThi + (((size_t)bg * HD + r2) * NPIX + j0) * 2 + ch * 16;
            } else {
                dst = sb + ATN_VT(buf) + 8192 + sw;
                src = (const char*)g_vTlo + (((size_t)bg * HD + r2) * NPIX + j0) * 2 + ch * 16;
            }
            cp_async16(dst, src, 16);
        }
        if (tid < 64)
            ((float*)(smem + ATN_IK + buf * 256))[tid] =
                g_invkn[((size_t)bg << 10) + j0 + tid];
        cp_commit();
    };
    issueKV(0, 0);

    float acco[2][4][4];
#pragma unroll
    for (int i = 0; i < 2; i++)
#pragma unroll
        for (int j = 0; j < 4; j++)
#pragma unroll
            for (int q = 0; q < 4; q++) acco[i][j][q] = 0.f;

    for (int jt = 0; jt < 16; jt++) {
        int buf = jt & 1;
        cp_wait0();
        __syncthreads();
        if (jt < 15) issueKV((jt + 1) * 64, buf ^ 1);

        float s[2][4][4];
#pragma unroll
        for (int i = 0; i < 2; i++)
#pragma unroll
            for (int j = 0; j < 4; j++)
#pragma unroll
                for (int q = 0; q < 4; q++) s[i][j][q] = 0.f;
        {
            uint32_t Qh = sb + ATN_QHI, Ql = sb + ATN_QLO;
            uint32_t Kh = sb + ATN_K(buf), Kl = Kh + 8192;
#pragma unroll
            for (int k16 = 0; k16 < 4; k16++) {
                uint32_t ah[2][4], al[2][4], bh[2][4], bl[2][4];
#pragma unroll
                for (int mi = 0; mi < 2; mi++) {
                    int row = wm * 32 + mi * 16 + (lane & 15);
                    int ch = k16 * 2 + (lane >> 4);
                    uint32_t ad = row * 128 + ((ch ^ (row & 7)) << 4);
                    ldsm_x4(ah[mi], Qh + ad);
                    ldsm_x4(al[mi], Ql + ad);
                }
#pragma unroll
                for (int t = 0; t < 2; t++) {
                    int row = wn * 32 + t * 16 + ((lane >> 4) << 3) + (lane & 7);
                    int ch = k16 * 2 + ((lane >> 3) & 1);
                    uint32_t ad = row * 128 + ((ch ^ (row & 7)) << 4);
                    ldsm_x4(bh[t], Kh + ad);
                    ldsm_x4(bl[t], Kl + ad);
                }
#pragma unroll
                for (int mi = 0; mi < 2; mi++)
#pragma unroll
                    for (int nj = 0; nj < 4; nj++) {
                        const uint32_t* bhf = &bh[nj >> 1][(nj & 1) * 2];
                        const uint32_t* blf = &bl[nj >> 1][(nj & 1) * 2];
                        mma_bf16(s[mi][nj], ah[mi], bhf);
                        mma_bf16(s[mi][nj], ah[mi], blf);
                        mma_bf16(s[mi][nj], al[mi], bhf);
                    }
            }
        }
        {
            const float* IQ = (const float*)(smem + ATN_IQ);
            const float* IK = (const float*)(smem + ATN_IK + buf * 256);
#pragma unroll
            for (int mi = 0; mi < 2; mi++) {
                int r0 = wm * 32 + mi * 16 + (lane >> 2);
                float iq0 = IQ[r0], iq1 = IQ[r0 + 8];
#pragma unroll
                for (int nj = 0; nj < 4; nj++) {
                    int col = wn * 32 + nj * 8 + (lane & 3) * 2;
                    float ik0 = IK[col], ik1 = IK[col + 1];
                    float* u = s[mi][nj];
                    float t00 = iq0 * ik0, t01 = iq0 * ik1;
                    float t10 = iq1 * ik0, t11 = iq1 * ik1;
                    float v0 = fmaf(-SMOOTHF * t00, u[0], u[0]);
                    float v1 = fmaf(-SMOOTHF * t01, u[1], u[1]);
                    float v2 = fmaf(-SMOOTHF * t10, u[2], u[2]);
                    float v3 = fmaf(-SMOOTHF * t11, u[3], u[3]);
                    __nv_bfloat162 h01 = __floats2bfloat162_rn(v0, v1);
                    float r0f = v0 - __bfloat162float(h01.x);
                    float r1f = v1 - __bfloat162float(h01.y);
                    __nv_bfloat162 h23 = __floats2bfloat162_rn(v2, v3);
                    float r2f = v2 - __bfloat162float(h23.x);
                    float r3f = v3 - __bfloat162float(h23.y);
                    int bo = col * 2;
                    int ch = bo >> 4, wi = bo & 15;
                    int a0 = r0 * 128 + ((ch ^ (r0 & 7)) << 4) + wi;
                    int a1 = (r0 + 8) * 128 + ((ch ^ ((r0 + 8) & 7)) << 4) + wi;
                    *(uint32_t*)(smem + ATN_SHI + a0) = *(uint32_t*)&h01;
                    *(uint32_t*)(smem + ATN_SHI + a1) = *(uint32_t*)&h23;
                    *(uint32_t*)(smem + ATN_SLO + a0) = pack_bf16x2(r0f, r1f);
                    *(uint32_t*)(smem + ATN_SLO + a1) = pack_bf16x2(r2f, r3f);
                }
            }
        }
        __syncthreads();
        {
            uint32_t Sh = sb + ATN_SHI, Sl = sb + ATN_SLO;
            uint32_t Vh = sb + ATN_VT(buf), Vl = Vh + 8192;
#pragma unroll
            for (int k16 = 0; k16 < 4; k16++) {
                uint32_t ah[2][4], al[2][4], bh[2][4], bl[2][4];
#pragma unroll
                for (int mi = 0; mi < 2; mi++) {
                    int row = wm * 32 + mi * 16 + (lane & 15);
                    int ch = k16 * 2 + (lane >> 4);
                    uint32_t ad = row * 128 + ((ch ^ (row & 7)) << 4);
                    ldsm_x4(ah[mi], Sh + ad);
                    ldsm_x4(al[mi], Sl + ad);
                }
#pragma unroll
                for (int t = 0; t < 2; t++) {
                    int row = wn * 32 + t * 16 + ((lane >> 4) << 3) + (lane & 7);
                    int ch = k16 * 2 + ((lane >> 3) & 1);
                    uint32_t ad = row * 128 + ((ch ^ (row & 7)) << 4);
                    ldsm_x4(bh[t], Vh + ad);
                    ldsm_x4(bl[t], Vl + ad);
                }
#pragma unroll
                for (int mi = 0; mi < 2; mi++)
#pragma unroll
                    for (int nj = 0; nj < 4; nj++) {
                        const uint32_t* bhf = &bh[nj >> 1][(nj & 1) * 2];
                        const uint32_t* blf = &bl[nj >> 1][(nj & 1) * 2];
                        mma_bf16(acco[mi][nj], ah[mi], bhf);
                        mma_bf16(acco[mi][nj], ah[mi], blf);
                        mma_bf16(acco[mi][nj], al[mi], bhf);
                    }
            }
        }
    }
#pragma unroll
    for (int mi = 0; mi < 2; mi++)
#pragma unroll
        for (int nj = 0; nj < 4; nj++) {
            int row = wm * 32 + mi * 16 + (lane >> 2);
            int col = g * HD + wn * 32 + nj * 8 + (lane & 3) * 2;
            float* u = acco[mi][nj];
            __nv_bfloat162 h01 = __floats2bfloat162_rn(u[0], u[1]);
            __nv_bfloat162 h23 = __floats2bfloat162_rn(u[2], u[3]);
            size_t o0 = (((size_t)b << 10) + i0 + row) * DIM + col;
            size_t o1 = (((size_t)b << 10) + i0 + row + 8) * DIM + col;
            *(uint32_t*)((char*)g_Ahi + o0 * 2) = *(uint32_t*)&h01;
            *(uint32_t*)((char*)g_Ahi + o1 * 2) = *(uint32_t*)&h23;
            *(uint32_t*)((char*)g_Alo + o0 * 2) =
                pack_bf16x2(u[0] - __bfloat162float(h01.x),
                            u[1] - __bfloat162float(h01.y));
            *(uint32_t*)((char*)g_Alo + o1 * 2) =
                pack_bf16x2(u[2] - __bfloat162float(h23.x),
                            u[3] - __bfloat162float(h23.y));
        }
}

// ---------------- conv1x1 via mma.sync bf16 (unchanged, passing) --------------
#define STAGE_BYTES 65536
#define OFF_AHI 0
#define OFF_ALO 16384
#define OFF_BHI 32768
#define OFF_BLO 49152
#define CONV_SMEM (2 * STAGE_BYTES)

__global__ __launch_bounds__(256) void k_conv1x1_mma(void) {
    extern __shared__ char smem[];
    const uint32_t sb = s2u(smem);
    const int tid = threadIdx.x;
    const int wid = tid >> 5, lane = tid & 31;
    const int b = blockIdx.z, co0 = blockIdx.y * 128, p0 = blockIdx.x * 128;
    const int wm = wid & 1, wn = wid >> 1;

    float acc[4][4][4];
#pragma unroll
    for (int i = 0; i < 4; i++)
#pragma unroll
        for (int j = 0; j < 4; j++)
#pragma unroll
            for (int q = 0; q < 4; q++) acc[i][j][q] = 0.f;

    auto issue = [&](int c, int buf) {
        int ci0 = c << 6;
        uint32_t S = sb + buf * STAGE_BYTES;
#pragma unroll
        for (int u = 0; u < 4; u++) {
            int unit = tid + u * 256;
            int row = unit >> 3, ch = unit & 7;
            int sw = row * 128 + ((ch ^ (row & 7)) << 4);
            size_t offA = ((((size_t)b << 10) + p0 + row) << 9) + ci0 + (ch << 3);
            cp_async16(S + OFF_AHI + sw, (const char*)g_Ahi + offA * 2, 16);
            cp_async16(S + OFF_ALO + sw, (const char*)g_Alo + offA * 2, 16);
            size_t offB = (((size_t)co0 + row) << 9) + ci0 + (ch << 3);
            cp_async16(S + OFF_BHI + sw, (const char*)g_w2hi + offB * 2, 16);
            cp_async16(S + OFF_BLO + sw, (const char*)g_w2lo + offB * 2, 16);
        }
        cp_commit();
    };

    issue(0, 0);
    for (int c = 0; c < 8; c++) {
        int buf = c & 1;
        cp_wait0();
        __syncthreads();
        if (c + 1 < 8) issue(c + 1, buf ^ 1);

        uint32_t S = sb + buf * STAGE_BYTES;
        int rowA_lo = wm * 64 + (lane & 15);
        int kc8A = lane >> 4;
        int rowB_lo = wn * 32 + ((lane >> 4) << 3) + (lane & 7);
        int kc8B = (lane >> 3) & 1;
#pragma unroll
        for (int k16 = 0; k16 < 4; k16++) {
            uint32_t ah[4][4], al[4][4], bh[2][4], bl[2][4];
#pragma unroll
            for (int mi = 0; mi < 4; mi++) {
                int row = rowA_lo + mi * 16;
                int ch = k16 * 2 + kc8A;
                uint32_t ad = S + row * 128 + ((ch ^ (row & 7)) << 4);
                ldsm_x4(ah[mi], ad + OFF_AHI);
                ldsm_x4(al[mi], ad + OFF_ALO);
            }
#pragma unroll
            for (int t = 0; t < 2; t++) {
                int row = rowB_lo + t * 16;
                int ch = k16 * 2 + kc8B;
                uint32_t ad = S + row * 128 + ((ch ^ (row & 7)) << 4);
                ldsm_x4(bh[t], ad + OFF_BHI);
                ldsm_x4(bl[t], ad + OFF_BLO);
            }
#pragma unroll
            for (int mi = 0; mi < 4; mi++)
#pragma unroll
                for (int nj = 0; nj < 4; nj++) {
                    const uint32_t* bhf = &bh[nj >> 1][(nj & 1) * 2];
                    const uint32_t* blf = &bl[nj >> 1][(nj & 1) * 2];
                    mma_bf16(acc[mi][nj], ah[mi], bhf);
                    mma_bf16(acc[mi][nj], ah[mi], blf);
                    mma_bf16(acc[mi][nj], al[mi], bhf);
                }
        }
    }
#pragma unroll
    for (int mi = 0; mi < 4; mi++)
#pragma unroll
        for (int nj = 0; nj < 4; nj++) {
            int row = wm * 64 + mi * 16 + (lane >> 2);
            int col = wn * 32 + nj * 8 + (lane & 3) * 2;
            float* u = acc[mi][nj];
            size_t o0 = (((size_t)b << 10) + p0 + row) * DIM + co0 + col;
            size_t o1 = o0 + 8 * DIM;
            *(float2*)(g_conv2 + o0) = make_float2(u[0], u[1]);
            *(float2*)(g_conv2 + o1) = make_float2(u[2], u[3]);
        }
}

// ---------------- BN partial sums ---------------------------------------------
__global__ void k_bnpartial(void) {
    int z = blockIdx.x;
    int t = threadIdx.x;
    const float* base = g_conv2 + (size_t)z * 128 * DIM;
    float s1 = 0.f, q1 = 0.f, s2 = 0.f, q2 = 0.f;
    for (int r = 0; r < 128; r++) {
        float a = base[r * DIM + t];
        float c = base[r * DIM + t + 256];
        s1 += a; q1 = fmaf(a, a, q1);
        s2 += c; q2 = fmaf(c, c, q2);
    }
    g_part[0][z][t] = s1;
    g_part[1][z][t] = q1;
    g_part[0][z][t + 256] = s2;
    g_part[1][z][t + 256] = q2;
}

__global__ void k_bnfinal(const float* __restrict__ gamma,
                          const float* __restrict__ beta) {
    int c = threadIdx.x;
    float s = 0.f, s2 = 0.f;
    for (int i = 0; i < 64; i++) { s += g_part[0][i][c]; s2 += g_part[1][i][c]; }
    float mean = s * (1.f / 8192.f);
    float var = s2 * (1.f / 8192.f) - mean * mean;
    float rstd = rsqrtf(var + BN_EPSF);
    float sc = gamma[c] * rstd;
    g_scale[c] = sc;
    g_shift[c] = beta[c] - mean * sc;
}

// ---------------- BN apply + ReLU + transpose ---------------------------------
__global__ void k_bn_relu_t(float* __restrict__ out) {
    __shared__ float t[32][33];
    int p0 = blockIdx.x * 32, c0 = blockIdx.y * 32, b = blockIdx.z;
    int tx = threadIdx.x, ty = threadIdx.y;
#pragma unroll
    for (int u = 0; u < 4; u++) {
        int p = p0 + ty + u * 8;
        t[ty + u * 8][tx] = g_conv2[(((size_t)b << 10) + p) * DIM + c0 + tx];
    }
    __syncthreads();
#pragma unroll
    for (int u = 0; u < 4; u++) {
        int c = c0 + ty + u * 8;
        float v = fmaf(t[tx][ty + u * 8], g_scale[c], g_shift[c]);
        out[((size_t)b * DIM + c) * NPIX + p0 + tx] = v > 0.f ? v : 0.f;
    }
}

// ---------------- launch ------------------------------------------------------
extern "C" void kernel_launch(void* const* d_in, const int* in_sizes, int n_in,
                              void* d_out, int out_size) {
    const float* x      = (const float*)d_in[0];
    const float* W_qkv  = (const float*)d_in[1];
    const float* W_out  = (const float*)d_in[2];
    const float* gamma  = (const float*)d_in[3];
    const float* beta   = (const float*)d_in[4];
    float* out = (float*)d_out;

    k_prep_x<<<dim3(32, 16, BATCH), dim3(32, 8)>>>(x);
    k_prep_w<<<THREE_DIM, 256>>>(W_qkv);
    k_split_wout<<<(DIM * DIM + 255) / 256, 256>>>(W_out);

    cudaFuncSetAttribute(k_conv3x3_mma, cudaFuncAttributeMaxDynamicSharedMemorySize,
                         C3_SMEM);
    k_conv3x3_mma<<<dim3(8, 24, BATCH), 256, C3_SMEM>>>();

    k_norms<<<(BATCH * HEADS * NPIX) / 256, 256>>>();
    k_split_qkv<<<dim3(32, 2, 64), dim3(32, 8)>>>();
    k_split_v<<<(64 * HD * NPIX) / 256, 256>>>();

    cudaFuncSetAttribute(k_attn_mma, cudaFuncAttributeMaxDynamicSharedMemorySize,
                         ATN_SMEM);
    k_attn_mma<<<dim3(8, HEADS, BATCH), 256, ATN_SMEM>>>();

    cudaFuncSetAttribute(k_conv1x1_mma, cudaFuncAttributeMaxDynamicSharedMemorySize,
                         CONV_SMEM);
    k_conv1x1_mma<<<dim3(8, 4, BATCH), 256, CONV_SMEM>>>();

    k_bnpartial<<<64, 256>>>();
    k_bnfinal<<<1, DIM>>>(gamma, beta);
    k_bn_relu_t<<<dim3(32, 16, BATCH), dim3(32, 8)>>>(out);
}

// round 10
// speedup vs baseline: 4.3609x; 1.2470x over previous
#include <cuda_runtime.h>
#include <cuda_bf16.h>
#include <cuda_fp16.h>
#include <cstdint>

#define DIM 512
#define THREE_DIM 1536
#define NPIX 1024
#define BATCH 8
#define HEADS 8
#define HD 64
#define SMOOTHF 1e-4f
#define BN_EPSF 1e-5f

// ---------------- scratch (static __device__, no allocation) ----------------
__device__ float g_qkv[BATCH * THREE_DIM * NPIX];   // [b][c3][p]
__device__ float g_invqn[BATCH * HEADS * NPIX];
__device__ float g_invkn[BATCH * HEADS * NPIX];
__device__ float g_conv2[BATCH * NPIX * DIM];       // [b][p][c]
__device__ float g_scale[DIM];
__device__ float g_shift[DIM];
__device__ float g_part[2][64][DIM];                // BN partial sums
// fp16 split operands for conv3x3 (x split hi/lo, W rounded once)
__device__ __half g_xHhi[BATCH * NPIX * DIM];       // [b][p][ci]
__device__ __half g_xHlo[BATCH * NPIX * DIM];
__device__ __half g_WrH[9 * THREE_DIM * DIM];       // [kpos][co][ci]
// bf16 split operands for attention (normalized q,k; raw v transposed)
__device__ __nv_bfloat16 g_qhi[64 * NPIX * HD];     // [bg][n][d]  (q * invqn)
__device__ __nv_bfloat16 g_qlo[64 * NPIX * HD];
__device__ __nv_bfloat16 g_khi[64 * NPIX * HD];     // [bg][n][d]  (k * invkn)
__device__ __nv_bfloat16 g_klo[64 * NPIX * HD];
__device__ __nv_bfloat16 g_vThi[64 * HD * NPIX];    // [bg][d][n]
__device__ __nv_bfloat16 g_vTlo[64 * HD * NPIX];
// attention output (conv1x1 A operand), bf16 split
__device__ __nv_bfloat16 g_Ahi[BATCH * NPIX * DIM]; // [b][p][c]
__device__ __nv_bfloat16 g_Alo[BATCH * NPIX * DIM];
// conv1x1 weights split
__device__ __nv_bfloat16 g_w2hi[DIM * DIM];         // [co][ci]
__device__ __nv_bfloat16 g_w2lo[DIM * DIM];

// ---------------- helpers ----------------------------------------------------
__device__ __forceinline__ uint32_t s2u(const void* p) {
    uint32_t a;
    asm("{ .reg .u64 t; cvta.to.shared.u64 t, %1; cvt.u32.u64 %0, t; }"
        : "=r"(a) : "l"(p));
    return a;
}
__device__ __forceinline__ void cp_async16(uint32_t saddr, const void* gaddr, int sz) {
    asm volatile("cp.async.cg.shared.global [%0], [%1], 16, %2;"
                 :: "r"(saddr), "l"(gaddr), "r"(sz));
}
__device__ __forceinline__ void cp_commit() {
    asm volatile("cp.async.commit_group;" ::: "memory");
}
__device__ __forceinline__ void cp_wait0() {
    asm volatile("cp.async.wait_group 0;" ::: "memory");
}
__device__ __forceinline__ void ldsm_x4(uint32_t* r, uint32_t addr) {
    asm volatile("ldmatrix.sync.aligned.m8n8.x4.shared.b16 {%0,%1,%2,%3}, [%4];"
                 : "=r"(r[0]), "=r"(r[1]), "=r"(r[2]), "=r"(r[3]) : "r"(addr));
}
__device__ __forceinline__ void mma_bf16(float* d, const uint32_t* a,
                                         const uint32_t* b) {
    asm volatile(
        "mma.sync.aligned.m16n8k16.row.col.f32.bf16.bf16.f32 "
        "{%0,%1,%2,%3}, {%4,%5,%6,%7}, {%8,%9}, {%0,%1,%2,%3};"
        : "+f"(d[0]), "+f"(d[1]), "+f"(d[2]), "+f"(d[3])
        : "r"(a[0]), "r"(a[1]), "r"(a[2]), "r"(a[3]), "r"(b[0]), "r"(b[1]));
}
__device__ __forceinline__ void mma_fp16(float* d, const uint32_t* a,
                                         const uint32_t* b) {
    asm volatile(
        "mma.sync.aligned.m16n8k16.row.col.f32.f16.f16.f32 "
        "{%0,%1,%2,%3}, {%4,%5,%6,%7}, {%8,%9}, {%0,%1,%2,%3};"
        : "+f"(d[0]), "+f"(d[1]), "+f"(d[2]), "+f"(d[3])
        : "r"(a[0]), "r"(a[1]), "r"(a[2]), "r"(a[3]), "r"(b[0]), "r"(b[1]));
}
__device__ __forceinline__ uint32_t pack_bf16x2(float a, float b) {
    __nv_bfloat162 h = __floats2bfloat162_rn(a, b);
    return *(uint32_t*)&h;
}

// ---------------- prep: x -> [b][p][ci] fp16 hi/lo ----------------------------
__global__ void k_prep_x(const float* __restrict__ x) {
    __shared__ float t[32][33];
    int b = blockIdx.z, c0 = blockIdx.y * 32, p0 = blockIdx.x * 32;
    int tx = threadIdx.x, ty = threadIdx.y;  // 32 x 8
    const float* xb = x + ((size_t)b * DIM + c0) * NPIX + p0;
#pragma unroll
    for (int u = 0; u < 4; u++) t[ty + u * 8][tx] = xb[(ty + u * 8) * NPIX + tx];
    __syncthreads();
    size_t ob = ((size_t)b * NPIX + p0) * DIM + c0;
#pragma unroll
    for (int u = 0; u < 4; u++) {
        int p = ty + u * 8;
        float v = t[tx][p];
        __half hi = __float2half(v);
        g_xHhi[ob + (size_t)p * DIM + tx] = hi;
        g_xHlo[ob + (size_t)p * DIM + tx] = __float2half(v - __half2float(hi));
    }
}

// ---------------- prep: W_qkv -> [kpos][co][ci] fp16 --------------------------
__global__ void k_prep_w(const float* __restrict__ W) {
    __shared__ float s[4608];
    int co = blockIdx.x;
    const float* wr = W + (size_t)co * 4608;
    for (int i = threadIdx.x; i < 4608; i += 256) s[i] = wr[i];
    __syncthreads();
    for (int kpos = 0; kpos < 9; kpos++) {
        size_t ob = ((size_t)kpos * THREE_DIM + co) * DIM;
        for (int ci = threadIdx.x; ci < DIM; ci += 256)
            g_WrH[ob + ci] = __float2half(s[ci * 9 + kpos]);
    }
}

// ---------------- prep: W_out split ([co][ci], no transpose) ------------------
__global__ void k_split_wout(const float* __restrict__ W) {
    int idx = blockIdx.x * 256 + threadIdx.x;
    if (idx >= DIM * DIM) return;
    float v = W[idx];
    __nv_bfloat16 hi = __float2bfloat16(v);
    g_w2hi[idx] = hi;
    g_w2lo[idx] = __float2bfloat16(v - __bfloat162float(hi));
}

// ---------------- conv3x3 via mma.sync fp16 2-term, BM=128 BN=64 --------------
// D = (xh + xl) . Wh  (W rounded to fp16 once; error ~1.7e-4 rel)
// Stage: Ahi 16K | Alo 16K | Bh 8K = 40KB; double buffered = 80KB; 2 CTAs/SM.
#define C3_OFF_AHI 0
#define C3_OFF_ALO 16384
#define C3_OFF_BH  32768
#define C3_STAGE 40960
#define C3_SMEM (2 * C3_STAGE)

__global__ __launch_bounds__(256, 2) void k_conv3x3_mma(void) {
    extern __shared__ char smem[];
    const uint32_t sb = s2u(smem);
    const int tid = threadIdx.x;
    const int wid = tid >> 5, lane = tid & 31;
    const int b = blockIdx.z, co0 = blockIdx.y * 64, p0 = blockIdx.x * 128;
    const int wm = wid >> 1, wn = wid & 1;   // 4 x 2 warps, 32x32 tiles

    float acc[2][4][4];
#pragma unroll
    for (int i = 0; i < 2; i++)
#pragma unroll
        for (int j = 0; j < 4; j++)
#pragma unroll
            for (int q = 0; q < 4; q++) acc[i][j][q] = 0.f;

    auto issue = [&](int c, int buf) {
        int kpos = c >> 3, ci0 = (c & 7) << 6;
        int kh = kpos / 3 - 1, kw = kpos % 3 - 1;
        uint32_t S = sb + buf * C3_STAGE;
#pragma unroll
        for (int u = 0; u < 10; u++) {
            int unit = tid + u * 256;            // 0..2559
            if (unit < 2048) {
                // A: sel 0=hi 1=lo, 128 rows x 8 ch
                int sel = unit >> 10;
                int row = (unit >> 3) & 127, ch = unit & 7;
                int sw = row * 128 + ((ch ^ (row & 7)) << 4);
                int p = p0 + row;
                int h = (p >> 5) + kh, w = (p & 31) + kw;
                bool valid = ((unsigned)h < 32u) && ((unsigned)w < 32u);
                size_t offA = valid
                    ? (((((size_t)b << 10) + ((h << 5) + w)) << 9) + ci0 + (ch << 3))
                    : 0;
                int sz = valid ? 16 : 0;
                const char* src = sel ? (const char*)g_xHlo : (const char*)g_xHhi;
                cp_async16(S + (sel ? C3_OFF_ALO : C3_OFF_AHI) + sw,
                           src + offA * 2, sz);
            } else {
                // B: 64 rows x 8 ch (single fp16 tensor)
                int v2 = unit - 2048;
                int row = v2 >> 3, ch = v2 & 7;
                int sw = row * 128 + ((ch ^ (row & 7)) << 4);
                size_t offB = (((size_t)kpos * THREE_DIM + co0 + row) << 9)
                              + ci0 + (ch << 3);
                cp_async16(S + C3_OFF_BH + sw, (const char*)g_WrH + offB * 2, 16);
            }
        }
        cp_commit();
    };

    issue(0, 0);
    for (int c = 0; c < 72; c++) {
        int buf = c & 1;
        cp_wait0();
        __syncthreads();
        if (c + 1 < 72) issue(c + 1, buf ^ 1);

        uint32_t S = sb + buf * C3_STAGE;
        int rowA_lo = wm * 32 + (lane & 15);
        int kc8A = lane >> 4;
        int rowB_lo = wn * 32 + ((lane >> 4) << 3) + (lane & 7);
        int kc8B = (lane >> 3) & 1;
#pragma unroll
        for (int k16 = 0; k16 < 4; k16++) {
            uint32_t ah[2][4], al[2][4], bh[2][4];
#pragma unroll
            for (int mi = 0; mi < 2; mi++) {
                int row = rowA_lo + mi * 16;
                int ch = k16 * 2 + kc8A;
                uint32_t ad = S + row * 128 + ((ch ^ (row & 7)) << 4);
                ldsm_x4(ah[mi], ad + C3_OFF_AHI);
                ldsm_x4(al[mi], ad + C3_OFF_ALO);
            }
#pragma unroll
            for (int t = 0; t < 2; t++) {
                int row = rowB_lo + t * 16;
                int ch = k16 * 2 + kc8B;
                uint32_t ad = S + row * 128 + ((ch ^ (row & 7)) << 4);
                ldsm_x4(bh[t], ad + C3_OFF_BH);
            }
#pragma unroll
            for (int mi = 0; mi < 2; mi++)
#pragma unroll
                for (int nj = 0; nj < 4; nj++) {
                    const uint32_t* bhf = &bh[nj >> 1][(nj & 1) * 2];
                    mma_fp16(acc[mi][nj], ah[mi], bhf);   // xh * Wh
                    mma_fp16(acc[mi][nj], al[mi], bhf);   // xl * Wh
                }
        }
    }
    __syncthreads();

    // epilogue: frags -> smem T[p 128][co 64+pad4] -> g_qkv[co][p]
    float* T = (float*)smem;
#pragma unroll
    for (int mi = 0; mi < 2; mi++)
#pragma unroll
        for (int nj = 0; nj < 4; nj++) {
            int row = wm * 32 + mi * 16 + (lane >> 2);
            int col = wn * 32 + nj * 8 + (lane & 3) * 2;
            T[row * 68 + col]          = acc[mi][nj][0];
            T[row * 68 + col + 1]      = acc[mi][nj][1];
            T[(row + 8) * 68 + col]     = acc[mi][nj][2];
            T[(row + 8) * 68 + col + 1] = acc[mi][nj][3];
        }
    __syncthreads();
    float* outbase = g_qkv + ((size_t)b * THREE_DIM + co0) * NPIX + p0;
#pragma unroll
    for (int t = 0; t < 8; t++) {
        int cc = wid * 8 + t;
        float4 v;
        v.x = T[(lane * 4 + 0) * 68 + cc];
        v.y = T[(lane * 4 + 1) * 68 + cc];
        v.z = T[(lane * 4 + 2) * 68 + cc];
        v.w = T[(lane * 4 + 3) * 68 + cc];
        *(float4*)(outbase + (size_t)cc * NPIX + lane * 4) = v;
    }
}

// ---------------- q/k inverse norms ------------------------------------------
__global__ void k_norms(void) {
    int idx = blockIdx.x * 256 + threadIdx.x;
    int i = idx & 1023;
    int bg = idx >> 10;
    int b = bg >> 3, g = bg & 7;
    const float* qp = g_qkv + ((size_t)b * THREE_DIM + g * HD) * NPIX + i;
    const float* kp = qp + (size_t)DIM * NPIX;
    float sq = 0.f, sk = 0.f;
#pragma unroll 8
    for (int d = 0; d < HD; d++) {
        float vq = qp[d * NPIX]; sq = fmaf(vq, vq, sq);
        float vk = kp[d * NPIX]; sk = fmaf(vk, vk, sk);
    }
    g_invqn[idx] = rsqrtf(sq + SMOOTHF);
    g_invkn[idx] = rsqrtf(sk + SMOOTHF);
}

// ---------------- split q,k: normalize + transpose [d][n]->[n][d] + bf16 split
__global__ void k_split_qkv(void) {
    __shared__ float t[32][33];
    int n0 = blockIdx.x * 32, d0 = blockIdx.y * 32, bg = blockIdx.z;
    int b = bg >> 3, g = bg & 7;
    int tx = threadIdx.x, ty = threadIdx.y;  // 32 x 8
    const float* srcq = g_qkv + ((size_t)b * THREE_DIM + g * HD + d0) * NPIX + n0;
    // ---- q ----
#pragma unroll
    for (int u = 0; u < 4; u++)
        t[ty + u * 8][tx] = srcq[(size_t)(ty + u * 8) * NPIX + tx];
    __syncthreads();
#pragma unroll
    for (int u = 0; u < 4; u++) {
        int nl = ty + u * 8;
        int n = n0 + nl;
        float iv = g_invqn[((size_t)bg << 10) + n];
        float v = t[tx][nl] * iv;
        __nv_bfloat16 hi = __float2bfloat16(v);
        size_t o = (((size_t)bg << 10) + n) * HD + d0 + tx;
        g_qhi[o] = hi;
        g_qlo[o] = __float2bfloat16(v - __bfloat162float(hi));
    }
    __syncthreads();
    // ---- k ----
    const float* srck = srcq + (size_t)DIM * NPIX;
#pragma unroll
    for (int u = 0; u < 4; u++)
        t[ty + u * 8][tx] = srck[(size_t)(ty + u * 8) * NPIX + tx];
    __syncthreads();
#pragma unroll
    for (int u = 0; u < 4; u++) {
        int nl = ty + u * 8;
        int n = n0 + nl;
        float iv = g_invkn[((size_t)bg << 10) + n];
        float v = t[tx][nl] * iv;
        __nv_bfloat16 hi = __float2bfloat16(v);
        size_t o = (((size_t)bg << 10) + n) * HD + d0 + tx;
        g_khi[o] = hi;
        g_klo[o] = __float2bfloat16(v - __bfloat162float(hi));
    }
}

// ---------------- split v (keeps [d][n] layout) -------------------------------
__global__ void k_split_v(void) {
    int idx = blockIdx.x * 256 + threadIdx.x;   // 64*64*1024 total
    int bg = idx >> 16;
    int rem = idx & 65535;
    int d = rem >> 10, n = rem & 1023;
    int b = bg >> 3, g = bg & 7;
    float v = g_qkv[((size_t)b * THREE_DIM + 2 * DIM + g * HD + d) * NPIX + n];
    __nv_bfloat16 hi = __float2bfloat16(v);
    size_t o = ((size_t)bg * HD + d) * NPIX + n;
    g_vThi[o] = hi;
    g_vTlo[o] = __float2bfloat16(v - __bfloat162float(hi));
}

// ---------------- attention via mma.sync bf16 (unchanged, passing) ------------
#define ATN_QHI 0
#define ATN_QLO 16384
#define ATN_K(buf)  (32768 + (buf) * 16384)   // Khi +0, Klo +8192
#define ATN_VT(buf) (65536 + (buf) * 16384)   // VThi +0, VTlo +8192
#define ATN_SHI 98304
#define ATN_SLO 114688
#define ATN_IQ 131072
#define ATN_IK 131584                          // + buf*256
#define ATN_SMEM 132096

__global__ __launch_bounds__(256, 1) void k_attn_mma(void) {
    extern __shared__ char smem[];
    const uint32_t sb = s2u(smem);
    const int tid = threadIdx.x, wid = tid >> 5, lane = tid & 31;
    const int i0 = blockIdx.x * 128;
    const int g = blockIdx.y, b = blockIdx.z;
    const int bg = b * 8 + g;
    const int wm = wid & 3, wn = wid >> 2;

#pragma unroll
    for (int u = 0; u < 4; u++) {
        int unit = tid + u * 256;
        int row = unit >> 3, ch = unit & 7;
        int sw = row * 128 + ((ch ^ (row & 7)) << 4);
        size_t go = (((size_t)bg << 10) + i0 + row) * 128 + ch * 16;
        cp_async16(sb + ATN_QHI + sw, (const char*)g_qhi + go, 16);
        cp_async16(sb + ATN_QLO + sw, (const char*)g_qlo + go, 16);
    }
    if (tid < 128)
        ((float*)(smem + ATN_IQ))[tid] = g_invqn[((size_t)bg << 10) + i0 + tid];
    cp_commit();

    auto issueKV = [&](int j0, int buf) {
#pragma unroll
        for (int u = 0; u < 8; u++) {
            int unit = tid + u * 256;
            int sel = unit >> 9;
            int r2 = (unit >> 3) & 63, ch = unit & 7;
            int sw = r2 * 128 + ((ch ^ (r2 & 7)) << 4);
            uint32_t dst;
            const char* src;
            if (sel == 0) {
                dst = sb + ATN_K(buf) + sw;
                src = (const char*)g_khi + (((size_t)bg << 10) + j0 + r2) * 128 + ch * 16;
            } else if (sel == 1) {
                dst = sb + ATN_K(buf) + 8192 + sw;
                src = (const char*)g_klo + (((size_t)bg << 10) + j0 + r2) * 128 + ch * 16;
            } else if (sel == 2) {
                dst = sb + ATN_VT(buf) + sw;
                src = (const char*)g_vThi + (((size_t)bg * HD + r2) * NPIX + j0) * 2 + ch * 16;
            } else {
                dst = sb + ATN_VT(buf) + 8192 + sw;
                src = (const char*)g_vTlo + (((size_t)bg * HD + r2) * NPIX + j0) * 2 + ch * 16;
            }
            cp_async16(dst, src, 16);
        }
        if (tid < 64)
            ((float*)(smem + ATN_IK + buf * 256))[tid] =
                g_invkn[((size_t)bg << 10) + j0 + tid];
        cp_commit();
    };
    issueKV(0, 0);

    float acco[2][4][4];
#pragma unroll
    for (int i = 0; i < 2; i++)
#pragma unroll
        for (int j = 0; j < 4; j++)
#pragma unroll
            for (int q = 0; q < 4; q++) acco[i][j][q] = 0.f;

    for (int jt = 0; jt < 16; jt++) {
        int buf = jt & 1;
        cp_wait0();
        __syncthreads();
        if (jt < 15) issueKV((jt + 1) * 64, buf ^ 1);

        float s[2][4][4];
#pragma unroll
        for (int i = 0; i < 2; i++)
#pragma unroll
            for (int j = 0; j < 4; j++)
#pragma unroll
                for (int q = 0; q < 4; q++) s[i][j][q] = 0.f;
        {
            uint32_t Qh = sb + ATN_QHI, Ql = sb + ATN_QLO;
            uint32_t Kh = sb + ATN_K(buf), Kl = Kh + 8192;
#pragma unroll
            for (int k16 = 0; k16 < 4; k16++) {
                uint32_t ah[2][4], al[2][4], bh[2][4], bl[2][4];
#pragma unroll
                for (int mi = 0; mi < 2; mi++) {
                    int row = wm * 32 + mi * 16 + (lane & 15);
                    int ch = k16 * 2 + (lane >> 4);
                    uint32_t ad = row * 128 + ((ch ^ (row & 7)) << 4);
                    ldsm_x4(ah[mi], Qh + ad);
                    ldsm_x4(al[mi], Ql + ad);
                }
#pragma unroll
                for (int t = 0; t < 2; t++) {
                    int row = wn * 32 + t * 16 + ((lane >> 4) << 3) + (lane & 7);
                    int ch = k16 * 2 + ((lane >> 3) & 1);
                    uint32_t ad = row * 128 + ((ch ^ (row & 7)) << 4);
                    ldsm_x4(bh[t], Kh + ad);
                    ldsm_x4(bl[t], Kl + ad);
                }
#pragma unroll
                for (int mi = 0; mi < 2; mi++)
#pragma unroll
                    for (int nj = 0; nj < 4; nj++) {
                        const uint32_t* bhf = &bh[nj >> 1][(nj & 1) * 2];
                        const uint32_t* blf = &bl[nj >> 1][(nj & 1) * 2];
                        mma_bf16(s[mi][nj], ah[mi], bhf);
                        mma_bf16(s[mi][nj], ah[mi], blf);
                        mma_bf16(s[mi][nj], al[mi], bhf);
                    }
            }
        }
        {
            const float* IQ = (const float*)(smem + ATN_IQ);
            const float* IK = (const float*)(smem + ATN_IK + buf * 256);
#pragma unroll
            for (int mi = 0; mi < 2; mi++) {
                int r0 = wm * 32 + mi * 16 + (lane >> 2);
                float iq0 = IQ[r0], iq1 = IQ[r0 + 8];
#pragma unroll
                for (int nj = 0; nj < 4; nj++) {
                    int col = wn * 32 + nj * 8 + (lane & 3) * 2;
                    float ik0 = IK[col], ik1 = IK[col + 1];
                    float* u = s[mi][nj];
                    float t00 = iq0 * ik0, t01 = iq0 * ik1;
                    float t10 = iq1 * ik0, t11 = iq1 * ik1;
                    float v0 = fmaf(-SMOOTHF * t00, u[0], u[0]);
                    float v1 = fmaf(-SMOOTHF * t01, u[1], u[1]);
                    float v2 = fmaf(-SMOOTHF * t10, u[2], u[2]);
                    float v3 = fmaf(-SMOOTHF * t11, u[3], u[3]);
                    __nv_bfloat162 h01 = __floats2bfloat162_rn(v0, v1);
                    float r0f = v0 - __bfloat162float(h01.x);
                    float r1f = v1 - __bfloat162float(h01.y);
                    __nv_bfloat162 h23 = __floats2bfloat162_rn(v2, v3);
                    float r2f = v2 - __bfloat162float(h23.x);
                    float r3f = v3 - __bfloat162float(h23.y);
                    int bo = col * 2;
                    int ch = bo >> 4, wi = bo & 15;
                    int a0 = r0 * 128 + ((ch ^ (r0 & 7)) << 4) + wi;
                    int a1 = (r0 + 8) * 128 + ((ch ^ ((r0 + 8) & 7)) << 4) + wi;
                    *(uint32_t*)(smem + ATN_SHI + a0) = *(uint32_t*)&h01;
                    *(uint32_t*)(smem + ATN_SHI + a1) = *(uint32_t*)&h23;
                    *(uint32_t*)(smem + ATN_SLO + a0) = pack_bf16x2(r0f, r1f);
                    *(uint32_t*)(smem + ATN_SLO + a1) = pack_bf16x2(r2f, r3f);
                }
            }
        }
        __syncthreads();
        {
            uint32_t Sh = sb + ATN_SHI, Sl = sb + ATN_SLO;
            uint32_t Vh = sb + ATN_VT(buf), Vl = Vh + 8192;
#pragma unroll
            for (int k16 = 0; k16 < 4; k16++) {
                uint32_t ah[2][4], al[2][4], bh[2][4], bl[2][4];
#pragma unroll
                for (int mi = 0; mi < 2; mi++) {
                    int row = wm * 32 + mi * 16 + (lane & 15);
                    int ch = k16 * 2 + (lane >> 4);
                    uint32_t ad = row * 128 + ((ch ^ (row & 7)) << 4);
                    ldsm_x4(ah[mi], Sh + ad);
                    ldsm_x4(al[mi], Sl + ad);
                }
#pragma unroll
                for (int t = 0; t < 2; t++) {
                    int row = wn * 32 + t * 16 + ((lane >> 4) << 3) + (lane & 7);
                    int ch = k16 * 2 + ((lane >> 3) & 1);
                    uint32_t ad = row * 128 + ((ch ^ (row & 7)) << 4);
                    ldsm_x4(bh[t], Vh + ad);
                    ldsm_x4(bl[t], Vl + ad);
                }
#pragma unroll
                for (int mi = 0; mi < 2; mi++)
#pragma unroll
                    for (int nj = 0; nj < 4; nj++) {
                        const uint32_t* bhf = &bh[nj >> 1][(nj & 1) * 2];
                        const uint32_t* blf = &bl[nj >> 1][(nj & 1) * 2];
                        mma_bf16(acco[mi][nj], ah[mi], bhf);
                        mma_bf16(acco[mi][nj], ah[mi], blf);
                        mma_bf16(acco[mi][nj], al[mi], bhf);
                    }
            }
        }
    }
#pragma unroll
    for (int mi = 0; mi < 2; mi++)
#pragma unroll
        for (int nj = 0; nj < 4; nj++) {
            int row = wm * 32 + mi * 16 + (lane >> 2);
            int col = g * HD + wn * 32 + nj * 8 + (lane & 3) * 2;
            float* u = acco[mi][nj];
            __nv_bfloat162 h01 = __floats2bfloat162_rn(u[0], u[1]);
            __nv_bfloat162 h23 = __floats2bfloat162_rn(u[2], u[3]);
            size_t o0 = (((size_t)b << 10) + i0 + row) * DIM + col;
            size_t o1 = (((size_t)b << 10) + i0 + row + 8) * DIM + col;
            *(uint32_t*)((char*)g_Ahi + o0 * 2) = *(uint32_t*)&h01;
            *(uint32_t*)((char*)g_Ahi + o1 * 2) = *(uint32_t*)&h23;
            *(uint32_t*)((char*)g_Alo + o0 * 2) =
                pack_bf16x2(u[0] - __bfloat162float(h01.x),
                            u[1] - __bfloat162float(h01.y));
            *(uint32_t*)((char*)g_Alo + o1 * 2) =
                pack_bf16x2(u[2] - __bfloat162float(h23.x),
                            u[3] - __bfloat162float(h23.y));
        }
}

// ---------------- conv1x1 via mma.sync bf16 (unchanged, passing) --------------
#define STAGE_BYTES 65536
#define OFF_AHI 0
#define OFF_ALO 16384
#define OFF_BHI 32768
#define OFF_BLO 49152
#define CONV_SMEM (2 * STAGE_BYTES)

__global__ __launch_bounds__(256) void k_conv1x1_mma(void) {
    extern __shared__ char smem[];
    const uint32_t sb = s2u(smem);
    const int tid = threadIdx.x;
    const int wid = tid >> 5, lane = tid & 31;
    const int b = blockIdx.z, co0 = blockIdx.y * 128, p0 = blockIdx.x * 128;
    const int wm = wid & 1, wn = wid >> 1;

    float acc[4][4][4];
#pragma unroll
    for (int i = 0; i < 4; i++)
#pragma unroll
        for (int j = 0; j < 4; j++)
#pragma unroll
            for (int q = 0; q < 4; q++) acc[i][j][q] = 0.f;

    auto issue = [&](int c, int buf) {
        int ci0 = c << 6;
        uint32_t S = sb + buf * STAGE_BYTES;
#pragma unroll
        for (int u = 0; u < 4; u++) {
            int unit = tid + u * 256;
            int row = unit >> 3, ch = unit & 7;
            int sw = row * 128 + ((ch ^ (row & 7)) << 4);
            size_t offA = ((((size_t)b << 10) + p0 + row) << 9) + ci0 + (ch << 3);
            cp_async16(S + OFF_AHI + sw, (const char*)g_Ahi + offA * 2, 16);
            cp_async16(S + OFF_ALO + sw, (const char*)g_Alo + offA * 2, 16);
            size_t offB = (((size_t)co0 + row) << 9) + ci0 + (ch << 3);
            cp_async16(S + OFF_BHI + sw, (const char*)g_w2hi + offB * 2, 16);
            cp_async16(S + OFF_BLO + sw, (const char*)g_w2lo + offB * 2, 16);
        }
        cp_commit();
    };

    issue(0, 0);
    for (int c = 0; c < 8; c++) {
        int buf = c & 1;
        cp_wait0();
        __syncthreads();
        if (c + 1 < 8) issue(c + 1, buf ^ 1);

        uint32_t S = sb + buf * STAGE_BYTES;
        int rowA_lo = wm * 64 + (lane & 15);
        int kc8A = lane >> 4;
        int rowB_lo = wn * 32 + ((lane >> 4) << 3) + (lane & 7);
        int kc8B = (lane >> 3) & 1;
#pragma unroll
        for (int k16 = 0; k16 < 4; k16++) {
            uint32_t ah[4][4], al[4][4], bh[2][4], bl[2][4];
#pragma unroll
            for (int mi = 0; mi < 4; mi++) {
                int row = rowA_lo + mi * 16;
                int ch = k16 * 2 + kc8A;
                uint32_t ad = S + row * 128 + ((ch ^ (row & 7)) << 4);
                ldsm_x4(ah[mi], ad + OFF_AHI);
                ldsm_x4(al[mi], ad + OFF_ALO);
            }
#pragma unroll
            for (int t = 0; t < 2; t++) {
                int row = rowB_lo + t * 16;
                int ch = k16 * 2 + kc8B;
                uint32_t ad = S + row * 128 + ((ch ^ (row & 7)) << 4);
                ldsm_x4(bh[t], ad + OFF_BHI);
                ldsm_x4(bl[t], ad + OFF_BLO);
            }
#pragma unroll
            for (int mi = 0; mi < 4; mi++)
#pragma unroll
                for (int nj = 0; nj < 4; nj++) {
                    const uint32_t* bhf = &bh[nj >> 1][(nj & 1) * 2];
                    const uint32_t* blf = &bl[nj >> 1][(nj & 1) * 2];
                    mma_bf16(acc[mi][nj], ah[mi], bhf);
                    mma_bf16(acc[mi][nj], ah[mi], blf);
                    mma_bf16(acc[mi][nj], al[mi], bhf);
                }
        }
    }
#pragma unroll
    for (int mi = 0; mi < 4; mi++)
#pragma unroll
        for (int nj = 0; nj < 4; nj++) {
            int row = wm * 64 + mi * 16 + (lane >> 2);
            int col = wn * 32 + nj * 8 + (lane & 3) * 2;
            float* u = acc[mi][nj];
            size_t o0 = (((size_t)b << 10) + p0 + row) * DIM + co0 + col;
            size_t o1 = o0 + 8 * DIM;
            *(float2*)(g_conv2 + o0) = make_float2(u[0], u[1]);
            *(float2*)(g_conv2 + o1) = make_float2(u[2], u[3]);
        }
}

// ---------------- BN partial sums ---------------------------------------------
__global__ void k_bnpartial(void) {
    int z = blockIdx.x;
    int t = threadIdx.x;
    const float* base = g_conv2 + (size_t)z * 128 * DIM;
    float s1 = 0.f, q1 = 0.f, s2 = 0.f, q2 = 0.f;
    for (int r = 0; r < 128; r++) {
        float a = base[r * DIM + t];
        float c = base[r * DIM + t + 256];
        s1 += a; q1 = fmaf(a, a, q1);
        s2 += c; q2 = fmaf(c, c, q2);
    }
    g_part[0][z][t] = s1;
    g_part[1][z][t] = q1;
    g_part[0][z][t + 256] = s2;
    g_part[1][z][t + 256] = q2;
}

__global__ void k_bnfinal(const float* __restrict__ gamma,
                          const float* __restrict__ beta) {
    int c = threadIdx.x;
    float s = 0.f, s2 = 0.f;
    for (int i = 0; i < 64; i++) { s += g_part[0][i][c]; s2 += g_part[1][i][c]; }
    float mean = s * (1.f / 8192.f);
    float var = s2 * (1.f / 8192.f) - mean * mean;
    float rstd = rsqrtf(var + BN_EPSF);
    float sc = gamma[c] * rstd;
    g_scale[c] = sc;
    g_shift[c] = beta[c] - mean * sc;
}

// ---------------- BN apply + ReLU + transpose ---------------------------------
__global__ void k_bn_relu_t(float* __restrict__ out) {
    __shared__ float t[32][33];
    int p0 = blockIdx.x * 32, c0 = blockIdx.y * 32, b = blockIdx.z;
    int tx = threadIdx.x, ty = threadIdx.y;
#pragma unroll
    for (int u = 0; u < 4; u++) {
        int p = p0 + ty + u * 8;
        t[ty + u * 8][tx] = g_conv2[(((size_t)b << 10) + p) * DIM + c0 + tx];
    }
    __syncthreads();
#pragma unroll
    for (int u = 0; u < 4; u++) {
        int c = c0 + ty + u * 8;
        float v = fmaf(t[tx][ty + u * 8], g_scale[c], g_shift[c]);
        out[((size_t)b * DIM + c) * NPIX + p0 + tx] = v > 0.f ? v : 0.f;
    }
}

// ---------------- launch ------------------------------------------------------
extern "C" void kernel_launch(void* const* d_in, const int* in_sizes, int n_in,
                              void* d_out, int out_size) {
    const float* x      = (const float*)d_in[0];
    const float* W_qkv  = (const float*)d_in[1];
    const float* W_out  = (const float*)d_in[2];
    const float* gamma  = (const float*)d_in[3];
    const float* beta   = (const float*)d_in[4];
    float* out = (float*)d_out;

    k_prep_x<<<dim3(32, 16, BATCH), dim3(32, 8)>>>(x);
    k_prep_w<<<THREE_DIM, 256>>>(W_qkv);
    k_split_wout<<<(DIM * DIM + 255) / 256, 256>>>(W_out);

    cudaFuncSetAttribute(k_conv3x3_mma, cudaFuncAttributeMaxDynamicSharedMemorySize,
                         C3_SMEM);
    k_conv3x3_mma<<<dim3(8, 24, BATCH), 256, C3_SMEM>>>();

    k_norms<<<(BATCH * HEADS * NPIX) / 256, 256>>>();
    k_split_qkv<<<dim3(32, 2, 64), dim3(32, 8)>>>();
    k_split_v<<<(64 * HD * NPIX) / 256, 256>>>();

    cudaFuncSetAttribute(k_attn_mma, cudaFuncAttributeMaxDynamicSharedMemorySize,
                         ATN_SMEM);
    k_attn_mma<<<dim3(8, HEADS, BATCH), 256, ATN_SMEM>>>();

    cudaFuncSetAttribute(k_conv1x1_mma, cudaFuncAttributeMaxDynamicSharedMemorySize,
                         CONV_SMEM);
    k_conv1x1_mma<<<dim3(8, 4, BATCH), 256, CONV_SMEM>>>();

    k_bnpartial<<<64, 256>>>();
    k_bnfinal<<<1, DIM>>>(gamma, beta);
    k_bn_relu_t<<<dim3(32, 16, BATCH), dim3(32, 8)>>>(out);
}

// round 11
// speedup vs baseline: 4.7017x; 1.0781x over previous
#include <cuda_runtime.h>
#include <cuda_bf16.h>
#include <cuda_fp16.h>
#include <cstdint>

#define DIM 512
#define THREE_DIM 1536
#define NPIX 1024
#define BATCH 8
#define HEADS 8
#define HD 64
#define SMOOTHF 1e-4f
#define BN_EPSF 1e-5f

// ---------------- scratch (static __device__, no allocation) ----------------
__device__ float g_qkv[BATCH * THREE_DIM * NPIX];   // [b][c3][p]
__device__ float g_invqn[BATCH * HEADS * NPIX];
__device__ float g_invkn[BATCH * HEADS * NPIX];
__device__ float g_conv2[BATCH * NPIX * DIM];       // [b][p][c]
__device__ float g_scale[DIM];
__device__ float g_shift[DIM];
__device__ float g_part[2][64][DIM];                // BN partial sums
// fp16 split operands for conv3x3 (x split hi/lo, W rounded once)
__device__ __half g_xHhi[BATCH * NPIX * DIM];       // [b][p][ci]
__device__ __half g_xHlo[BATCH * NPIX * DIM];
__device__ __half g_WrH[9 * THREE_DIM * DIM];       // [kpos][co][ci]
// fp16 operands for attention (q split hi/lo; k,v rounded once)
__device__ __half g_qfhi[64 * NPIX * HD];           // [bg][n][d]  (q * invqn)
__device__ __half g_qflo[64 * NPIX * HD];
__device__ __half g_kf[64 * NPIX * HD];             // [bg][n][d]  (k * invkn)
__device__ __half g_vTf[64 * HD * NPIX];            // [bg][d][n]
// attention output (conv1x1 A operand), bf16 split
__device__ __nv_bfloat16 g_Ahi[BATCH * NPIX * DIM]; // [b][p][c]
__device__ __nv_bfloat16 g_Alo[BATCH * NPIX * DIM];
// conv1x1 weights split (bf16 3-term kept for accuracy)
__device__ __nv_bfloat16 g_w2hi[DIM * DIM];         // [co][ci]
__device__ __nv_bfloat16 g_w2lo[DIM * DIM];

// ---------------- helpers ----------------------------------------------------
__device__ __forceinline__ uint32_t s2u(const void* p) {
    uint32_t a;
    asm("{ .reg .u64 t; cvta.to.shared.u64 t, %1; cvt.u32.u64 %0, t; }"
        : "=r"(a) : "l"(p));
    return a;
}
__device__ __forceinline__ void cp_async16(uint32_t saddr, const void* gaddr, int sz) {
    asm volatile("cp.async.cg.shared.global [%0], [%1], 16, %2;"
                 :: "r"(saddr), "l"(gaddr), "r"(sz));
}
__device__ __forceinline__ void cp_commit() {
    asm volatile("cp.async.commit_group;" ::: "memory");
}
__device__ __forceinline__ void cp_wait0() {
    asm volatile("cp.async.wait_group 0;" ::: "memory");
}
__device__ __forceinline__ void ldsm_x4(uint32_t* r, uint32_t addr) {
    asm volatile("ldmatrix.sync.aligned.m8n8.x4.shared.b16 {%0,%1,%2,%3}, [%4];"
                 : "=r"(r[0]), "=r"(r[1]), "=r"(r[2]), "=r"(r[3]) : "r"(addr));
}
__device__ __forceinline__ void mma_bf16(float* d, const uint32_t* a,
                                         const uint32_t* b) {
    asm volatile(
        "mma.sync.aligned.m16n8k16.row.col.f32.bf16.bf16.f32 "
        "{%0,%1,%2,%3}, {%4,%5,%6,%7}, {%8,%9}, {%0,%1,%2,%3};"
        : "+f"(d[0]), "+f"(d[1]), "+f"(d[2]), "+f"(d[3])
        : "r"(a[0]), "r"(a[1]), "r"(a[2]), "r"(a[3]), "r"(b[0]), "r"(b[1]));
}
__device__ __forceinline__ void mma_fp16(float* d, const uint32_t* a,
                                         const uint32_t* b) {
    asm volatile(
        "mma.sync.aligned.m16n8k16.row.col.f32.f16.f16.f32 "
        "{%0,%1,%2,%3}, {%4,%5,%6,%7}, {%8,%9}, {%0,%1,%2,%3};"
        : "+f"(d[0]), "+f"(d[1]), "+f"(d[2]), "+f"(d[3])
        : "r"(a[0]), "r"(a[1]), "r"(a[2]), "r"(a[3]), "r"(b[0]), "r"(b[1]));
}
__device__ __forceinline__ uint32_t pack_bf16x2(float a, float b) {
    __nv_bfloat162 h = __floats2bfloat162_rn(a, b);
    return *(uint32_t*)&h;
}
__device__ __forceinline__ uint32_t pack_h2(float a, float b) {
    __half2 h = __floats2half2_rn(a, b);
    return *(uint32_t*)&h;
}

// ---------------- prep: x -> [b][p][ci] fp16 hi/lo ----------------------------
__global__ void k_prep_x(const float* __restrict__ x) {
    __shared__ float t[32][33];
    int b = blockIdx.z, c0 = blockIdx.y * 32, p0 = blockIdx.x * 32;
    int tx = threadIdx.x, ty = threadIdx.y;  // 32 x 8
    const float* xb = x + ((size_t)b * DIM + c0) * NPIX + p0;
#pragma unroll
    for (int u = 0; u < 4; u++) t[ty + u * 8][tx] = xb[(ty + u * 8) * NPIX + tx];
    __syncthreads();
    size_t ob = ((size_t)b * NPIX + p0) * DIM + c0;
#pragma unroll
    for (int u = 0; u < 4; u++) {
        int p = ty + u * 8;
        float v = t[tx][p];
        __half hi = __float2half(v);
        g_xHhi[ob + (size_t)p * DIM + tx] = hi;
        g_xHlo[ob + (size_t)p * DIM + tx] = __float2half(v - __half2float(hi));
    }
}

// ---------------- prep: W_qkv -> [kpos][co][ci] fp16 --------------------------
__global__ void k_prep_w(const float* __restrict__ W) {
    __shared__ float s[4608];
    int co = blockIdx.x;
    const float* wr = W + (size_t)co * 4608;
    for (int i = threadIdx.x; i < 4608; i += 256) s[i] = wr[i];
    __syncthreads();
    for (int kpos = 0; kpos < 9; kpos++) {
        size_t ob = ((size_t)kpos * THREE_DIM + co) * DIM;
        for (int ci = threadIdx.x; ci < DIM; ci += 256)
            g_WrH[ob + ci] = __float2half(s[ci * 9 + kpos]);
    }
}

// ---------------- prep: W_out split ([co][ci], no transpose) ------------------
__global__ void k_split_wout(const float* __restrict__ W) {
    int idx = blockIdx.x * 256 + threadIdx.x;
    if (idx >= DIM * DIM) return;
    float v = W[idx];
    __nv_bfloat16 hi = __float2bfloat16(v);
    g_w2hi[idx] = hi;
    g_w2lo[idx] = __float2bfloat16(v - __bfloat162float(hi));
}

// ---------------- conv3x3 via mma.sync fp16 2-term (unchanged, passing) -------
#define C3_OFF_AHI 0
#define C3_OFF_ALO 16384
#define C3_OFF_BH  32768
#define C3_STAGE 40960
#define C3_SMEM (2 * C3_STAGE)

__global__ __launch_bounds__(256, 2) void k_conv3x3_mma(void) {
    extern __shared__ char smem[];
    const uint32_t sb = s2u(smem);
    const int tid = threadIdx.x;
    const int wid = tid >> 5, lane = tid & 31;
    const int b = blockIdx.z, co0 = blockIdx.y * 64, p0 = blockIdx.x * 128;
    const int wm = wid >> 1, wn = wid & 1;   // 4 x 2 warps, 32x32 tiles

    float acc[2][4][4];
#pragma unroll
    for (int i = 0; i < 2; i++)
#pragma unroll
        for (int j = 0; j < 4; j++)
#pragma unroll
            for (int q = 0; q < 4; q++) acc[i][j][q] = 0.f;

    auto issue = [&](int c, int buf) {
        int kpos = c >> 3, ci0 = (c & 7) << 6;
        int kh = kpos / 3 - 1, kw = kpos % 3 - 1;
        uint32_t S = sb + buf * C3_STAGE;
#pragma unroll
        for (int u = 0; u < 10; u++) {
            int unit = tid + u * 256;            // 0..2559
            if (unit < 2048) {
                int sel = unit >> 10;
                int row = (unit >> 3) & 127, ch = unit & 7;
                int sw = row * 128 + ((ch ^ (row & 7)) << 4);
                int p = p0 + row;
                int h = (p >> 5) + kh, w = (p & 31) + kw;
                bool valid = ((unsigned)h < 32u) && ((unsigned)w < 32u);
                size_t offA = valid
                    ? (((((size_t)b << 10) + ((h << 5) + w)) << 9) + ci0 + (ch << 3))
                    : 0;
                int sz = valid ? 16 : 0;
                const char* src = sel ? (const char*)g_xHlo : (const char*)g_xHhi;
                cp_async16(S + (sel ? C3_OFF_ALO : C3_OFF_AHI) + sw,
                           src + offA * 2, sz);
            } else {
                int v2 = unit - 2048;
                int row = v2 >> 3, ch = v2 & 7;
                int sw = row * 128 + ((ch ^ (row & 7)) << 4);
                size_t offB = (((size_t)kpos * THREE_DIM + co0 + row) << 9)
                              + ci0 + (ch << 3);
                cp_async16(S + C3_OFF_BH + sw, (const char*)g_WrH + offB * 2, 16);
            }
        }
        cp_commit();
    };

    issue(0, 0);
    for (int c = 0; c < 72; c++) {
        int buf = c & 1;
        cp_wait0();
        __syncthreads();
        if (c + 1 < 72) issue(c + 1, buf ^ 1);

        uint32_t S = sb + buf * C3_STAGE;
        int rowA_lo = wm * 32 + (lane & 15);
        int kc8A = lane >> 4;
        int rowB_lo = wn * 32 + ((lane >> 4) << 3) + (lane & 7);
        int kc8B = (lane >> 3) & 1;
#pragma unroll
        for (int k16 = 0; k16 < 4; k16++) {
            uint32_t ah[2][4], al[2][4], bh[2][4];
#pragma unroll
            for (int mi = 0; mi < 2; mi++) {
                int row = rowA_lo + mi * 16;
                int ch = k16 * 2 + kc8A;
                uint32_t ad = S + row * 128 + ((ch ^ (row & 7)) << 4);
                ldsm_x4(ah[mi], ad + C3_OFF_AHI);
                ldsm_x4(al[mi], ad + C3_OFF_ALO);
            }
#pragma unroll
            for (int t = 0; t < 2; t++) {
                int row = rowB_lo + t * 16;
                int ch = k16 * 2 + kc8B;
                uint32_t ad = S + row * 128 + ((ch ^ (row & 7)) << 4);
                ldsm_x4(bh[t], ad + C3_OFF_BH);
            }
#pragma unroll
            for (int mi = 0; mi < 2; mi++)
#pragma unroll
                for (int nj = 0; nj < 4; nj++) {
                    const uint32_t* bhf = &bh[nj >> 1][(nj & 1) * 2];
                    mma_fp16(acc[mi][nj], ah[mi], bhf);
                    mma_fp16(acc[mi][nj], al[mi], bhf);
                }
        }
    }
    __syncthreads();

    float* T = (float*)smem;
#pragma unroll
    for (int mi = 0; mi < 2; mi++)
#pragma unroll
        for (int nj = 0; nj < 4; nj++) {
            int row = wm * 32 + mi * 16 + (lane >> 2);
            int col = wn * 32 + nj * 8 + (lane & 3) * 2;
            T[row * 68 + col]          = acc[mi][nj][0];
            T[row * 68 + col + 1]      = acc[mi][nj][1];
            T[(row + 8) * 68 + col]     = acc[mi][nj][2];
            T[(row + 8) * 68 + col + 1] = acc[mi][nj][3];
        }
    __syncthreads();
    float* outbase = g_qkv + ((size_t)b * THREE_DIM + co0) * NPIX + p0;
#pragma unroll
    for (int t = 0; t < 8; t++) {
        int cc = wid * 8 + t;
        float4 v;
        v.x = T[(lane * 4 + 0) * 68 + cc];
        v.y = T[(lane * 4 + 1) * 68 + cc];
        v.z = T[(lane * 4 + 2) * 68 + cc];
        v.w = T[(lane * 4 + 3) * 68 + cc];
        *(float4*)(outbase + (size_t)cc * NPIX + lane * 4) = v;
    }
}

// ---------------- q/k inverse norms ------------------------------------------
__global__ void k_norms(void) {
    int idx = blockIdx.x * 256 + threadIdx.x;
    int i = idx & 1023;
    int bg = idx >> 10;
    int b = bg >> 3, g = bg & 7;
    const float* qp = g_qkv + ((size_t)b * THREE_DIM + g * HD) * NPIX + i;
    const float* kp = qp + (size_t)DIM * NPIX;
    float sq = 0.f, sk = 0.f;
#pragma unroll 8
    for (int d = 0; d < HD; d++) {
        float vq = qp[d * NPIX]; sq = fmaf(vq, vq, sq);
        float vk = kp[d * NPIX]; sk = fmaf(vk, vk, sk);
    }
    g_invqn[idx] = rsqrtf(sq + SMOOTHF);
    g_invkn[idx] = rsqrtf(sk + SMOOTHF);
}

// ---------------- split q,k: normalize + transpose + fp16 ---------------------
__global__ void k_split_qkv(void) {
    __shared__ float t[32][33];
    int n0 = blockIdx.x * 32, d0 = blockIdx.y * 32, bg = blockIdx.z;
    int b = bg >> 3, g = bg & 7;
    int tx = threadIdx.x, ty = threadIdx.y;  // 32 x 8
    const float* srcq = g_qkv + ((size_t)b * THREE_DIM + g * HD + d0) * NPIX + n0;
    // ---- q (split hi/lo) ----
#pragma unroll
    for (int u = 0; u < 4; u++)
        t[ty + u * 8][tx] = srcq[(size_t)(ty + u * 8) * NPIX + tx];
    __syncthreads();
#pragma unroll
    for (int u = 0; u < 4; u++) {
        int nl = ty + u * 8;
        int n = n0 + nl;
        float iv = g_invqn[((size_t)bg << 10) + n];
        float v = t[tx][nl] * iv;
        __half hi = __float2half(v);
        size_t o = (((size_t)bg << 10) + n) * HD + d0 + tx;
        g_qfhi[o] = hi;
        g_qflo[o] = __float2half(v - __half2float(hi));
    }
    __syncthreads();
    // ---- k (rounded once) ----
    const float* srck = srcq + (size_t)DIM * NPIX;
#pragma unroll
    for (int u = 0; u < 4; u++)
        t[ty + u * 8][tx] = srck[(size_t)(ty + u * 8) * NPIX + tx];
    __syncthreads();
#pragma unroll
    for (int u = 0; u < 4; u++) {
        int nl = ty + u * 8;
        int n = n0 + nl;
        float iv = g_invkn[((size_t)bg << 10) + n];
        g_kf[(((size_t)bg << 10) + n) * HD + d0 + tx] = __float2half(t[tx][nl] * iv);
    }
}

// ---------------- v -> fp16 (keeps [d][n] layout) ------------------------------
__global__ void k_split_v(void) {
    int idx = blockIdx.x * 256 + threadIdx.x;   // 64*64*1024 total
    int bg = idx >> 16;
    int rem = idx & 65535;
    int d = rem >> 10, n = rem & 1023;
    int b = bg >> 3, g = bg & 7;
    float v = g_qkv[((size_t)b * THREE_DIM + 2 * DIM + g * HD + d) * NPIX + n];
    g_vTf[((size_t)bg * HD + d) * NPIX + n] = __float2half(v);
}

// ---------------- attention via mma.sync fp16 2-term --------------------------
// S = (q̂h+q̂l).k̂_fp16 ; correct u-eps*t*u ; O += (Sh+Sl).V_fp16
#define ATN_QHI 0
#define ATN_QLO 16384
#define ATN_KH(buf)  (32768 + (buf) * 8192)
#define ATN_VT(buf)  (49152 + (buf) * 8192)
#define ATN_SHI 65536
#define ATN_SLO 81920
#define ATN_IQ 98304
#define ATN_IK 98816                           // + buf*256
#define ATN_SMEM 99328

__global__ __launch_bounds__(256, 2) void k_attn_mma(void) {
    extern __shared__ char smem[];
    const uint32_t sb = s2u(smem);
    const int tid = threadIdx.x, wid = tid >> 5, lane = tid & 31;
    const int i0 = blockIdx.x * 128;
    const int g = blockIdx.y, b = blockIdx.z;
    const int bg = b * 8 + g;
    const int wm = wid & 3, wn = wid >> 2;

#pragma unroll
    for (int u = 0; u < 4; u++) {
        int unit = tid + u * 256;            // 1024: 128 rows x 8 ch
        int row = unit >> 3, ch = unit & 7;
        int sw = row * 128 + ((ch ^ (row & 7)) << 4);
        size_t go = (((size_t)bg << 10) + i0 + row) * 128 + ch * 16;
        cp_async16(sb + ATN_QHI + sw, (const char*)g_qfhi + go, 16);
        cp_async16(sb + ATN_QLO + sw, (const char*)g_qflo + go, 16);
    }
    if (tid < 128)
        ((float*)(smem + ATN_IQ))[tid] = g_invqn[((size_t)bg << 10) + i0 + tid];
    cp_commit();

    auto issueKV = [&](int j0, int buf) {
#pragma unroll
        for (int u = 0; u < 4; u++) {
            int unit = tid + u * 256;        // 1024: 2 tensors x 64 rows x 8 ch
            int sel = unit >> 9;
            int r2 = (unit >> 3) & 63, ch = unit & 7;
            int sw = r2 * 128 + ((ch ^ (r2 & 7)) << 4);
            if (sel == 0) {
                cp_async16(sb + ATN_KH(buf) + sw,
                    (const char*)g_kf + (((size_t)bg << 10) + j0 + r2) * 128 + ch * 16, 16);
            } else {
                cp_async16(sb + ATN_VT(buf) + sw,
                    (const char*)g_vTf + (((size_t)bg * HD + r2) * NPIX + j0) * 2 + ch * 16, 16);
            }
        }
        if (tid < 64)
            ((float*)(smem + ATN_IK + buf * 256))[tid] =
                g_invkn[((size_t)bg << 10) + j0 + tid];
        cp_commit();
    };
    issueKV(0, 0);

    float acco[2][4][4];
#pragma unroll
    for (int i = 0; i < 2; i++)
#pragma unroll
        for (int j = 0; j < 4; j++)
#pragma unroll
            for (int q = 0; q < 4; q++) acco[i][j][q] = 0.f;

    for (int jt = 0; jt < 16; jt++) {
        int buf = jt & 1;
        cp_wait0();
        __syncthreads();
        if (jt < 15) issueKV((jt + 1) * 64, buf ^ 1);

        // ---- S phase ----
        float s[2][4][4];
#pragma unroll
        for (int i = 0; i < 2; i++)
#pragma unroll
            for (int j = 0; j < 4; j++)
#pragma unroll
                for (int q = 0; q < 4; q++) s[i][j][q] = 0.f;
        {
            uint32_t Qh = sb + ATN_QHI, Ql = sb + ATN_QLO;
            uint32_t Kh = sb + ATN_KH(buf);
#pragma unroll
            for (int k16 = 0; k16 < 4; k16++) {
                uint32_t ah[2][4], al[2][4], bh[2][4];
#pragma unroll
                for (int mi = 0; mi < 2; mi++) {
                    int row = wm * 32 + mi * 16 + (lane & 15);
                    int ch = k16 * 2 + (lane >> 4);
                    uint32_t ad = row * 128 + ((ch ^ (row & 7)) << 4);
                    ldsm_x4(ah[mi], Qh + ad);
                    ldsm_x4(al[mi], Ql + ad);
                }
#pragma unroll
                for (int t = 0; t < 2; t++) {
                    int row = wn * 32 + t * 16 + ((lane >> 4) << 3) + (lane & 7);
                    int ch = k16 * 2 + ((lane >> 3) & 1);
                    uint32_t ad = row * 128 + ((ch ^ (row & 7)) << 4);
                    ldsm_x4(bh[t], Kh + ad);
                }
#pragma unroll
                for (int mi = 0; mi < 2; mi++)
#pragma unroll
                    for (int nj = 0; nj < 4; nj++) {
                        const uint32_t* bhf = &bh[nj >> 1][(nj & 1) * 2];
                        mma_fp16(s[mi][nj], ah[mi], bhf);
                        mma_fp16(s[mi][nj], al[mi], bhf);
                    }
            }
        }
        // ---- correction + fp16 split of S into smem ----
        {
            const float* IQ = (const float*)(smem + ATN_IQ);
            const float* IK = (const float*)(smem + ATN_IK + buf * 256);
#pragma unroll
            for (int mi = 0; mi < 2; mi++) {
                int r0 = wm * 32 + mi * 16 + (lane >> 2);
                float iq0 = IQ[r0], iq1 = IQ[r0 + 8];
#pragma unroll
                for (int nj = 0; nj < 4; nj++) {
                    int col = wn * 32 + nj * 8 + (lane & 3) * 2;
                    float ik0 = IK[col], ik1 = IK[col + 1];
                    float* u = s[mi][nj];
                    float t00 = iq0 * ik0, t01 = iq0 * ik1;
                    float t10 = iq1 * ik0, t11 = iq1 * ik1;
                    float v0 = fmaf(-SMOOTHF * t00, u[0], u[0]);
                    float v1 = fmaf(-SMOOTHF * t01, u[1], u[1]);
                    float v2 = fmaf(-SMOOTHF * t10, u[2], u[2]);
                    float v3 = fmaf(-SMOOTHF * t11, u[3], u[3]);
                    __half2 h01 = __floats2half2_rn(v0, v1);
                    __half2 h23 = __floats2half2_rn(v2, v3);
                    float r0f = v0 - __half2float(h01.x);
                    float r1f = v1 - __half2float(h01.y);
                    float r2f = v2 - __half2float(h23.x);
                    float r3f = v3 - __half2float(h23.y);
                    int bo = col * 2;
                    int ch = bo >> 4, wi = bo & 15;
                    int a0 = r0 * 128 + ((ch ^ (r0 & 7)) << 4) + wi;
                    int a1 = (r0 + 8) * 128 + ((ch ^ ((r0 + 8) & 7)) << 4) + wi;
                    *(uint32_t*)(smem + ATN_SHI + a0) = *(uint32_t*)&h01;
                    *(uint32_t*)(smem + ATN_SHI + a1) = *(uint32_t*)&h23;
                    *(uint32_t*)(smem + ATN_SLO + a0) = pack_h2(r0f, r1f);
                    *(uint32_t*)(smem + ATN_SLO + a1) = pack_h2(r2f, r3f);
                }
            }
        }
        __syncthreads();
        // ---- O phase ----
        {
            uint32_t Sh = sb + ATN_SHI, Sl = sb + ATN_SLO;
            uint32_t Vh = sb + ATN_VT(buf);
#pragma unroll
            for (int k16 = 0; k16 < 4; k16++) {
                uint32_t ah[2][4], al[2][4], bh[2][4];
#pragma unroll
                for (int mi = 0; mi < 2; mi++) {
                    int row = wm * 32 + mi * 16 + (lane & 15);
                    int ch = k16 * 2 + (lane >> 4);
                    uint32_t ad = row * 128 + ((ch ^ (row & 7)) << 4);
                    ldsm_x4(ah[mi], Sh + ad);
                    ldsm_x4(al[mi], Sl + ad);
                }
#pragma unroll
                for (int t = 0; t < 2; t++) {
                    int row = wn * 32 + t * 16 + ((lane >> 4) << 3) + (lane & 7);
                    int ch = k16 * 2 + ((lane >> 3) & 1);
                    uint32_t ad = row * 128 + ((ch ^ (row & 7)) << 4);
                    ldsm_x4(bh[t], Vh + ad);
                }
#pragma unroll
                for (int mi = 0; mi < 2; mi++)
#pragma unroll
                    for (int nj = 0; nj < 4; nj++) {
                        const uint32_t* bhf = &bh[nj >> 1][(nj & 1) * 2];
                        mma_fp16(acco[mi][nj], ah[mi], bhf);
                        mma_fp16(acco[mi][nj], al[mi], bhf);
                    }
            }
        }
    }
    // ---- epilogue: O -> bf16 hi/lo at [b][p][c] (conv1x1 A operand) ----------
#pragma unroll
    for (int mi = 0; mi < 2; mi++)
#pragma unroll
        for (int nj = 0; nj < 4; nj++) {
            int row = wm * 32 + mi * 16 + (lane >> 2);
            int col = g * HD + wn * 32 + nj * 8 + (lane & 3) * 2;
            float* u = acco[mi][nj];
            __nv_bfloat162 h01 = __floats2bfloat162_rn(u[0], u[1]);
            __nv_bfloat162 h23 = __floats2bfloat162_rn(u[2], u[3]);
            size_t o0 = (((size_t)b << 10) + i0 + row) * DIM + col;
            size_t o1 = (((size_t)b << 10) + i0 + row + 8) * DIM + col;
            *(uint32_t*)((char*)g_Ahi + o0 * 2) = *(uint32_t*)&h01;
            *(uint32_t*)((char*)g_Ahi + o1 * 2) = *(uint32_t*)&h23;
            *(uint32_t*)((char*)g_Alo + o0 * 2) =
                pack_bf16x2(u[0] - __bfloat162float(h01.x),
                            u[1] - __bfloat162float(h01.y));
            *(uint32_t*)((char*)g_Alo + o1 * 2) =
                pack_bf16x2(u[2] - __bfloat162float(h23.x),
                            u[3] - __bfloat162float(h23.y));
        }
}

// ---------------- conv1x1 via mma.sync bf16 3-term (unchanged, passing) -------
#define STAGE_BYTES 65536
#define OFF_AHI 0
#define OFF_ALO 16384
#define OFF_BHI 32768
#define OFF_BLO 49152
#define CONV_SMEM (2 * STAGE_BYTES)

__global__ __launch_bounds__(256) void k_conv1x1_mma(void) {
    extern __shared__ char smem[];
    const uint32_t sb = s2u(smem);
    const int tid = threadIdx.x;
    const int wid = tid >> 5, lane = tid & 31;
    const int b = blockIdx.z, co0 = blockIdx.y * 128, p0 = blockIdx.x * 128;
    const int wm = wid & 1, wn = wid >> 1;

    float acc[4][4][4];
#pragma unroll
    for (int i = 0; i < 4; i++)
#pragma unroll
        for (int j = 0; j < 4; j++)
#pragma unroll
            for (int q = 0; q < 4; q++) acc[i][j][q] = 0.f;

    auto issue = [&](int c, int buf) {
        int ci0 = c << 6;
        uint32_t S = sb + buf * STAGE_BYTES;
#pragma unroll
        for (int u = 0; u < 4; u++) {
            int unit = tid + u * 256;
            int row = unit >> 3, ch = unit & 7;
            int sw = row * 128 + ((ch ^ (row & 7)) << 4);
            size_t offA = ((((size_t)b << 10) + p0 + row) << 9) + ci0 + (ch << 3);
            cp_async16(S + OFF_AHI + sw, (const char*)g_Ahi + offA * 2, 16);
            cp_async16(S + OFF_ALO + sw, (const char*)g_Alo + offA * 2, 16);
            size_t offB = (((size_t)co0 + row) << 9) + ci0 + (ch << 3);
            cp_async16(S + OFF_BHI + sw, (const char*)g_w2hi + offB * 2, 16);
            cp_async16(S + OFF_BLO + sw, (const char*)g_w2lo + offB * 2, 16);
        }
        cp_commit();
    };

    issue(0, 0);
    for (int c = 0; c < 8; c++) {
        int buf = c & 1;
        cp_wait0();
        __syncthreads();
        if (c + 1 < 8) issue(c + 1, buf ^ 1);

        uint32_t S = sb + buf * STAGE_BYTES;
        int rowA_lo = wm * 64 + (lane & 15);
        int kc8A = lane >> 4;
        int rowB_lo = wn * 32 + ((lane >> 4) << 3) + (lane & 7);
        int kc8B = (lane >> 3) & 1;
#pragma unroll
        for (int k16 = 0; k16 < 4; k16++) {
            uint32_t ah[4][4], al[4][4], bh[2][4], bl[2][4];
#pragma unroll
            for (int mi = 0; mi < 4; mi++) {
                int row = rowA_lo + mi * 16;
                int ch = k16 * 2 + kc8A;
                uint32_t ad = S + row * 128 + ((ch ^ (row & 7)) << 4);
                ldsm_x4(ah[mi], ad + OFF_AHI);
                ldsm_x4(al[mi], ad + OFF_ALO);
            }
#pragma unroll
            for (int t = 0; t < 2; t++) {
                int row = rowB_lo + t * 16;
                int ch = k16 * 2 + kc8B;
                uint32_t ad = S + row * 128 + ((ch ^ (row & 7)) << 4);
                ldsm_x4(bh[t], ad + OFF_BHI);
                ldsm_x4(bl[t], ad + OFF_BLO);
            }
#pragma unroll
            for (int mi = 0; mi < 4; mi++)
#pragma unroll
                for (int nj = 0; nj < 4; nj++) {
                    const uint32_t* bhf = &bh[nj >> 1][(nj & 1) * 2];
                    const uint32_t* blf = &bl[nj >> 1][(nj & 1) * 2];
                    mma_bf16(acc[mi][nj], ah[mi], bhf);
                    mma_bf16(acc[mi][nj], ah[mi], blf);
                    mma_bf16(acc[mi][nj], al[mi], bhf);
                }
        }
    }
#pragma unroll
    for (int mi = 0; mi < 4; mi++)
#pragma unroll
        for (int nj = 0; nj < 4; nj++) {
            int row = wm * 64 + mi * 16 + (lane >> 2);
            int col = wn * 32 + nj * 8 + (lane & 3) * 2;
            float* u = acc[mi][nj];
            size_t o0 = (((size_t)b << 10) + p0 + row) * DIM + co0 + col;
            size_t o1 = o0 + 8 * DIM;
            *(float2*)(g_conv2 + o0) = make_float2(u[0], u[1]);
            *(float2*)(g_conv2 + o1) = make_float2(u[2], u[3]);
        }
}

// ---------------- BN partial sums ---------------------------------------------
__global__ void k_bnpartial(void) {
    int z = blockIdx.x;
    int t = threadIdx.x;
    const float* base = g_conv2 + (size_t)z * 128 * DIM;
    float s1 = 0.f, q1 = 0.f, s2 = 0.f, q2 = 0.f;
    for (int r = 0; r < 128; r++) {
        float a = base[r * DIM + t];
        float c = base[r * DIM + t + 256];
        s1 += a; q1 = fmaf(a, a, q1);
        s2 += c; q2 = fmaf(c, c, q2);
    }
    g_part[0][z][t] = s1;
    g_part[1][z][t] = q1;
    g_part[0][z][t + 256] = s2;
    g_part[1][z][t + 256] = q2;
}

__global__ void k_bnfinal(const float* __restrict__ gamma,
                          const float* __restrict__ beta) {
    int c = threadIdx.x;
    float s = 0.f, s2 = 0.f;
    for (int i = 0; i < 64; i++) { s += g_part[0][i][c]; s2 += g_part[1][i][c]; }
    float mean = s * (1.f / 8192.f);
    float var = s2 * (1.f / 8192.f) - mean * mean;
    float rstd = rsqrtf(var + BN_EPSF);
    float sc = gamma[c] * rstd;
    g_scale[c] = sc;
    g_shift[c] = beta[c] - mean * sc;
}

// ---------------- BN apply + ReLU + transpose ---------------------------------
__global__ void k_bn_relu_t(float* __restrict__ out) {
    __shared__ float t[32][33];
    int p0 = blockIdx.x * 32, c0 = blockIdx.y * 32, b = blockIdx.z;
    int tx = threadIdx.x, ty = threadIdx.y;
#pragma unroll
    for (int u = 0; u < 4; u++) {
        int p = p0 + ty + u * 8;
        t[ty + u * 8][tx] = g_conv2[(((size_t)b << 10) + p) * DIM + c0 + tx];
    }
    __syncthreads();
#pragma unroll
    for (int u = 0; u < 4; u++) {
        int c = c0 + ty + u * 8;
        float v = fmaf(t[tx][ty + u * 8], g_scale[c], g_shift[c]);
        out[((size_t)b * DIM + c) * NPIX + p0 + tx] = v > 0.f ? v : 0.f;
    }
}

// ---------------- launch ------------------------------------------------------
extern "C" void kernel_launch(void* const* d_in, const int* in_sizes, int n_in,
                              void* d_out, int out_size) {
    const float* x      = (const float*)d_in[0];
    const float* W_qkv  = (const float*)d_in[1];
    const float* W_out  = (const float*)d_in[2];
    const float* gamma  = (const float*)d_in[3];
    const float* beta   = (const float*)d_in[4];
    float* out = (float*)d_out;

    k_prep_x<<<dim3(32, 16, BATCH), dim3(32, 8)>>>(x);
    k_prep_w<<<THREE_DIM, 256>>>(W_qkv);
    k_split_wout<<<(DIM * DIM + 255) / 256, 256>>>(W_out);

    cudaFuncSetAttribute(k_conv3x3_mma, cudaFuncAttributeMaxDynamicSharedMemorySize,
                         C3_SMEM);
    k_conv3x3_mma<<<dim3(8, 24, BATCH), 256, C3_SMEM>>>();

    k_norms<<<(BATCH * HEADS * NPIX) / 256, 256>>>();
    k_split_qkv<<<dim3(32, 2, 64), dim3(32, 8)>>>();
    k_split_v<<<(64 * HD * NPIX) / 256, 256>>>();

    cudaFuncSetAttribute(k_attn_mma, cudaFuncAttributeMaxDynamicSharedMemorySize,
                         ATN_SMEM);
    k_attn_mma<<<dim3(8, HEADS, BATCH), 256, ATN_SMEM>>>();

    cudaFuncSetAttribute(k_conv1x1_mma, cudaFuncAttributeMaxDynamicSharedMemorySize,
                         CONV_SMEM);
    k_conv1x1_mma<<<dim3(8, 4, BATCH), 256, CONV_SMEM>>>();

    k_bnpartial<<<64, 256>>>();
    k_bnfinal<<<1, DIM>>>(gamma, beta);
    k_bn_relu_t<<<dim3(32, 16, BATCH), dim3(32, 8)>>>(out);
}

// round 15
// speedup vs baseline: 4.9671x; 1.0565x over previous
#include <cuda_runtime.h>
#include <cuda_bf16.h>
#include <cuda_fp16.h>
#include <cstdint>

#define DIM 512
#define THREE_DIM 1536
#define NPIX 1024
#define BATCH 8
#define HEADS 8
#define HD 64
#define SMOOTHF 1e-4f
#define BN_EPSF 1e-5f

// ---------------- scratch (static __device__, no allocation) ----------------
__device__ float g_invqn[BATCH * HEADS * NPIX];
__device__ float g_invkn[BATCH * HEADS * NPIX];
__device__ float g_conv2[BATCH * NPIX * DIM];       // [b][p][c]
__device__ float g_scale[DIM];
__device__ float g_shift[DIM];
__device__ float g_part[2][64][DIM];                // BN partial sums
// fp16 split operands for conv3x3 (x split hi/lo, W rounded once)
__device__ __half g_xHhi[BATCH * NPIX * DIM];       // [b][p][ci]
__device__ __half g_xHlo[BATCH * NPIX * DIM];
__device__ __half g_WrH[9 * THREE_DIM * DIM];       // [kpos][co][ci]
// fp16 operands for attention (written directly by conv3x3 epilogue)
__device__ __half g_qfhi[64 * NPIX * HD];           // [bg][n][d]  (q * invqn)
__device__ __half g_qflo[64 * NPIX * HD];
__device__ __half g_kf[64 * NPIX * HD];             // [bg][n][d]  (k * invkn)
__device__ __half g_vTf[64 * HD * NPIX];            // [bg][d][n]
// attention output (conv1x1 A operand), fp16 split
__device__ __half g_Afhi[BATCH * NPIX * DIM];       // [b][p][c]
__device__ __half g_Aflo[BATCH * NPIX * DIM];
// conv1x1 weights fp16
__device__ __half g_w2f[DIM * DIM];                 // [co][ci]

// ---------------- helpers ----------------------------------------------------
__device__ __forceinline__ uint32_t s2u(const void* p) {
    uint32_t a;
    asm("{ .reg .u64 t; cvta.to.shared.u64 t, %1; cvt.u32.u64 %0, t; }"
        : "=r"(a) : "l"(p));
    return a;
}
__device__ __forceinline__ void cp_async16(uint32_t saddr, const void* gaddr, int sz) {
    asm volatile("cp.async.cg.shared.global [%0], [%1], 16, %2;"
                 :: "r"(saddr), "l"(gaddr), "r"(sz));
}
__device__ __forceinline__ void cp_commit() {
    asm volatile("cp.async.commit_group;" ::: "memory");
}
__device__ __forceinline__ void cp_wait0() {
    asm volatile("cp.async.wait_group 0;" ::: "memory");
}
__device__ __forceinline__ void ldsm_x4(uint32_t* r, uint32_t addr) {
    asm volatile("ldmatrix.sync.aligned.m8n8.x4.shared.b16 {%0,%1,%2,%3}, [%4];"
                 : "=r"(r[0]), "=r"(r[1]), "=r"(r[2]), "=r"(r[3]) : "r"(addr));
}
__device__ __forceinline__ void mma_fp16(float* d, const uint32_t* a,
                                         const uint32_t* b) {
    asm volatile(
        "mma.sync.aligned.m16n8k16.row.col.f32.f16.f16.f32 "
        "{%0,%1,%2,%3}, {%4,%5,%6,%7}, {%8,%9}, {%0,%1,%2,%3};"
        : "+f"(d[0]), "+f"(d[1]), "+f"(d[2]), "+f"(d[3])
        : "r"(a[0]), "r"(a[1]), "r"(a[2]), "r"(a[3]), "r"(b[0]), "r"(b[1]));
}
__device__ __forceinline__ uint32_t pack_h2(float a, float b) {
    __half2 h = __floats2half2_rn(a, b);
    return *(uint32_t*)&h;
}

// ---------------- prep: x -> [b][p][ci] fp16 hi/lo ----------------------------
__global__ void k_prep_x(const float* __restrict__ x) {
    __shared__ float t[32][33];
    int b = blockIdx.z, c0 = blockIdx.y * 32, p0 = blockIdx.x * 32;
    int tx = threadIdx.x, ty = threadIdx.y;  // 32 x 8
    const float* xb = x + ((size_t)b * DIM + c0) * NPIX + p0;
#pragma unroll
    for (int u = 0; u < 4; u++) t[ty + u * 8][tx] = xb[(ty + u * 8) * NPIX + tx];
    __syncthreads();
    size_t ob = ((size_t)b * NPIX + p0) * DIM + c0;
#pragma unroll
    for (int u = 0; u < 4; u++) {
        int p = ty + u * 8;
        float v = t[tx][p];
        __half hi = __float2half(v);
        g_xHhi[ob + (size_t)p * DIM + tx] = hi;
        g_xHlo[ob + (size_t)p * DIM + tx] = __float2half(v - __half2float(hi));
    }
}

// ---------------- prep: W_qkv -> [kpos][co][ci] fp16 --------------------------
__global__ void k_prep_w(const float* __restrict__ W) {
    __shared__ float s[4608];
    int co = blockIdx.x;
    const float* wr = W + (size_t)co * 4608;
    for (int i = threadIdx.x; i < 4608; i += 256) s[i] = wr[i];
    __syncthreads();
    for (int kpos = 0; kpos < 9; kpos++) {
        size_t ob = ((size_t)kpos * THREE_DIM + co) * DIM;
        for (int ci = threadIdx.x; ci < DIM; ci += 256)
            g_WrH[ob + ci] = __float2half(s[ci * 9 + kpos]);
    }
}

// ---------------- prep: W_out -> fp16 ([co][ci]) ------------------------------
__global__ void k_prep_w2(const float* __restrict__ W) {
    int idx = blockIdx.x * 256 + threadIdx.x;
    if (idx >= DIM * DIM) return;
    g_w2f[idx] = __float2half(W[idx]);
}

// ---------------- conv3x3 fp16 2-term, BM=128 BN=64, fused q/k/v epilogue -----
// kind = co-tile/8: 0 -> q (normalize, [n][d] fp16 hi/lo), 1 -> k (normalize,
// [n][d] fp16), 2 -> v (transpose, [d][n] fp16).
#define C3_OFF_AHI 0
#define C3_OFF_ALO 16384
#define C3_OFF_BH  32768
#define C3_STAGE 40960
#define C3_SMEM (2 * C3_STAGE)

__global__ __launch_bounds__(256, 2) void k_conv3x3_mma(void) {
    extern __shared__ char smem[];
    const uint32_t sb = s2u(smem);
    const int tid = threadIdx.x;
    const int wid = tid >> 5, lane = tid & 31;
    const int b = blockIdx.z, p0 = blockIdx.x * 128;
    const int y = blockIdx.y;                // 0..23
    const int co0 = y * 64;
    const int wm = wid >> 1, wn = wid & 1;   // 4 x 2 warps, 32x32 tiles

    float acc[2][4][4];
#pragma unroll
    for (int i = 0; i < 2; i++)
#pragma unroll
        for (int j = 0; j < 4; j++)
#pragma unroll
            for (int q = 0; q < 4; q++) acc[i][j][q] = 0.f;

    auto issue = [&](int c, int buf) {
        int kpos = c >> 3, ci0 = (c & 7) << 6;
        int kh = kpos / 3 - 1, kw = kpos % 3 - 1;
        uint32_t S = sb + buf * C3_STAGE;
#pragma unroll
        for (int u = 0; u < 10; u++) {
            int unit = tid + u * 256;            // 0..2559
            if (unit < 2048) {
                int sel = unit >> 10;
                int row = (unit >> 3) & 127, ch = unit & 7;
                int sw = row * 128 + ((ch ^ (row & 7)) << 4);
                int p = p0 + row;
                int h = (p >> 5) + kh, w = (p & 31) + kw;
                bool valid = ((unsigned)h < 32u) && ((unsigned)w < 32u);
                size_t offA = valid
                    ? (((((size_t)b << 10) + ((h << 5) + w)) << 9) + ci0 + (ch << 3))
                    : 0;
                int sz = valid ? 16 : 0;
                const char* src = sel ? (const char*)g_xHlo : (const char*)g_xHhi;
                cp_async16(S + (sel ? C3_OFF_ALO : C3_OFF_AHI) + sw,
                           src + offA * 2, sz);
            } else {
                int v2 = unit - 2048;
                int row = v2 >> 3, ch = v2 & 7;
                int sw = row * 128 + ((ch ^ (row & 7)) << 4);
                size_t offB = (((size_t)kpos * THREE_DIM + co0 + row) << 9)
                              + ci0 + (ch << 3);
                cp_async16(S + C3_OFF_BH + sw, (const char*)g_WrH + offB * 2, 16);
            }
        }
        cp_commit();
    };

    issue(0, 0);
    for (int c = 0; c < 72; c++) {
        int buf = c & 1;
        cp_wait0();
        __syncthreads();
        if (c + 1 < 72) issue(c + 1, buf ^ 1);

        uint32_t S = sb + buf * C3_STAGE;
        int rowA_lo = wm * 32 + (lane & 15);
        int kc8A = lane >> 4;
        int rowB_lo = wn * 32 + ((lane >> 4) << 3) + (lane & 7);
        int kc8B = (lane >> 3) & 1;
#pragma unroll
        for (int k16 = 0; k16 < 4; k16++) {
            uint32_t ah[2][4], al[2][4], bh[2][4];
#pragma unroll
            for (int mi = 0; mi < 2; mi++) {
                int row = rowA_lo + mi * 16;
                int ch = k16 * 2 + kc8A;
                uint32_t ad = S + row * 128 + ((ch ^ (row & 7)) << 4);
                ldsm_x4(ah[mi], ad + C3_OFF_AHI);
                ldsm_x4(al[mi], ad + C3_OFF_ALO);
            }
#pragma unroll
            for (int t = 0; t < 2; t++) {
                int row = rowB_lo + t * 16;
                int ch = k16 * 2 + kc8B;
                uint32_t ad = S + row * 128 + ((ch ^ (row & 7)) << 4);
                ldsm_x4(bh[t], ad + C3_OFF_BH);
            }
#pragma unroll
            for (int mi = 0; mi < 2; mi++)
#pragma unroll
                for (int nj = 0; nj < 4; nj++) {
                    const uint32_t* bhf = &bh[nj >> 1][(nj & 1) * 2];
                    mma_fp16(acc[mi][nj], ah[mi], bhf);
                    mma_fp16(acc[mi][nj], al[mi], bhf);
                }
        }
    }
    __syncthreads();

    const int kind = y >> 3;         // 0=q 1=k 2=v
    const int g = y & 7;
    const int bg = b * 8 + g;

    if (kind < 2) {
        // ---- fused row-norm: ssq over the 64-col head dim -------------------
        float* ssq = (float*)smem;   // [2][128]
        float pss[2][2];
#pragma unroll
        for (int mi = 0; mi < 2; mi++) {
            float s0 = 0.f, s1 = 0.f;
#pragma unroll
            for (int nj = 0; nj < 4; nj++) {
                float* u = acc[mi][nj];
                s0 = fmaf(u[0], u[0], s0); s0 = fmaf(u[1], u[1], s0);
                s1 = fmaf(u[2], u[2], s1); s1 = fmaf(u[3], u[3], s1);
            }
            pss[mi][0] = s0; pss[mi][1] = s1;
        }
#pragma unroll
        for (int mi = 0; mi < 2; mi++)
#pragma unroll
            for (int hh = 0; hh < 2; hh++) {
                float v = pss[mi][hh];
                v += __shfl_xor_sync(0xffffffffu, v, 1);
                v += __shfl_xor_sync(0xffffffffu, v, 2);
                pss[mi][hh] = v;
            }
        if ((lane & 3) == 0) {
#pragma unroll
            for (int mi = 0; mi < 2; mi++)
#pragma unroll
                for (int hh = 0; hh < 2; hh++) {
                    int row = wm * 32 + mi * 16 + (lane >> 2) + hh * 8;
                    ssq[wn * 128 + row] = pss[mi][hh];
                }
        }
        __syncthreads();
#pragma unroll
        for (int mi = 0; mi < 2; mi++)
#pragma unroll
            for (int hh = 0; hh < 2; hh++) {
                int row = wm * 32 + mi * 16 + (lane >> 2) + hh * 8;
                float inv = rsqrtf(ssq[row] + ssq[128 + row] + SMOOTHF);
                if (wn == 0 && (lane & 3) == 0) {
                    if (kind == 0) g_invqn[(bg << 10) + p0 + row] = inv;
                    else           g_invkn[(bg << 10) + p0 + row] = inv;
                }
#pragma unroll
                for (int nj = 0; nj < 4; nj++) {
                    int col = wn * 32 + nj * 8 + (lane & 3) * 2;
                    float v0 = acc[mi][nj][hh * 2 + 0] * inv;
                    float v1 = acc[mi][nj][hh * 2 + 1] * inv;
                    size_t o = ((size_t)(bg << 10) + p0 + row) * HD + col;
                    if (kind == 0) {
                        __half2 h = __floats2half2_rn(v0, v1);
                        *(uint32_t*)((char*)g_qfhi + o * 2) = *(uint32_t*)&h;
                        *(uint32_t*)((char*)g_qflo + o * 2) =
                            pack_h2(v0 - __half2float(h.x), v1 - __half2float(h.y));
                    } else {
                        *(uint32_t*)((char*)g_kf + o * 2) = pack_h2(v0, v1);
                    }
                }
            }
    } else {
        // ---- v: transpose to [d][n] fp16 ------------------------------------
        float* T = (float*)smem;     // [128][68]
#pragma unroll
        for (int mi = 0; mi < 2; mi++)
#pragma unroll
            for (int nj = 0; nj < 4; nj++) {
                int row = wm * 32 + mi * 16 + (lane >> 2);
                int col = wn * 32 + nj * 8 + (lane & 3) * 2;
                T[row * 68 + col]           = acc[mi][nj][0];
                T[row * 68 + col + 1]       = acc[mi][nj][1];
                T[(row + 8) * 68 + col]     = acc[mi][nj][2];
                T[(row + 8) * 68 + col + 1] = acc[mi][nj][3];
            }
        __syncthreads();
#pragma unroll
        for (int t = 0; t < 8; t++) {
            int cc = wid * 8 + t;    // d within head
            float v0 = T[(lane * 4 + 0) * 68 + cc];
            float v1 = T[(lane * 4 + 1) * 68 + cc];
            float v2 = T[(lane * 4 + 2) * 68 + cc];
            float v3 = T[(lane * 4 + 3) * 68 + cc];
            size_t o = ((size_t)bg * HD + cc) * NPIX + p0 + lane * 4;
            uint32_t* dst = (uint32_t*)((char*)g_vTf + o * 2);
            dst[0] = pack_h2(v0, v1);
            dst[1] = pack_h2(v2, v3);
        }
    }
}

// ---------------- attention via mma.sync fp16 2-term --------------------------
#define ATN_QHI 0
#define ATN_QLO 16384
#define ATN_KH(buf)  (32768 + (buf) * 8192)
#define ATN_VT(buf)  (49152 + (buf) * 8192)
#define ATN_SHI 65536
#define ATN_SLO 81920
#define ATN_IQ 98304
#define ATN_IK 98816                           // + buf*256
#define ATN_SMEM 99328

__global__ __launch_bounds__(256, 2) void k_attn_mma(void) {
    extern __shared__ char smem[];
    const uint32_t sb = s2u(smem);
    const int tid = threadIdx.x, wid = tid >> 5, lane = tid & 31;
    const int i0 = blockIdx.x * 128;
    const int g = blockIdx.y, b = blockIdx.z;
    const int bg = b * 8 + g;
    const int wm = wid & 3, wn = wid >> 2;

#pragma unroll
    for (int u = 0; u < 4; u++) {
        int unit = tid + u * 256;            // 1024: 128 rows x 8 ch
        int row = unit >> 3, ch = unit & 7;
        int sw = row * 128 + ((ch ^ (row & 7)) << 4);
        size_t go = (((size_t)bg << 10) + i0 + row) * 128 + ch * 16;
        cp_async16(sb + ATN_QHI + sw, (const char*)g_qfhi + go, 16);
        cp_async16(sb + ATN_QLO + sw, (const char*)g_qflo + go, 16);
    }
    if (tid < 128)
        ((float*)(smem + ATN_IQ))[tid] = g_invqn[((size_t)bg << 10) + i0 + tid];
    cp_commit();

    auto issueKV = [&](int j0, int buf) {
#pragma unroll
        for (int u = 0; u < 4; u++) {
            int unit = tid + u * 256;        // 1024: 2 tensors x 64 rows x 8 ch
            int sel = unit >> 9;
            int r2 = (unit >> 3) & 63, ch = unit & 7;
            int sw = r2 * 128 + ((ch ^ (r2 & 7)) << 4);
            if (sel == 0) {
                cp_async16(sb + ATN_KH(buf) + sw,
                    (const char*)g_kf + (((size_t)bg << 10) + j0 + r2) * 128 + ch * 16, 16);
            } else {
                cp_async16(sb + ATN_VT(buf) + sw,
                    (const char*)g_vTf + (((size_t)bg * HD + r2) * NPIX + j0) * 2 + ch * 16, 16);
            }
        }
        if (tid < 64)
            ((float*)(smem + ATN_IK + buf * 256))[tid] =
                g_invkn[((size_t)bg << 10) + j0 + tid];
        cp_commit();
    };
    issueKV(0, 0);

    float acco[2][4][4];
#pragma unroll
    for (int i = 0; i < 2; i++)
#pragma unroll
        for (int j = 0; j < 4; j++)
#pragma unroll
            for (int q = 0; q < 4; q++) acco[i][j][q] = 0.f;

    for (int jt = 0; jt < 16; jt++) {
        int buf = jt & 1;
        cp_wait0();
        __syncthreads();
        if (jt < 15) issueKV((jt + 1) * 64, buf ^ 1);

        // ---- S phase ----
        float s[2][4][4];
#pragma unroll
        for (int i = 0; i < 2; i++)
#pragma unroll
            for (int j = 0; j < 4; j++)
#pragma unroll
                for (int q = 0; q < 4; q++) s[i][j][q] = 0.f;
        {
            uint32_t Qh = sb + ATN_QHI, Ql = sb + ATN_QLO;
            uint32_t Kh = sb + ATN_KH(buf);
#pragma unroll
            for (int k16 = 0; k16 < 4; k16++) {
                uint32_t ah[2][4], al[2][4], bh[2][4];
#pragma unroll
                for (int mi = 0; mi < 2; mi++) {
                    int row = wm * 32 + mi * 16 + (lane & 15);
                    int ch = k16 * 2 + (lane >> 4);
                    uint32_t ad = row * 128 + ((ch ^ (row & 7)) << 4);
                    ldsm_x4(ah[mi], Qh + ad);
                    ldsm_x4(al[mi], Ql + ad);
                }
#pragma unroll
                for (int t = 0; t < 2; t++) {
                    int row = wn * 32 + t * 16 + ((lane >> 4) << 3) + (lane & 7);
                    int ch = k16 * 2 + ((lane >> 3) & 1);
                    uint32_t ad = row * 128 + ((ch ^ (row & 7)) << 4);
                    ldsm_x4(bh[t], Kh + ad);
                }
#pragma unroll
                for (int mi = 0; mi < 2; mi++)
#pragma unroll
                    for (int nj = 0; nj < 4; nj++) {
                        const uint32_t* bhf = &bh[nj >> 1][(nj & 1) * 2];
                        mma_fp16(s[mi][nj], ah[mi], bhf);
                        mma_fp16(s[mi][nj], al[mi], bhf);
                    }
            }
        }
        // ---- correction + fp16 split of S into smem ----
        {
            const float* IQ = (const float*)(smem + ATN_IQ);
            const float* IK = (const float*)(smem + ATN_IK + buf * 256);
#pragma unroll
            for (int mi = 0; mi < 2; mi++) {
                int r0 = wm * 32 + mi * 16 + (lane >> 2);
                float iq0 = IQ[r0], iq1 = IQ[r0 + 8];
#pragma unroll
                for (int nj = 0; nj < 4; nj++) {
                    int col = wn * 32 + nj * 8 + (lane & 3) * 2;
                    float ik0 = IK[col], ik1 = IK[col + 1];
                    float* u = s[mi][nj];
                    float t00 = iq0 * ik0, t01 = iq0 * ik1;
                    float t10 = iq1 * ik0, t11 = iq1 * ik1;
                    float v0 = fmaf(-SMOOTHF * t00, u[0], u[0]);
                    float v1 = fmaf(-SMOOTHF * t01, u[1], u[1]);
                    float v2 = fmaf(-SMOOTHF * t10, u[2], u[2]);
                    float v3 = fmaf(-SMOOTHF * t11, u[3], u[3]);
                    __half2 h01 = __floats2half2_rn(v0, v1);
                    __half2 h23 = __floats2half2_rn(v2, v3);
                    float r0f = v0 - __half2float(h01.x);
                    float r1f = v1 - __half2float(h01.y);
                    float r2f = v2 - __half2float(h23.x);
                    float r3f = v3 - __half2float(h23.y);
                    int bo = col * 2;
                    int ch = bo >> 4, wi = bo & 15;
                    int a0 = r0 * 128 + ((ch ^ (r0 & 7)) << 4) + wi;
                    int a1 = (r0 + 8) * 128 + ((ch ^ ((r0 + 8) & 7)) << 4) + wi;
                    *(uint32_t*)(smem + ATN_SHI + a0) = *(uint32_t*)&h01;
                    *(uint32_t*)(smem + ATN_SHI + a1) = *(uint32_t*)&h23;
                    *(uint32_t*)(smem + ATN_SLO + a0) = pack_h2(r0f, r1f);
                    *(uint32_t*)(smem + ATN_SLO + a1) = pack_h2(r2f, r3f);
                }
            }
        }
        __syncthreads();
        // ---- O phase ----
        {
            uint32_t Sh = sb + ATN_SHI, Sl = sb + ATN_SLO;
            uint32_t Vh = sb + ATN_VT(buf);
#pragma unroll
            for (int k16 = 0; k16 < 4; k16++) {
                uint32_t ah[2][4], al[2][4], bh[2][4];
#pragma unroll
                for (int mi = 0; mi < 2; mi++) {
                    int row = wm * 32 + mi * 16 + (lane & 15);
                    int ch = k16 * 2 + (lane >> 4);
                    uint32_t ad = row * 128 + ((ch ^ (row & 7)) << 4);
                    ldsm_x4(ah[mi], Sh + ad);
                    ldsm_x4(al[mi], Sl + ad);
                }
#pragma unroll
                for (int t = 0; t < 2; t++) {
                    int row = wn * 32 + t * 16 + ((lane >> 4) << 3) + (lane & 7);
                    int ch = k16 * 2 + ((lane >> 3) & 1);
                    uint32_t ad = row * 128 + ((ch ^ (row & 7)) << 4);
                    ldsm_x4(bh[t], Vh + ad);
                }
#pragma unroll
                for (int mi = 0; mi < 2; mi++)
#pragma unroll
                    for (int nj = 0; nj < 4; nj++) {
                        const uint32_t* bhf = &bh[nj >> 1][(nj & 1) * 2];
                        mma_fp16(acco[mi][nj], ah[mi], bhf);
                        mma_fp16(acco[mi][nj], al[mi], bhf);
                    }
            }
        }
    }
    // ---- epilogue: O -> fp16 hi/lo at [b][p][c] (conv1x1 A operand) ----------
#pragma unroll
    for (int mi = 0; mi < 2; mi++)
#pragma unroll
        for (int nj = 0; nj < 4; nj++) {
            int row = wm * 32 + mi * 16 + (lane >> 2);
            int col = g * HD + wn * 32 + nj * 8 + (lane & 3) * 2;
            float* u = acco[mi][nj];
            __half2 h01 = __floats2half2_rn(u[0], u[1]);
            __half2 h23 = __floats2half2_rn(u[2], u[3]);
            size_t o0 = (((size_t)b << 10) + i0 + row) * DIM + col;
            size_t o1 = (((size_t)b << 10) + i0 + row + 8) * DIM + col;
            *(uint32_t*)((char*)g_Afhi + o0 * 2) = *(uint32_t*)&h01;
            *(uint32_t*)((char*)g_Afhi + o1 * 2) = *(uint32_t*)&h23;
            *(uint32_t*)((char*)g_Aflo + o0 * 2) =
                pack_h2(u[0] - __half2float(h01.x), u[1] - __half2float(h01.y));
            *(uint32_t*)((char*)g_Aflo + o1 * 2) =
                pack_h2(u[2] - __half2float(h23.x), u[3] - __half2float(h23.y));
        }
}

// ---------------- conv1x1 fp16 2-term, BM=128 BN=64, 2 CTAs/SM ----------------
#define C1_OFF_AHI 0
#define C1_OFF_ALO 16384
#define C1_OFF_BH  32768
#define C1_STAGE 40960
#define C1_SMEM (2 * C1_STAGE)

__global__ __launch_bounds__(256, 2) void k_conv1x1_mma(void) {
    extern __shared__ char smem[];
    const uint32_t sb = s2u(smem);
    const int tid = threadIdx.x;
    const int wid = tid >> 5, lane = tid & 31;
    const int b = blockIdx.z, co0 = blockIdx.y * 64, p0 = blockIdx.x * 128;
    const int wm = wid >> 1, wn = wid & 1;

    float acc[2][4][4];
#pragma unroll
    for (int i = 0; i < 2; i++)
#pragma unroll
        for (int j = 0; j < 4; j++)
#pragma unroll
            for (int q = 0; q < 4; q++) acc[i][j][q] = 0.f;

    auto issue = [&](int c, int buf) {
        int ci0 = c << 6;
        uint32_t S = sb + buf * C1_STAGE;
#pragma unroll
        for (int u = 0; u < 10; u++) {
            int unit = tid + u * 256;
            if (unit < 2048) {
                int sel = unit >> 10;
                int row = (unit >> 3) & 127, ch = unit & 7;
                int sw = row * 128 + ((ch ^ (row & 7)) << 4);
                size_t offA = ((((size_t)b << 10) + p0 + row) << 9) + ci0 + (ch << 3);
                const char* src = sel ? (const char*)g_Aflo : (const char*)g_Afhi;
                cp_async16(S + (sel ? C1_OFF_ALO : C1_OFF_AHI) + sw,
                           src + offA * 2, 16);
            } else {
                int v2 = unit - 2048;
                int row = v2 >> 3, ch = v2 & 7;
                int sw = row * 128 + ((ch ^ (row & 7)) << 4);
                size_t offB = (((size_t)co0 + row) << 9) + ci0 + (ch << 3);
                cp_async16(S + C1_OFF_BH + sw, (const char*)g_w2f + offB * 2, 16);
            }
        }
        cp_commit();
    };

    issue(0, 0);
    for (int c = 0; c < 8; c++) {
        int buf = c & 1;
        cp_wait0();
        __syncthreads();
        if (c + 1 < 8) issue(c + 1, buf ^ 1);

        uint32_t S = sb + buf * C1_STAGE;
        int rowA_lo = wm * 32 + (lane & 15);
        int kc8A = lane >> 4;
        int rowB_lo = wn * 32 + ((lane >> 4) << 3) + (lane & 7);
        int kc8B = (lane >> 3) & 1;
#pragma unroll
        for (int k16 = 0; k16 < 4; k16++) {
            uint32_t ah[2][4], al[2][4], bh[2][4];
#pragma unroll
            for (int mi = 0; mi < 2; mi++) {
                int row = rowA_lo + mi * 16;
                int ch = k16 * 2 + kc8A;
                uint32_t ad = S + row * 128 + ((ch ^ (row & 7)) << 4);
                ldsm_x4(ah[mi], ad + C1_OFF_AHI);
                ldsm_x4(al[mi], ad + C1_OFF_ALO);
            }
#pragma unroll
            for (int t = 0; t < 2; t++) {
                int row = rowB_lo + t * 16;
                int ch = k16 * 2 + kc8B;
                uint32_t ad = S + row * 128 + ((ch ^ (row & 7)) << 4);
                ldsm_x4(bh[t], ad + C1_OFF_BH);
            }
#pragma unroll
            for (int mi = 0; mi < 2; mi++)
#pragma unroll
                for (int nj = 0; nj < 4; nj++) {
                    const uint32_t* bhf = &bh[nj >> 1][(nj & 1) * 2];
                    mma_fp16(acc[mi][nj], ah[mi], bhf);
                    mma_fp16(acc[mi][nj], al[mi], bhf);
                }
        }
    }
    // direct write C[p][co] to g_conv2 [b][p][c]
#pragma unroll
    for (int mi = 0; mi < 2; mi++)
#pragma unroll
        for (int nj = 0; nj < 4; nj++) {
            int row = wm * 32 + mi * 16 + (lane >> 2);
            int col = wn * 32 + nj * 8 + (lane & 3) * 2;
            float* u = acc[mi][nj];
            size_t o0 = (((size_t)b << 10) + p0 + row) * DIM + co0 + col;
            size_t o1 = o0 + 8 * DIM;
            *(float2*)(g_conv2 + o0) = make_float2(u[0], u[1]);
            *(float2*)(g_conv2 + o1) = make_float2(u[2], u[3]);
        }
}

// ---------------- BN partial sums ---------------------------------------------
__global__ void k_bnpartial(void) {
    int z = blockIdx.x;
    int t = threadIdx.x;
    const float* base = g_conv2 + (size_t)z * 128 * DIM;
    float s1 = 0.f, q1 = 0.f, s2 = 0.f, q2 = 0.f;
    for (int r = 0; r < 128; r++) {
        float a = base[r * DIM + t];
        float c = base[r * DIM + t + 256];
        s1 += a; q1 = fmaf(a, a, q1);
        s2 += c; q2 = fmaf(c, c, q2);
    }
    g_part[0][z][t] = s1;
    g_part[1][z][t] = q1;
    g_part[0][z][t + 256] = s2;
    g_part[1][z][t + 256] = q2;
}

__global__ void k_bnfinal(const float* __restrict__ gamma,
                          const float* __restrict__ beta) {
    int c = threadIdx.x;
    float s = 0.f, s2 = 0.f;
    for (int i = 0; i < 64; i++) { s += g_part[0][i][c]; s2 += g_part[1][i][c]; }
    float mean = s * (1.f / 8192.f);
    float var = s2 * (1.f / 8192.f) - mean * mean;
    float rstd = rsqrtf(var + BN_EPSF);
    float sc = gamma[c] * rstd;
    g_scale[c] = sc;
    g_shift[c] = beta[c] - mean * sc;
}

// ---------------- BN apply + ReLU + transpose ---------------------------------
__global__ void k_bn_relu_t(float* __restrict__ out) {
    __shared__ float t[32][33];
    int p0 = blockIdx.x * 32, c0 = blockIdx.y * 32, b = blockIdx.z;
    int tx = threadIdx.x, ty = threadIdx.y;
#pragma unroll
    for (int u = 0; u < 4; u++) {
        int p = p0 + ty + u * 8;
        t[ty + u * 8][tx] = g_conv2[(((size_t)b << 10) + p) * DIM + c0 + tx];
    }
    __syncthreads();
#pragma unroll
    for (int u = 0; u < 4; u++) {
        int c = c0 + ty + u * 8;
        float v = fmaf(t[tx][ty + u * 8], g_scale[c], g_shift[c]);
        out[((size_t)b * DIM + c) * NPIX + p0 + tx] = v > 0.f ? v : 0.f;
    }
}

// ---------------- launch ------------------------------------------------------
extern "C" void kernel_launch(void* const* d_in, const int* in_sizes, int n_in,
                              void* d_out, int out_size) {
    const float* x      = (const float*)d_in[0];
    const float* W_qkv  = (const float*)d_in[1];
    const float* W_out  = (const float*)d_in[2];
    const float* gamma  = (const float*)d_in[3];
    const float* beta   = (const float*)d_in[4];
    float* out = (float*)d_out;

    k_prep_x<<<dim3(32, 16, BATCH), dim3(32, 8)>>>(x);
    k_prep_w<<<THREE_DIM, 256>>>(W_qkv);
    k_prep_w2<<<(DIM * DIM + 255) / 256, 256>>>(W_out);

    cudaFuncSetAttribute(k_conv3x3_mma, cudaFuncAttributeMaxDynamicSharedMemorySize,
                         C3_SMEM);
    k_conv3x3_mma<<<dim3(8, 24, BATCH), 256, C3_SMEM>>>();

    cudaFuncSetAttribute(k_attn_mma, cudaFuncAttributeMaxDynamicSharedMemorySize,
                         ATN_SMEM);
    k_attn_mma<<<dim3(8, HEADS, BATCH), 256, ATN_SMEM>>>();

    cudaFuncSetAttribute(k_conv1x1_mma, cudaFuncAttributeMaxDynamicSharedMemorySize,
                         C1_SMEM);
    k_conv1x1_mma<<<dim3(8, 8, BATCH), 256, C1_SMEM>>>();

    k_bnpartial<<<64, 256>>>();
    k_bnfinal<<<1, DIM>>>(gamma, beta);
    k_bn_relu_t<<<dim3(32, 16, BATCH), dim3(32, 8)>>>(out);
}

// round 16
// speedup vs baseline: 7.5467x; 1.5193x over previous
#include <cuda_runtime.h>
#include <cuda_bf16.h>
#include <cuda_fp16.h>
#include <cstdint>

#define DIM 512
#define THREE_DIM 1536
#define NPIX 1024
#define BATCH 8
#define HEADS 8
#define HD 64
#define SMOOTHF 1e-4f
#define BN_EPSF 1e-5f

// ---------------- scratch (static __device__, no allocation) ----------------
__device__ float g_invqn[BATCH * HEADS * NPIX];
__device__ float g_invkn[BATCH * HEADS * NPIX];
__device__ float g_conv2[BATCH * NPIX * DIM];       // [b][p][c]
__device__ float g_scale[DIM];
__device__ float g_shift[DIM];
__device__ float g_part[2][64][DIM];                // BN partial sums
// fp16 operands for conv3x3 (x rounded once, W rounded once)
__device__ __half g_xHf[BATCH * NPIX * DIM];        // [b][p][ci]
__device__ __half g_WrH[9 * THREE_DIM * DIM];       // [kpos][co][ci]
// fp16 operands for attention (written directly by conv3x3 epilogue)
__device__ __half g_qfhi[64 * NPIX * HD];           // [bg][n][d]  (q * invqn)
__device__ __half g_qflo[64 * NPIX * HD];
__device__ __half g_kf[64 * NPIX * HD];             // [bg][n][d]  (k * invkn)
__device__ __half g_vTf[64 * HD * NPIX];            // [bg][d][n]
// attention output (conv1x1 A operand), fp16 split
__device__ __half g_Afhi[BATCH * NPIX * DIM];       // [b][p][c]
__device__ __half g_Aflo[BATCH * NPIX * DIM];
// conv1x1 weights fp16
__device__ __half g_w2f[DIM * DIM];                 // [co][ci]

// ---------------- helpers ----------------------------------------------------
__device__ __forceinline__ uint32_t s2u(const void* p) {
    uint32_t a;
    asm("{ .reg .u64 t; cvta.to.shared.u64 t, %1; cvt.u32.u64 %0, t; }"
        : "=r"(a) : "l"(p));
    return a;
}
__device__ __forceinline__ void cp_async16(uint32_t saddr, const void* gaddr, int sz) {
    asm volatile("cp.async.cg.shared.global [%0], [%1], 16, %2;"
                 :: "r"(saddr), "l"(gaddr), "r"(sz));
}
__device__ __forceinline__ void cp_commit() {
    asm volatile("cp.async.commit_group;" ::: "memory");
}
__device__ __forceinline__ void cp_wait0() {
    asm volatile("cp.async.wait_group 0;" ::: "memory");
}
__device__ __forceinline__ void ldsm_x4(uint32_t* r, uint32_t addr) {
    asm volatile("ldmatrix.sync.aligned.m8n8.x4.shared.b16 {%0,%1,%2,%3}, [%4];"
                 : "=r"(r[0]), "=r"(r[1]), "=r"(r[2]), "=r"(r[3]) : "r"(addr));
}
__device__ __forceinline__ void mma_fp16(float* d, const uint32_t* a,
                                         const uint32_t* b) {
    asm volatile(
        "mma.sync.aligned.m16n8k16.row.col.f32.f16.f16.f32 "
        "{%0,%1,%2,%3}, {%4,%5,%6,%7}, {%8,%9}, {%0,%1,%2,%3};"
        : "+f"(d[0]), "+f"(d[1]), "+f"(d[2]), "+f"(d[3])
        : "r"(a[0]), "r"(a[1]), "r"(a[2]), "r"(a[3]), "r"(b[0]), "r"(b[1]));
}
__device__ __forceinline__ uint32_t pack_h2(float a, float b) {
    __half2 h = __floats2half2_rn(a, b);
    return *(uint32_t*)&h;
}

// ---------------- prep: x -> [b][p][ci] fp16 ----------------------------------
__global__ void k_prep_x(const float* __restrict__ x) {
    __shared__ float t[32][33];
    int b = blockIdx.z, c0 = blockIdx.y * 32, p0 = blockIdx.x * 32;
    int tx = threadIdx.x, ty = threadIdx.y;  // 32 x 8
    const float* xb = x + ((size_t)b * DIM + c0) * NPIX + p0;
#pragma unroll
    for (int u = 0; u < 4; u++) t[ty + u * 8][tx] = xb[(ty + u * 8) * NPIX + tx];
    __syncthreads();
    size_t ob = ((size_t)b * NPIX + p0) * DIM + c0;
#pragma unroll
    for (int u = 0; u < 4; u++) {
        int p = ty + u * 8;
        g_xHf[ob + (size_t)p * DIM + tx] = __float2half(t[tx][p]);
    }
}

// ---------------- prep: W_qkv -> [kpos][co][ci] fp16 --------------------------
__global__ void k_prep_w(const float* __restrict__ W) {
    __shared__ float s[4608];
    int co = blockIdx.x;
    const float* wr = W + (size_t)co * 4608;
    for (int i = threadIdx.x; i < 4608; i += 256) s[i] = wr[i];
    __syncthreads();
    for (int kpos = 0; kpos < 9; kpos++) {
        size_t ob = ((size_t)kpos * THREE_DIM + co) * DIM;
        for (int ci = threadIdx.x; ci < DIM; ci += 256)
            g_WrH[ob + ci] = __float2half(s[ci * 9 + kpos]);
    }
}

// ---------------- prep: W_out -> fp16 ([co][ci]) ------------------------------
__global__ void k_prep_w2(const float* __restrict__ W) {
    int idx = blockIdx.x * 256 + threadIdx.x;
    if (idx >= DIM * DIM) return;
    g_w2f[idx] = __float2half(W[idx]);
}

// ---------------- conv3x3 single-pass fp16, BM=128 BN=64 BK=128 ---------------
// 36 chunks of (kpos, ci-128-block). Rows are 256B (16 chunks of 16B), XOR
// swizzle ch^(row&7) stays within each 128B half -> conflict-free ldmatrix.
// kind = co-tile/8: 0 -> q (normalize, [n][d] fp16 hi/lo), 1 -> k, 2 -> v.
#define C3_OFF_B 32768
#define C3_STAGE 49152
#define C3_SMEM (2 * C3_STAGE)

__global__ __launch_bounds__(256, 2) void k_conv3x3_mma(void) {
    extern __shared__ char smem[];
    const uint32_t sb = s2u(smem);
    const int tid = threadIdx.x;
    const int wid = tid >> 5, lane = tid & 31;
    const int b = blockIdx.z, p0 = blockIdx.x * 128;
    const int y = blockIdx.y;                // 0..23
    const int co0 = y * 64;
    const int wm = wid >> 1, wn = wid & 1;   // 4 x 2 warps, 32x32 tiles

    float acc[2][4][4];
#pragma unroll
    for (int i = 0; i < 2; i++)
#pragma unroll
        for (int j = 0; j < 4; j++)
#pragma unroll
            for (int q = 0; q < 4; q++) acc[i][j][q] = 0.f;

    auto issue = [&](int c, int buf) {
        int kpos = c >> 2, ci0 = (c & 3) << 7;
        int kh = kpos / 3 - 1, kw = kpos % 3 - 1;
        uint32_t S = sb + buf * C3_STAGE;
#pragma unroll
        for (int u = 0; u < 12; u++) {
            int unit = tid + u * 256;            // 0..3071
            if (unit < 2048) {
                // A: 128 rows x 16 ch (16B each)
                int row = unit >> 4, ch = unit & 15;
                int sw = row * 256 + ((ch ^ (row & 7)) << 4);
                int p = p0 + row;
                int h = (p >> 5) + kh, w = (p & 31) + kw;
                bool valid = ((unsigned)h < 32u) && ((unsigned)w < 32u);
                size_t offA = valid
                    ? (((((size_t)b << 10) + ((h << 5) + w)) << 9) + ci0 + (ch << 3))
                    : 0;
                int sz = valid ? 16 : 0;
                cp_async16(S + sw, (const char*)g_xHf + offA * 2, sz);
            } else {
                // B: 64 rows x 16 ch
                int v2 = unit - 2048;
                int row = v2 >> 4, ch = v2 & 15;
                int sw = row * 256 + ((ch ^ (row & 7)) << 4);
                size_t offB = (((size_t)kpos * THREE_DIM + co0 + row) << 9)
                              + ci0 + (ch << 3);
                cp_async16(S + C3_OFF_B + sw, (const char*)g_WrH + offB * 2, 16);
            }
        }
        cp_commit();
    };

    issue(0, 0);
    for (int c = 0; c < 36; c++) {
        int buf = c & 1;
        cp_wait0();
        __syncthreads();
        if (c + 1 < 36) issue(c + 1, buf ^ 1);

        uint32_t S = sb + buf * C3_STAGE;
        int rowA_lo = wm * 32 + (lane & 15);
        int kc8A = lane >> 4;
        int rowB_lo = wn * 32 + ((lane >> 4) << 3) + (lane & 7);
        int kc8B = (lane >> 3) & 1;
#pragma unroll
        for (int k16 = 0; k16 < 8; k16++) {
            uint32_t ah[2][4], bh[2][4];
#pragma unroll
            for (int mi = 0; mi < 2; mi++) {
                int row = rowA_lo + mi * 16;
                int ch = k16 * 2 + kc8A;
                uint32_t ad = S + row * 256 + ((ch ^ (row & 7)) << 4);
                ldsm_x4(ah[mi], ad);
            }
#pragma unroll
            for (int t = 0; t < 2; t++) {
                int row = rowB_lo + t * 16;
                int ch = k16 * 2 + kc8B;
                uint32_t ad = S + C3_OFF_B + row * 256 + ((ch ^ (row & 7)) << 4);
                ldsm_x4(bh[t], ad);
            }
#pragma unroll
            for (int mi = 0; mi < 2; mi++)
#pragma unroll
                for (int nj = 0; nj < 4; nj++) {
                    const uint32_t* bhf = &bh[nj >> 1][(nj & 1) * 2];
                    mma_fp16(acc[mi][nj], ah[mi], bhf);
                }
        }
    }
    __syncthreads();

    const int kind = y >> 3;         // 0=q 1=k 2=v
    const int g = y & 7;
    const int bg = b * 8 + g;

    if (kind < 2) {
        // ---- fused row-norm over the 64-col head dim ------------------------
        float* ssq = (float*)smem;   // [2][128]
        float pss[2][2];
#pragma unroll
        for (int mi = 0; mi < 2; mi++) {
            float s0 = 0.f, s1 = 0.f;
#pragma unroll
            for (int nj = 0; nj < 4; nj++) {
                float* u = acc[mi][nj];
                s0 = fmaf(u[0], u[0], s0); s0 = fmaf(u[1], u[1], s0);
                s1 = fmaf(u[2], u[2], s1); s1 = fmaf(u[3], u[3], s1);
            }
            pss[mi][0] = s0; pss[mi][1] = s1;
        }
#pragma unroll
        for (int mi = 0; mi < 2; mi++)
#pragma unroll
            for (int hh = 0; hh < 2; hh++) {
                float v = pss[mi][hh];
                v += __shfl_xor_sync(0xffffffffu, v, 1);
                v += __shfl_xor_sync(0xffffffffu, v, 2);
                pss[mi][hh] = v;
            }
        if ((lane & 3) == 0) {
#pragma unroll
            for (int mi = 0; mi < 2; mi++)
#pragma unroll
                for (int hh = 0; hh < 2; hh++) {
                    int row = wm * 32 + mi * 16 + (lane >> 2) + hh * 8;
                    ssq[wn * 128 + row] = pss[mi][hh];
                }
        }
        __syncthreads();
#pragma unroll
        for (int mi = 0; mi < 2; mi++)
#pragma unroll
            for (int hh = 0; hh < 2; hh++) {
                int row = wm * 32 + mi * 16 + (lane >> 2) + hh * 8;
                float inv = rsqrtf(ssq[row] + ssq[128 + row] + SMOOTHF);
                if (wn == 0 && (lane & 3) == 0) {
                    if (kind == 0) g_invqn[(bg << 10) + p0 + row] = inv;
                    else           g_invkn[(bg << 10) + p0 + row] = inv;
                }
#pragma unroll
                for (int nj = 0; nj < 4; nj++) {
                    int col = wn * 32 + nj * 8 + (lane & 3) * 2;
                    float v0 = acc[mi][nj][hh * 2 + 0] * inv;
                    float v1 = acc[mi][nj][hh * 2 + 1] * inv;
                    size_t o = ((size_t)(bg << 10) + p0 + row) * HD + col;
                    if (kind == 0) {
                        __half2 h = __floats2half2_rn(v0, v1);
                        *(uint32_t*)((char*)g_qfhi + o * 2) = *(uint32_t*)&h;
                        *(uint32_t*)((char*)g_qflo + o * 2) =
                            pack_h2(v0 - __half2float(h.x), v1 - __half2float(h.y));
                    } else {
                        *(uint32_t*)((char*)g_kf + o * 2) = pack_h2(v0, v1);
                    }
                }
            }
    } else {
        // ---- v: transpose to [d][n] fp16 ------------------------------------
        float* T = (float*)smem;     // [128][68]
#pragma unroll
        for (int mi = 0; mi < 2; mi++)
#pragma unroll
            for (int nj = 0; nj < 4; nj++) {
                int row = wm * 32 + mi * 16 + (lane >> 2);
                int col = wn * 32 + nj * 8 + (lane & 3) * 2;
                T[row * 68 + col]           = acc[mi][nj][0];
                T[row * 68 + col + 1]       = acc[mi][nj][1];
                T[(row + 8) * 68 + col]     = acc[mi][nj][2];
                T[(row + 8) * 68 + col + 1] = acc[mi][nj][3];
            }
        __syncthreads();
#pragma unroll
        for (int t = 0; t < 8; t++) {
            int cc = wid * 8 + t;    // d within head
            float v0 = T[(lane * 4 + 0) * 68 + cc];
            float v1 = T[(lane * 4 + 1) * 68 + cc];
            float v2 = T[(lane * 4 + 2) * 68 + cc];
            float v3 = T[(lane * 4 + 3) * 68 + cc];
            size_t o = ((size_t)bg * HD + cc) * NPIX + p0 + lane * 4;
            uint32_t* dst = (uint32_t*)((char*)g_vTf + o * 2);
            dst[0] = pack_h2(v0, v1);
            dst[1] = pack_h2(v2, v3);
        }
    }
}

// ---------------- attention via mma.sync fp16 2-term (unchanged, passing) -----
#define ATN_QHI 0
#define ATN_QLO 16384
#define ATN_KH(buf)  (32768 + (buf) * 8192)
#define ATN_VT(buf)  (49152 + (buf) * 8192)
#define ATN_SHI 65536
#define ATN_SLO 81920
#define ATN_IQ 98304
#define ATN_IK 98816                           // + buf*256
#define ATN_SMEM 99328

__global__ __launch_bounds__(256, 2) void k_attn_mma(void) {
    extern __shared__ char smem[];
    const uint32_t sb = s2u(smem);
    const int tid = threadIdx.x, wid = tid >> 5, lane = tid & 31;
    const int i0 = blockIdx.x * 128;
    const int g = blockIdx.y, b = blockIdx.z;
    const int bg = b * 8 + g;
    const int wm = wid & 3, wn = wid >> 2;

#pragma unroll
    for (int u = 0; u < 4; u++) {
        int unit = tid + u * 256;            // 1024: 128 rows x 8 ch
        int row = unit >> 3, ch = unit & 7;
        int sw = row * 128 + ((ch ^ (row & 7)) << 4);
        size_t go = (((size_t)bg << 10) + i0 + row) * 128 + ch * 16;
        cp_async16(sb + ATN_QHI + sw, (const char*)g_qfhi + go, 16);
        cp_async16(sb + ATN_QLO + sw, (const char*)g_qflo + go, 16);
    }
    if (tid < 128)
        ((float*)(smem + ATN_IQ))[tid] = g_invqn[((size_t)bg << 10) + i0 + tid];
    cp_commit();

    auto issueKV = [&](int j0, int buf) {
#pragma unroll
        for (int u = 0; u < 4; u++) {
            int unit = tid + u * 256;        // 1024: 2 tensors x 64 rows x 8 ch
            int sel = unit >> 9;
            int r2 = (unit >> 3) & 63, ch = unit & 7;
            int sw = r2 * 128 + ((ch ^ (r2 & 7)) << 4);
            if (sel == 0) {
                cp_async16(sb + ATN_KH(buf) + sw,
                    (const char*)g_kf + (((size_t)bg << 10) + j0 + r2) * 128 + ch * 16, 16);
            } else {
                cp_async16(sb + ATN_VT(buf) + sw,
                    (const char*)g_vTf + (((size_t)bg * HD + r2) * NPIX + j0) * 2 + ch * 16, 16);
            }
        }
        if (tid < 64)
            ((float*)(smem + ATN_IK + buf * 256))[tid] =
                g_invkn[((size_t)bg << 10) + j0 + tid];
        cp_commit();
    };
    issueKV(0, 0);

    float acco[2][4][4];
#pragma unroll
    for (int i = 0; i < 2; i++)
#pragma unroll
        for (int j = 0; j < 4; j++)
#pragma unroll
            for (int q = 0; q < 4; q++) acco[i][j][q] = 0.f;

    for (int jt = 0; jt < 16; jt++) {
        int buf = jt & 1;
        cp_wait0();
        __syncthreads();
        if (jt < 15) issueKV((jt + 1) * 64, buf ^ 1);

        // ---- S phase ----
        float s[2][4][4];
#pragma unroll
        for (int i = 0; i < 2; i++)
#pragma unroll
            for (int j = 0; j < 4; j++)
#pragma unroll
                for (int q = 0; q < 4; q++) s[i][j][q] = 0.f;
        {
            uint32_t Qh = sb + ATN_QHI, Ql = sb + ATN_QLO;
            uint32_t Kh = sb + ATN_KH(buf);
#pragma unroll
            for (int k16 = 0; k16 < 4; k16++) {
                uint32_t ah[2][4], al[2][4], bh[2][4];
#pragma unroll
                for (int mi = 0; mi < 2; mi++) {
                    int row = wm * 32 + mi * 16 + (lane & 15);
                    int ch = k16 * 2 + (lane >> 4);
                    uint32_t ad = row * 128 + ((ch ^ (row & 7)) << 4);
                    ldsm_x4(ah[mi], Qh + ad);
                    ldsm_x4(al[mi], Ql + ad);
                }
#pragma unroll
                for (int t = 0; t < 2; t++) {
                    int row = wn * 32 + t * 16 + ((lane >> 4) << 3) + (lane & 7);
                    int ch = k16 * 2 + ((lane >> 3) & 1);
                    uint32_t ad = row * 128 + ((ch ^ (row & 7)) << 4);
                    ldsm_x4(bh[t], Kh + ad);
                }
#pragma unroll
                for (int mi = 0; mi < 2; mi++)
#pragma unroll
                    for (int nj = 0; nj < 4; nj++) {
                        const uint32_t* bhf = &bh[nj >> 1][(nj & 1) * 2];
                        mma_fp16(s[mi][nj], ah[mi], bhf);
                        mma_fp16(s[mi][nj], al[mi], bhf);
                    }
            }
        }
        // ---- correction + fp16 split of S into smem ----
        {
            const float* IQ = (const float*)(smem + ATN_IQ);
            const float* IK = (const float*)(smem + ATN_IK + buf * 256);
#pragma unroll
            for (int mi = 0; mi < 2; mi++) {
                int r0 = wm * 32 + mi * 16 + (lane >> 2);
                float iq0 = IQ[r0], iq1 = IQ[r0 + 8];
#pragma unroll
                for (int nj = 0; nj < 4; nj++) {
                    int col = wn * 32 + nj * 8 + (lane & 3) * 2;
                    float ik0 = IK[col], ik1 = IK[col + 1];
                    float* u = s[mi][nj];
                    float t00 = iq0 * ik0, t01 = iq0 * ik1;
                    float t10 = iq1 * ik0, t11 = iq1 * ik1;
                    float v0 = fmaf(-SMOOTHF * t00, u[0], u[0]);
                    float v1 = fmaf(-SMOOTHF * t01, u[1], u[1]);
                    float v2 = fmaf(-SMOOTHF * t10, u[2], u[2]);
                    float v3 = fmaf(-SMOOTHF * t11, u[3], u[3]);
                    __half2 h01 = __floats2half2_rn(v0, v1);
                    __half2 h23 = __floats2half2_rn(v2, v3);
                    float r0f = v0 - __half2float(h01.x);
                    float r1f = v1 - __half2float(h01.y);
                    float r2f = v2 - __half2float(h23.x);
                    float r3f = v3 - __half2float(h23.y);
                    int bo = col * 2;
                    int ch = bo >> 4, wi = bo & 15;
                    int a0 = r0 * 128 + ((ch ^ (r0 & 7)) << 4) + wi;
                    int a1 = (r0 + 8) * 128 + ((ch ^ ((r0 + 8) & 7)) << 4) + wi;
                    *(uint32_t*)(smem + ATN_SHI + a0) = *(uint32_t*)&h01;
                    *(uint32_t*)(smem + ATN_SHI + a1) = *(uint32_t*)&h23;
                    *(uint32_t*)(smem + ATN_SLO + a0) = pack_h2(r0f, r1f);
                    *(uint32_t*)(smem + ATN_SLO + a1) = pack_h2(r2f, r3f);
                }
            }
        }
        __syncthreads();
        // ---- O phase ----
        {
            uint32_t Sh = sb + ATN_SHI, Sl = sb + ATN_SLO;
            uint32_t Vh = sb + ATN_VT(buf);
#pragma unroll
            for (int k16 = 0; k16 < 4; k16++) {
                uint32_t ah[2][4], al[2][4], bh[2][4];
#pragma unroll
                for (int mi = 0; mi < 2; mi++) {
                    int row = wm * 32 + mi * 16 + (lane & 15);
                    int ch = k16 * 2 + (lane >> 4);
                    uint32_t ad = row * 128 + ((ch ^ (row & 7)) << 4);
                    ldsm_x4(ah[mi], Sh + ad);
                    ldsm_x4(al[mi], Sl + ad);
                }
#pragma unroll
                for (int t = 0; t < 2; t++) {
                    int row = wn * 32 + t * 16 + ((lane >> 4) << 3) + (lane & 7);
                    int ch = k16 * 2 + ((lane >> 3) & 1);
                    uint32_t ad = row * 128 + ((ch ^ (row & 7)) << 4);
                    ldsm_x4(bh[t], Vh + ad);
                }
#pragma unroll
                for (int mi = 0; mi < 2; mi++)
#pragma unroll
                    for (int nj = 0; nj < 4; nj++) {
                        const uint32_t* bhf = &bh[nj >> 1][(nj & 1) * 2];
                        mma_fp16(acco[mi][nj], ah[mi], bhf);
                        mma_fp16(acco[mi][nj], al[mi], bhf);
                    }
            }
        }
    }
    // ---- epilogue: O -> fp16 hi/lo at [b][p][c] (conv1x1 A operand) ----------
#pragma unroll
    for (int mi = 0; mi < 2; mi++)
#pragma unroll
        for (int nj = 0; nj < 4; nj++) {
            int row = wm * 32 + mi * 16 + (lane >> 2);
            int col = g * HD + wn * 32 + nj * 8 + (lane & 3) * 2;
            float* u = acco[mi][nj];
            __half2 h01 = __floats2half2_rn(u[0], u[1]);
            __half2 h23 = __floats2half2_rn(u[2], u[3]);
            size_t o0 = (((size_t)b << 10) + i0 + row) * DIM + col;
            size_t o1 = (((size_t)b << 10) + i0 + row + 8) * DIM + col;
            *(uint32_t*)((char*)g_Afhi + o0 * 2) = *(uint32_t*)&h01;
            *(uint32_t*)((char*)g_Afhi + o1 * 2) = *(uint32_t*)&h23;
            *(uint32_t*)((char*)g_Aflo + o0 * 2) =
                pack_h2(u[0] - __half2float(h01.x), u[1] - __half2float(h01.y));
            *(uint32_t*)((char*)g_Aflo + o1 * 2) =
                pack_h2(u[2] - __half2float(h23.x), u[3] - __half2float(h23.y));
        }
}

// ---------------- conv1x1 fp16 2-term (unchanged, passing) --------------------
#define C1_OFF_AHI 0
#define C1_OFF_ALO 16384
#define C1_OFF_BH  32768
#define C1_STAGE 40960
#define C1_SMEM (2 * C1_STAGE)

__global__ __launch_bounds__(256, 2) void k_conv1x1_mma(void) {
    extern __shared__ char smem[];
    const uint32_t sb = s2u(smem);
    const int tid = threadIdx.x;
    const int wid = tid >> 5, lane = tid & 31;
    const int b = blockIdx.z, co0 = blockIdx.y * 64, p0 = blockIdx.x * 128;
    const int wm = wid >> 1, wn = wid & 1;

    float acc[2][4][4];
#pragma unroll
    for (int i = 0; i < 2; i++)
#pragma unroll
        for (int j = 0; j < 4; j++)
#pragma unroll
            for (int q = 0; q < 4; q++) acc[i][j][q] = 0.f;

    auto issue = [&](int c, int buf) {
        int ci0 = c << 6;
        uint32_t S = sb + buf * C1_STAGE;
#pragma unroll
        for (int u = 0; u < 10; u++) {
            int unit = tid + u * 256;
            if (unit < 2048) {
                int sel = unit >> 10;
                int row = (unit >> 3) & 127, ch = unit & 7;
                int sw = row * 128 + ((ch ^ (row & 7)) << 4);
                size_t offA = ((((size_t)b << 10) + p0 + row) << 9) + ci0 + (ch << 3);
                const char* src = sel ? (const char*)g_Aflo : (const char*)g_Afhi;
                cp_async16(S + (sel ? C1_OFF_ALO : C1_OFF_AHI) + sw,
                           src + offA * 2, 16);
            } else {
                int v2 = unit - 2048;
                int row = v2 >> 3, ch = v2 & 7;
                int sw = row * 128 + ((ch ^ (row & 7)) << 4);
                size_t offB = (((size_t)co0 + row) << 9) + ci0 + (ch << 3);
                cp_async16(S + C1_OFF_BH + sw, (const char*)g_w2f + offB * 2, 16);
            }
        }
        cp_commit();
    };

    issue(0, 0);
    for (int c = 0; c < 8; c++) {
        int buf = c & 1;
        cp_wait0();
        __syncthreads();
        if (c + 1 < 8) issue(c + 1, buf ^ 1);

        uint32_t S = sb + buf * C1_STAGE;
        int rowA_lo = wm * 32 + (lane & 15);
        int kc8A = lane >> 4;
        int rowB_lo = wn * 32 + ((lane >> 4) << 3) + (lane & 7);
        int kc8B = (lane >> 3) & 1;
#pragma unroll
        for (int k16 = 0; k16 < 4; k16++) {
            uint32_t ah[2][4], al[2][4], bh[2][4];
#pragma unroll
            for (int mi = 0; mi < 2; mi++) {
                int row = rowA_lo + mi * 16;
                int ch = k16 * 2 + kc8A;
                uint32_t ad = S + row * 128 + ((ch ^ (row & 7)) << 4);
                ldsm_x4(ah[mi], ad + C1_OFF_AHI);
                ldsm_x4(al[mi], ad + C1_OFF_ALO);
            }
#pragma unroll
            for (int t = 0; t < 2; t++) {
                int row = rowB_lo + t * 16;
                int ch = k16 * 2 + kc8B;
                uint32_t ad = S + row * 128 + ((ch ^ (row & 7)) << 4);
                ldsm_x4(bh[t], ad + C1_OFF_BH);
            }
#pragma unroll
            for (int mi = 0; mi < 2; mi++)
#pragma unroll
                for (int nj = 0; nj < 4; nj++) {
                    const uint32_t* bhf = &bh[nj >> 1][(nj & 1) * 2];
                    mma_fp16(acc[mi][nj], ah[mi], bhf);
                    mma_fp16(acc[mi][nj], al[mi], bhf);
                }
        }
    }
#pragma unroll
    for (int mi = 0; mi < 2; mi++)
#pragma unroll
        for (int nj = 0; nj < 4; nj++) {
            int row = wm * 32 + mi * 16 + (lane >> 2);
            int col = wn * 32 + nj * 8 + (lane & 3) * 2;
            float* u = acc[mi][nj];
            size_t o0 = (((size_t)b << 10) + p0 + row) * DIM + co0 + col;
            size_t o1 = o0 + 8 * DIM;
            *(float2*)(g_conv2 + o0) = make_float2(u[0], u[1]);
            *(float2*)(g_conv2 + o1) = make_float2(u[2], u[3]);
        }
}

// ---------------- BN partial sums ---------------------------------------------
__global__ void k_bnpartial(void) {
    int z = blockIdx.x;
    int t = threadIdx.x;
    const float* base = g_conv2 + (size_t)z * 128 * DIM;
    float s1 = 0.f, q1 = 0.f, s2 = 0.f, q2 = 0.f;
    for (int r = 0; r < 128; r++) {
        float a = base[r * DIM + t];
        float c = base[r * DIM + t + 256];
        s1 += a; q1 = fmaf(a, a, q1);
        s2 += c; q2 = fmaf(c, c, q2);
    }
    g_part[0][z][t] = s1;
    g_part[1][z][t] = q1;
    g_part[0][z][t + 256] = s2;
    g_part[1][z][t + 256] = q2;
}

__global__ void k_bnfinal(const float* __restrict__ gamma,
                          const float* __restrict__ beta) {
    int c = threadIdx.x;
    float s = 0.f, s2 = 0.f;
    for (int i = 0; i < 64; i++) { s += g_part[0][i][c]; s2 += g_part[1][i][c]; }
    float mean = s * (1.f / 8192.f);
    float var = s2 * (1.f / 8192.f) - mean * mean;
    float rstd = rsqrtf(var + BN_EPSF);
    float sc = gamma[c] * rstd;
    g_scale[c] = sc;
    g_shift[c] = beta[c] - mean * sc;
}

// ---------------- BN apply + ReLU + transpose ---------------------------------
__global__ void k_bn_relu_t(float* __restrict__ out) {
    __shared__ float t[32][33];
    int p0 = blockIdx.x * 32, c0 = blockIdx.y * 32, b = blockIdx.z;
    int tx = threadIdx.x, ty = threadIdx.y;
#pragma unroll
    for (int u = 0; u < 4; u++) {
        int p = p0 + ty + u * 8;
        t[ty + u * 8][tx] = g_conv2[(((size_t)b << 10) + p) * DIM + c0 + tx];
    }
    __syncthreads();
#pragma unroll
    for (int u = 0; u < 4; u++) {
        int c = c0 + ty + u * 8;
        float v = fmaf(t[tx][ty + u * 8], g_scale[c], g_shift[c]);
        out[((size_t)b * DIM + c) * NPIX + p0 + tx] = v > 0.f ? v : 0.f;
    }
}

// ---------------- launch ------------------------------------------------------
extern "C" void kernel_launch(void* const* d_in, const int* in_sizes, int n_in,
                              void* d_out, int out_size) {
    const float* x      = (const float*)d_in[0];
    const float* W_qkv  = (const float*)d_in[1];
    const float* W_out  = (const float*)d_in[2];
    const float* gamma  = (const float*)d_in[3];
    const float* beta   = (const float*)d_in[4];
    float* out = (float*)d_out;

    k_prep_x<<<dim3(32, 16, BATCH), dim3(32, 8)>>>(x);
    k_prep_w<<<THREE_DIM, 256>>>(W_qkv);
    k_prep_w2<<<(DIM * DIM + 255) / 256, 256>>>(W_out);

    cudaFuncSetAttribute(k_conv3x3_mma, cudaFuncAttributeMaxDynamicSharedMemorySize,
                         C3_SMEM);
    k_conv3x3_mma<<<dim3(8, 24, BATCH), 256, C3_SMEM>>>();

    cudaFuncSetAttribute(k_attn_mma, cudaFuncAttributeMaxDynamicSharedMemorySize,
                         ATN_SMEM);
    k_attn_mma<<<dim3(8, HEADS, BATCH), 256, ATN_SMEM>>>();

    cudaFuncSetAttribute(k_conv1x1_mma, cudaFuncAttributeMaxDynamicSharedMemorySize,
                         C1_SMEM);
    k_conv1x1_mma<<<dim3(8, 8, BATCH), 256, C1_SMEM>>>();

    k_bnpartial<<<64, 256>>>();
    k_bnfinal<<<1, DIM>>>(gamma, beta);
    k_bn_relu_t<<<dim3(32, 16, BATCH), dim3(32, 8)>>>(out);
}

// round 17
// speedup vs baseline: 7.9843x; 1.0580x over previous
#include <cuda_runtime.h>
#include <cuda_bf16.h>
#include <cuda_fp16.h>
#include <cstdint>

#define DIM 512
#define THREE_DIM 1536
#define NPIX 1024
#define BATCH 8
#define HEADS 8
#define HD 64
#define SMOOTHF 1e-4f
#define BN_EPSF 1e-5f

// ---------------- scratch (static __device__, no allocation) ----------------
__device__ float g_invqn[BATCH * HEADS * NPIX];
__device__ float g_invkn[BATCH * HEADS * NPIX];
__device__ float g_conv2[BATCH * NPIX * DIM];       // [b][p][c]
__device__ float g_scale[DIM];
__device__ float g_shift[DIM];
__device__ float g_part[2][64][DIM];                // BN partial sums
// fp16 operands for conv3x3 (x rounded once, W rounded once)
__device__ __half g_xHf[BATCH * NPIX * DIM];        // [b][p][ci]
__device__ __half g_WrH[9 * THREE_DIM * DIM];       // [kpos][co][ci]
// fp16 operands for attention (written directly by conv3x3 epilogue)
__device__ __half g_qfhi[64 * NPIX * HD];           // [bg][n][d]  (q * invqn)
__device__ __half g_qflo[64 * NPIX * HD];
__device__ __half g_kf[64 * NPIX * HD];             // [bg][n][d]  (k * invkn)
__device__ __half g_vTf[64 * HD * NPIX];            // [bg][d][n]
// attention output (conv1x1 A operand), fp16 split
__device__ __half g_Afhi[BATCH * NPIX * DIM];       // [b][p][c]
__device__ __half g_Aflo[BATCH * NPIX * DIM];
// conv1x1 weights fp16
__device__ __half g_w2f[DIM * DIM];                 // [co][ci]

// ---------------- helpers ----------------------------------------------------
__device__ __forceinline__ uint32_t s2u(const void* p) {
    uint32_t a;
    asm("{ .reg .u64 t; cvta.to.shared.u64 t, %1; cvt.u32.u64 %0, t; }"
        : "=r"(a) : "l"(p));
    return a;
}
__device__ __forceinline__ void cp_async16(uint32_t saddr, const void* gaddr, int sz) {
    asm volatile("cp.async.cg.shared.global [%0], [%1], 16, %2;"
                 :: "r"(saddr), "l"(gaddr), "r"(sz));
}
__device__ __forceinline__ void cp_commit() {
    asm volatile("cp.async.commit_group;" ::: "memory");
}
__device__ __forceinline__ void cp_wait0() {
    asm volatile("cp.async.wait_group 0;" ::: "memory");
}
__device__ __forceinline__ void ldsm_x4(uint32_t* r, uint32_t addr) {
    asm volatile("ldmatrix.sync.aligned.m8n8.x4.shared.b16 {%0,%1,%2,%3}, [%4];"
                 : "=r"(r[0]), "=r"(r[1]), "=r"(r[2]), "=r"(r[3]) : "r"(addr));
}
__device__ __forceinline__ void mma_fp16(float* d, const uint32_t* a,
                                         const uint32_t* b) {
    asm volatile(
        "mma.sync.aligned.m16n8k16.row.col.f32.f16.f16.f32 "
        "{%0,%1,%2,%3}, {%4,%5,%6,%7}, {%8,%9}, {%0,%1,%2,%3};"
        : "+f"(d[0]), "+f"(d[1]), "+f"(d[2]), "+f"(d[3])
        : "r"(a[0]), "r"(a[1]), "r"(a[2]), "r"(a[3]), "r"(b[0]), "r"(b[1]));
}
__device__ __forceinline__ uint32_t pack_h2(float a, float b) {
    __half2 h = __floats2half2_rn(a, b);
    return *(uint32_t*)&h;
}

// ---------------- prep: x -> [b][p][ci] fp16 ----------------------------------
__global__ void k_prep_x(const float* __restrict__ x) {
    __shared__ float t[32][33];
    int b = blockIdx.z, c0 = blockIdx.y * 32, p0 = blockIdx.x * 32;
    int tx = threadIdx.x, ty = threadIdx.y;  // 32 x 8
    const float* xb = x + ((size_t)b * DIM + c0) * NPIX + p0;
#pragma unroll
    for (int u = 0; u < 4; u++) t[ty + u * 8][tx] = xb[(ty + u * 8) * NPIX + tx];
    __syncthreads();
    size_t ob = ((size_t)b * NPIX + p0) * DIM + c0;
#pragma unroll
    for (int u = 0; u < 4; u++) {
        int p = ty + u * 8;
        g_xHf[ob + (size_t)p * DIM + tx] = __float2half(t[tx][p]);
    }
}

// ---------------- prep: W_qkv -> [kpos][co][ci] fp16 --------------------------
__global__ void k_prep_w(const float* __restrict__ W) {
    __shared__ float s[4608];
    int co = blockIdx.x;
    const float* wr = W + (size_t)co * 4608;
    for (int i = threadIdx.x; i < 4608; i += 256) s[i] = wr[i];
    __syncthreads();
    for (int kpos = 0; kpos < 9; kpos++) {
        size_t ob = ((size_t)kpos * THREE_DIM + co) * DIM;
        for (int ci = threadIdx.x; ci < DIM; ci += 256)
            g_WrH[ob + ci] = __float2half(s[ci * 9 + kpos]);
    }
}

// ---------------- prep: W_out -> fp16 ([co][ci]) ------------------------------
__global__ void k_prep_w2(const float* __restrict__ W) {
    int idx = blockIdx.x * 256 + threadIdx.x;
    if (idx >= DIM * DIM) return;
    g_w2f[idx] = __float2half(W[idx]);
}

// ---------------- conv3x3 single-pass fp16 (unchanged, passing) ---------------
#define C3_OFF_B 32768
#define C3_STAGE 49152
#define C3_SMEM (2 * C3_STAGE)

__global__ __launch_bounds__(256, 2) void k_conv3x3_mma(void) {
    extern __shared__ char smem[];
    const uint32_t sb = s2u(smem);
    const int tid = threadIdx.x;
    const int wid = tid >> 5, lane = tid & 31;
    const int b = blockIdx.z, p0 = blockIdx.x * 128;
    const int y = blockIdx.y;                // 0..23
    const int co0 = y * 64;
    const int wm = wid >> 1, wn = wid & 1;   // 4 x 2 warps, 32x32 tiles

    float acc[2][4][4];
#pragma unroll
    for (int i = 0; i < 2; i++)
#pragma unroll
        for (int j = 0; j < 4; j++)
#pragma unroll
            for (int q = 0; q < 4; q++) acc[i][j][q] = 0.f;

    auto issue = [&](int c, int buf) {
        int kpos = c >> 2, ci0 = (c & 3) << 7;
        int kh = kpos / 3 - 1, kw = kpos % 3 - 1;
        uint32_t S = sb + buf * C3_STAGE;
#pragma unroll
        for (int u = 0; u < 12; u++) {
            int unit = tid + u * 256;            // 0..3071
            if (unit < 2048) {
                int row = unit >> 4, ch = unit & 15;
                int sw = row * 256 + ((ch ^ (row & 7)) << 4);
                int p = p0 + row;
                int h = (p >> 5) + kh, w = (p & 31) + kw;
                bool valid = ((unsigned)h < 32u) && ((unsigned)w < 32u);
                size_t offA = valid
                    ? (((((size_t)b << 10) + ((h << 5) + w)) << 9) + ci0 + (ch << 3))
                    : 0;
                int sz = valid ? 16 : 0;
                cp_async16(S + sw, (const char*)g_xHf + offA * 2, sz);
            } else {
                int v2 = unit - 2048;
                int row = v2 >> 4, ch = v2 & 15;
                int sw = row * 256 + ((ch ^ (row & 7)) << 4);
                size_t offB = (((size_t)kpos * THREE_DIM + co0 + row) << 9)
                              + ci0 + (ch << 3);
                cp_async16(S + C3_OFF_B + sw, (const char*)g_WrH + offB * 2, 16);
            }
        }
        cp_commit();
    };

    issue(0, 0);
    for (int c = 0; c < 36; c++) {
        int buf = c & 1;
        cp_wait0();
        __syncthreads();
        if (c + 1 < 36) issue(c + 1, buf ^ 1);

        uint32_t S = sb + buf * C3_STAGE;
        int rowA_lo = wm * 32 + (lane & 15);
        int kc8A = lane >> 4;
        int rowB_lo = wn * 32 + ((lane >> 4) << 3) + (lane & 7);
        int kc8B = (lane >> 3) & 1;
#pragma unroll
        for (int k16 = 0; k16 < 8; k16++) {
            uint32_t ah[2][4], bh[2][4];
#pragma unroll
            for (int mi = 0; mi < 2; mi++) {
                int row = rowA_lo + mi * 16;
                int ch = k16 * 2 + kc8A;
                uint32_t ad = S + row * 256 + ((ch ^ (row & 7)) << 4);
                ldsm_x4(ah[mi], ad);
            }
#pragma unroll
            for (int t = 0; t < 2; t++) {
                int row = rowB_lo + t * 16;
                int ch = k16 * 2 + kc8B;
                uint32_t ad = S + C3_OFF_B + row * 256 + ((ch ^ (row & 7)) << 4);
                ldsm_x4(bh[t], ad);
            }
#pragma unroll
            for (int mi = 0; mi < 2; mi++)
#pragma unroll
                for (int nj = 0; nj < 4; nj++) {
                    const uint32_t* bhf = &bh[nj >> 1][(nj & 1) * 2];
                    mma_fp16(acc[mi][nj], ah[mi], bhf);
                }
        }
    }
    __syncthreads();

    const int kind = y >> 3;         // 0=q 1=k 2=v
    const int g = y & 7;
    const int bg = b * 8 + g;

    if (kind < 2) {
        float* ssq = (float*)smem;   // [2][128]
        float pss[2][2];
#pragma unroll
        for (int mi = 0; mi < 2; mi++) {
            float s0 = 0.f, s1 = 0.f;
#pragma unroll
            for (int nj = 0; nj < 4; nj++) {
                float* u = acc[mi][nj];
                s0 = fmaf(u[0], u[0], s0); s0 = fmaf(u[1], u[1], s0);
                s1 = fmaf(u[2], u[2], s1); s1 = fmaf(u[3], u[3], s1);
            }
            pss[mi][0] = s0; pss[mi][1] = s1;
        }
#pragma unroll
        for (int mi = 0; mi < 2; mi++)
#pragma unroll
            for (int hh = 0; hh < 2; hh++) {
                float v = pss[mi][hh];
                v += __shfl_xor_sync(0xffffffffu, v, 1);
                v += __shfl_xor_sync(0xffffffffu, v, 2);
                pss[mi][hh] = v;
            }
        if ((lane & 3) == 0) {
#pragma unroll
            for (int mi = 0; mi < 2; mi++)
#pragma unroll
                for (int hh = 0; hh < 2; hh++) {
                    int row = wm * 32 + mi * 16 + (lane >> 2) + hh * 8;
                    ssq[wn * 128 + row] = pss[mi][hh];
                }
        }
        __syncthreads();
#pragma unroll
        for (int mi = 0; mi < 2; mi++)
#pragma unroll
            for (int hh = 0; hh < 2; hh++) {
                int row = wm * 32 + mi * 16 + (lane >> 2) + hh * 8;
                float inv = rsqrtf(ssq[row] + ssq[128 + row] + SMOOTHF);
                if (wn == 0 && (lane & 3) == 0) {
                    if (kind == 0) g_invqn[(bg << 10) + p0 + row] = inv;
                    else           g_invkn[(bg << 10) + p0 + row] = inv;
                }
#pragma unroll
                for (int nj = 0; nj < 4; nj++) {
                    int col = wn * 32 + nj * 8 + (lane & 3) * 2;
                    float v0 = acc[mi][nj][hh * 2 + 0] * inv;
                    float v1 = acc[mi][nj][hh * 2 + 1] * inv;
                    size_t o = ((size_t)(bg << 10) + p0 + row) * HD + col;
                    if (kind == 0) {
                        __half2 h = __floats2half2_rn(v0, v1);
                        *(uint32_t*)((char*)g_qfhi + o * 2) = *(uint32_t*)&h;
                        *(uint32_t*)((char*)g_qflo + o * 2) =
                            pack_h2(v0 - __half2float(h.x), v1 - __half2float(h.y));
                    } else {
                        *(uint32_t*)((char*)g_kf + o * 2) = pack_h2(v0, v1);
                    }
                }
            }
    } else {
        float* T = (float*)smem;     // [128][68]
#pragma unroll
        for (int mi = 0; mi < 2; mi++)
#pragma unroll
            for (int nj = 0; nj < 4; nj++) {
                int row = wm * 32 + mi * 16 + (lane >> 2);
                int col = wn * 32 + nj * 8 + (lane & 3) * 2;
                T[row * 68 + col]           = acc[mi][nj][0];
                T[row * 68 + col + 1]       = acc[mi][nj][1];
                T[(row + 8) * 68 + col]     = acc[mi][nj][2];
                T[(row + 8) * 68 + col + 1] = acc[mi][nj][3];
            }
        __syncthreads();
#pragma unroll
        for (int t = 0; t < 8; t++) {
            int cc = wid * 8 + t;
            float v0 = T[(lane * 4 + 0) * 68 + cc];
            float v1 = T[(lane * 4 + 1) * 68 + cc];
            float v2 = T[(lane * 4 + 2) * 68 + cc];
            float v3 = T[(lane * 4 + 3) * 68 + cc];
            size_t o = ((size_t)bg * HD + cc) * NPIX + p0 + lane * 4;
            uint32_t* dst = (uint32_t*)((char*)g_vTf + o * 2);
            dst[0] = pack_h2(v0, v1);
            dst[1] = pack_h2(v2, v3);
        }
    }
}

// ---------------- attention: S single fp16 (q hi/lo kept) ---------------------
#define ATN_QHI 0
#define ATN_QLO 16384
#define ATN_KH(buf)  (32768 + (buf) * 8192)
#define ATN_VT(buf)  (49152 + (buf) * 8192)
#define ATN_SHI 65536
#define ATN_IQ 81920
#define ATN_IK 82432                           // + buf*256
#define ATN_SMEM 82944

__global__ __launch_bounds__(256, 2) void k_attn_mma(void) {
    extern __shared__ char smem[];
    const uint32_t sb = s2u(smem);
    const int tid = threadIdx.x, wid = tid >> 5, lane = tid & 31;
    const int i0 = blockIdx.x * 128;
    const int g = blockIdx.y, b = blockIdx.z;
    const int bg = b * 8 + g;
    const int wm = wid & 3, wn = wid >> 2;

#pragma unroll
    for (int u = 0; u < 4; u++) {
        int unit = tid + u * 256;            // 1024: 128 rows x 8 ch
        int row = unit >> 3, ch = unit & 7;
        int sw = row * 128 + ((ch ^ (row & 7)) << 4);
        size_t go = (((size_t)bg << 10) + i0 + row) * 128 + ch * 16;
        cp_async16(sb + ATN_QHI + sw, (const char*)g_qfhi + go, 16);
        cp_async16(sb + ATN_QLO + sw, (const char*)g_qflo + go, 16);
    }
    if (tid < 128)
        ((float*)(smem + ATN_IQ))[tid] = g_invqn[((size_t)bg << 10) + i0 + tid];
    cp_commit();

    auto issueKV = [&](int j0, int buf) {
#pragma unroll
        for (int u = 0; u < 4; u++) {
            int unit = tid + u * 256;        // 1024: 2 tensors x 64 rows x 8 ch
            int sel = unit >> 9;
            int r2 = (unit >> 3) & 63, ch = unit & 7;
            int sw = r2 * 128 + ((ch ^ (r2 & 7)) << 4);
            if (sel == 0) {
                cp_async16(sb + ATN_KH(buf) + sw,
                    (const char*)g_kf + (((size_t)bg << 10) + j0 + r2) * 128 + ch * 16, 16);
            } else {
                cp_async16(sb + ATN_VT(buf) + sw,
                    (const char*)g_vTf + (((size_t)bg * HD + r2) * NPIX + j0) * 2 + ch * 16, 16);
            }
        }
        if (tid < 64)
            ((float*)(smem + ATN_IK + buf * 256))[tid] =
                g_invkn[((size_t)bg << 10) + j0 + tid];
        cp_commit();
    };
    issueKV(0, 0);

    float acco[2][4][4];
#pragma unroll
    for (int i = 0; i < 2; i++)
#pragma unroll
        for (int j = 0; j < 4; j++)
#pragma unroll
            for (int q = 0; q < 4; q++) acco[i][j][q] = 0.f;

    for (int jt = 0; jt < 16; jt++) {
        int buf = jt & 1;
        cp_wait0();
        __syncthreads();
        if (jt < 15) issueKV((jt + 1) * 64, buf ^ 1);

        // ---- S phase: 2-term (q hi/lo) ----
        float s[2][4][4];
#pragma unroll
        for (int i = 0; i < 2; i++)
#pragma unroll
            for (int j = 0; j < 4; j++)
#pragma unroll
                for (int q = 0; q < 4; q++) s[i][j][q] = 0.f;
        {
            uint32_t Qh = sb + ATN_QHI, Ql = sb + ATN_QLO;
            uint32_t Kh = sb + ATN_KH(buf);
#pragma unroll
            for (int k16 = 0; k16 < 4; k16++) {
                uint32_t ah[2][4], al[2][4], bh[2][4];
#pragma unroll
                for (int mi = 0; mi < 2; mi++) {
                    int row = wm * 32 + mi * 16 + (lane & 15);
                    int ch = k16 * 2 + (lane >> 4);
                    uint32_t ad = row * 128 + ((ch ^ (row & 7)) << 4);
                    ldsm_x4(ah[mi], Qh + ad);
                    ldsm_x4(al[mi], Ql + ad);
                }
#pragma unroll
                for (int t = 0; t < 2; t++) {
                    int row = wn * 32 + t * 16 + ((lane >> 4) << 3) + (lane & 7);
                    int ch = k16 * 2 + ((lane >> 3) & 1);
                    uint32_t ad = row * 128 + ((ch ^ (row & 7)) << 4);
                    ldsm_x4(bh[t], Kh + ad);
                }
#pragma unroll
                for (int mi = 0; mi < 2; mi++)
#pragma unroll
                    for (int nj = 0; nj < 4; nj++) {
                        const uint32_t* bhf = &bh[nj >> 1][(nj & 1) * 2];
                        mma_fp16(s[mi][nj], ah[mi], bhf);
                        mma_fp16(s[mi][nj], al[mi], bhf);
                    }
            }
        }
        // ---- correction + single-fp16 S into smem ----
        {
            const float* IQ = (const float*)(smem + ATN_IQ);
            const float* IK = (const float*)(smem + ATN_IK + buf * 256);
#pragma unroll
            for (int mi = 0; mi < 2; mi++) {
                int r0 = wm * 32 + mi * 16 + (lane >> 2);
                float iq0 = IQ[r0], iq1 = IQ[r0 + 8];
#pragma unroll
                for (int nj = 0; nj < 4; nj++) {
                    int col = wn * 32 + nj * 8 + (lane & 3) * 2;
                    float ik0 = IK[col], ik1 = IK[col + 1];
                    float* u = s[mi][nj];
                    float t00 = iq0 * ik0, t01 = iq0 * ik1;
                    float t10 = iq1 * ik0, t11 = iq1 * ik1;
                    float v0 = fmaf(-SMOOTHF * t00, u[0], u[0]);
                    float v1 = fmaf(-SMOOTHF * t01, u[1], u[1]);
                    float v2 = fmaf(-SMOOTHF * t10, u[2], u[2]);
                    float v3 = fmaf(-SMOOTHF * t11, u[3], u[3]);
                    int bo = col * 2;
                    int ch = bo >> 4, wi = bo & 15;
                    int a0 = r0 * 128 + ((ch ^ (r0 & 7)) << 4) + wi;
                    int a1 = (r0 + 8) * 128 + ((ch ^ ((r0 + 8) & 7)) << 4) + wi;
                    *(uint32_t*)(smem + ATN_SHI + a0) = pack_h2(v0, v1);
                    *(uint32_t*)(smem + ATN_SHI + a1) = pack_h2(v2, v3);
                }
            }
        }
        __syncthreads();
        // ---- O phase: single-term S ----
        {
            uint32_t Sh = sb + ATN_SHI;
            uint32_t Vh = sb + ATN_VT(buf);
#pragma unroll
            for (int k16 = 0; k16 < 4; k16++) {
                uint32_t ah[2][4], bh[2][4];
#pragma unroll
                for (int mi = 0; mi < 2; mi++) {
                    int row = wm * 32 + mi * 16 + (lane & 15);
                    int ch = k16 * 2 + (lane >> 4);
                    uint32_t ad = row * 128 + ((ch ^ (row & 7)) << 4);
                    ldsm_x4(ah[mi], Sh + ad);
                }
#pragma unroll
                for (int t = 0; t < 2; t++) {
                    int row = wn * 32 + t * 16 + ((lane >> 4) << 3) + (lane & 7);
                    int ch = k16 * 2 + ((lane >> 3) & 1);
                    uint32_t ad = row * 128 + ((ch ^ (row & 7)) << 4);
                    ldsm_x4(bh[t], Vh + ad);
                }
#pragma unroll
                for (int mi = 0; mi < 2; mi++)
#pragma unroll
                    for (int nj = 0; nj < 4; nj++) {
                        const uint32_t* bhf = &bh[nj >> 1][(nj & 1) * 2];
                        mma_fp16(acco[mi][nj], ah[mi], bhf);
                    }
            }
        }
    }
    // ---- epilogue: O -> fp16 hi/lo at [b][p][c] ----
#pragma unroll
    for (int mi = 0; mi < 2; mi++)
#pragma unroll
        for (int nj = 0; nj < 4; nj++) {
            int row = wm * 32 + mi * 16 + (lane >> 2);
            int col = g * HD + wn * 32 + nj * 8 + (lane & 3) * 2;
            float* u = acco[mi][nj];
            __half2 h01 = __floats2half2_rn(u[0], u[1]);
            __half2 h23 = __floats2half2_rn(u[2], u[3]);
            size_t o0 = (((size_t)b << 10) + i0 + row) * DIM + col;
            size_t o1 = (((size_t)b << 10) + i0 + row + 8) * DIM + col;
            *(uint32_t*)((char*)g_Afhi + o0 * 2) = *(uint32_t*)&h01;
            *(uint32_t*)((char*)g_Afhi + o1 * 2) = *(uint32_t*)&h23;
            *(uint32_t*)((char*)g_Aflo + o0 * 2) =
                pack_h2(u[0] - __half2float(h01.x), u[1] - __half2float(h01.y));
            *(uint32_t*)((char*)g_Aflo + o1 * 2) =
                pack_h2(u[2] - __half2float(h23.x), u[3] - __half2float(h23.y));
        }
}

// ---------------- conv1x1 fp16 2-term + fused BN partial sums -----------------
#define C1_OFF_AHI 0
#define C1_OFF_ALO 16384
#define C1_OFF_BH  32768
#define C1_STAGE 40960
#define C1_SMEM (2 * C1_STAGE)

__global__ __launch_bounds__(256, 2) void k_conv1x1_mma(void) {
    extern __shared__ char smem[];
    const uint32_t sb = s2u(smem);
    const int tid = threadIdx.x;
    const int wid = tid >> 5, lane = tid & 31;
    const int b = blockIdx.z, co0 = blockIdx.y * 64, p0 = blockIdx.x * 128;
    const int wm = wid >> 1, wn = wid & 1;

    float acc[2][4][4];
#pragma unroll
    for (int i = 0; i < 2; i++)
#pragma unroll
        for (int j = 0; j < 4; j++)
#pragma unroll
            for (int q = 0; q < 4; q++) acc[i][j][q] = 0.f;

    auto issue = [&](int c, int buf) {
        int ci0 = c << 6;
        uint32_t S = sb + buf * C1_STAGE;
#pragma unroll
        for (int u = 0; u < 10; u++) {
            int unit = tid + u * 256;
            if (unit < 2048) {
                int sel = unit >> 10;
                int row = (unit >> 3) & 127, ch = unit & 7;
                int sw = row * 128 + ((ch ^ (row & 7)) << 4);
                size_t offA = ((((size_t)b << 10) + p0 + row) << 9) + ci0 + (ch << 3);
                const char* src = sel ? (const char*)g_Aflo : (const char*)g_Afhi;
                cp_async16(S + (sel ? C1_OFF_ALO : C1_OFF_AHI) + sw,
                           src + offA * 2, 16);
            } else {
                int v2 = unit - 2048;
                int row = v2 >> 3, ch = v2 & 7;
                int sw = row * 128 + ((ch ^ (row & 7)) << 4);
                size_t offB = (((size_t)co0 + row) << 9) + ci0 + (ch << 3);
                cp_async16(S + C1_OFF_BH + sw, (const char*)g_w2f + offB * 2, 16);
            }
        }
        cp_commit();
    };

    issue(0, 0);
    for (int c = 0; c < 8; c++) {
        int buf = c & 1;
        cp_wait0();
        __syncthreads();
        if (c + 1 < 8) issue(c + 1, buf ^ 1);

        uint32_t S = sb + buf * C1_STAGE;
        int rowA_lo = wm * 32 + (lane & 15);
        int kc8A = lane >> 4;
        int rowB_lo = wn * 32 + ((lane >> 4) << 3) + (lane & 7);
        int kc8B = (lane >> 3) & 1;
#pragma unroll
        for (int k16 = 0; k16 < 4; k16++) {
            uint32_t ah[2][4], al[2][4], bh[2][4];
#pragma unroll
            for (int mi = 0; mi < 2; mi++) {
                int row = rowA_lo + mi * 16;
                int ch = k16 * 2 + kc8A;
                uint32_t ad = S + row * 128 + ((ch ^ (row & 7)) << 4);
                ldsm_x4(ah[mi], ad + C1_OFF_AHI);
                ldsm_x4(al[mi], ad + C1_OFF_ALO);
            }
#pragma unroll
            for (int t = 0; t < 2; t++) {
                int row = rowB_lo + t * 16;
                int ch = k16 * 2 + kc8B;
                uint32_t ad = S + row * 128 + ((ch ^ (row & 7)) << 4);
                ldsm_x4(bh[t], ad + C1_OFF_BH);
            }
#pragma unroll
            for (int mi = 0; mi < 2; mi++)
#pragma unroll
                for (int nj = 0; nj < 4; nj++) {
                    const uint32_t* bhf = &bh[nj >> 1][(nj & 1) * 2];
                    mma_fp16(acc[mi][nj], ah[mi], bhf);
                    mma_fp16(acc[mi][nj], al[mi], bhf);
                }
        }
    }
    // ---- write C[p][co] to g_conv2 [b][p][c] --------------------------------
#pragma unroll
    for (int mi = 0; mi < 2; mi++)
#pragma unroll
        for (int nj = 0; nj < 4; nj++) {
            int row = wm * 32 + mi * 16 + (lane >> 2);
            int col = wn * 32 + nj * 8 + (lane & 3) * 2;
            float* u = acc[mi][nj];
            size_t o0 = (((size_t)b << 10) + p0 + row) * DIM + co0 + col;
            size_t o1 = o0 + 8 * DIM;
            *(float2*)(g_conv2 + o0) = make_float2(u[0], u[1]);
            *(float2*)(g_conv2 + o1) = make_float2(u[2], u[3]);
        }

    // ---- fused BN partial sums (deterministic) ------------------------------
    // This CTA covers z = b*8 + blockIdx.x (128 rows) x channels [co0, co0+64).
    __syncthreads();                    // stage smem reuse
    float* sred = (float*)smem;         // [4 wm][64 col][2]
    float s_[4][2], q_[4][2];
#pragma unroll
    for (int nj = 0; nj < 4; nj++) {
        float sa = 0.f, qa = 0.f, sb2 = 0.f, qb = 0.f;
#pragma unroll
        for (int mi = 0; mi < 2; mi++) {
            float* u = acc[mi][nj];
            sa += u[0] + u[2];
            qa = fmaf(u[0], u[0], qa); qa = fmaf(u[2], u[2], qa);
            sb2 += u[1] + u[3];
            qb = fmaf(u[1], u[1], qb); qb = fmaf(u[3], u[3], qb);
        }
        s_[nj][0] = sa; q_[nj][0] = qa;
        s_[nj][1] = sb2; q_[nj][1] = qb;
    }
#pragma unroll
    for (int off = 4; off <= 16; off <<= 1)
#pragma unroll
        for (int nj = 0; nj < 4; nj++)
#pragma unroll
            for (int cp = 0; cp < 2; cp++) {
                s_[nj][cp] += __shfl_down_sync(0xffffffffu, s_[nj][cp], off);
                q_[nj][cp] += __shfl_down_sync(0xffffffffu, q_[nj][cp], off);
            }
    if (lane < 4) {
#pragma unroll
        for (int nj = 0; nj < 4; nj++)
#pragma unroll
            for (int cp = 0; cp < 2; cp++) {
                int col = wn * 32 + nj * 8 + lane * 2 + cp;
                sred[(wm * 64 + col) * 2 + 0] = s_[nj][cp];
                sred[(wm * 64 + col) * 2 + 1] = q_[nj][cp];
            }
    }
    __syncthreads();
    if (tid < 64) {
        float ts = 0.f, tq = 0.f;
#pragma unroll
        for (int w = 0; w < 4; w++) {
            ts += sred[(w * 64 + tid) * 2 + 0];
            tq += sred[(w * 64 + tid) * 2 + 1];
        }
        int z = b * 8 + blockIdx.x;
        g_part[0][z][co0 + tid] = ts;
        g_part[1][z][co0 + tid] = tq;
    }
}

// ---------------- BN final ------------------------------------------------------
__global__ void k_bnfinal(const float* __restrict__ gamma,
                          const float* __restrict__ beta) {
    int c = threadIdx.x;
    float s = 0.f, s2 = 0.f;
    for (int i = 0; i < 64; i++) { s += g_part[0][i][c]; s2 += g_part[1][i][c]; }
    float mean = s * (1.f / 8192.f);
    float var = s2 * (1.f / 8192.f) - mean * mean;
    float rstd = rsqrtf(var + BN_EPSF);
    float sc = gamma[c] * rstd;
    g_scale[c] = sc;
    g_shift[c] = beta[c] - mean * sc;
}

// ---------------- BN apply + ReLU + transpose ---------------------------------
__global__ void k_bn_relu_t(float* __restrict__ out) {
    __shared__ float t[32][33];
    int p0 = blockIdx.x * 32, c0 = blockIdx.y * 32, b = blockIdx.z;
    int tx = threadIdx.x, ty = threadIdx.y;
#pragma unroll
    for (int u = 0; u < 4; u++) {
        int p = p0 + ty + u * 8;
        t[ty + u * 8][tx] = g_conv2[(((size_t)b << 10) + p) * DIM + c0 + tx];
    }
    __syncthreads();
#pragma unroll
    for (int u = 0; u < 4; u++) {
        int c = c0 + ty + u * 8;
        float v = fmaf(t[tx][ty + u * 8], g_scale[c], g_shift[c]);
        out[((size_t)b * DIM + c) * NPIX + p0 + tx] = v > 0.f ? v : 0.f;
    }
}

// ---------------- launch ------------------------------------------------------
extern "C" void kernel_launch(void* const* d_in, const int* in_sizes, int n_in,
                              void* d_out, int out_size) {
    const float* x      = (const float*)d_in[0];
    const float* W_qkv  = (const float*)d_in[1];
    const float* W_out  = (const float*)d_in[2];
    const float* gamma  = (const float*)d_in[3];
    const float* beta   = (const float*)d_in[4];
    float* out = (float*)d_out;

    k_prep_x<<<dim3(32, 16, BATCH), dim3(32, 8)>>>(x);
    k_prep_w<<<THREE_DIM, 256>>>(W_qkv);
    k_prep_w2<<<(DIM * DIM + 255) / 256, 256>>>(W_out);

    cudaFuncSetAttribute(k_conv3x3_mma, cudaFuncAttributeMaxDynamicSharedMemorySize,
                         C3_SMEM);
    k_conv3x3_mma<<<dim3(8, 24, BATCH), 256, C3_SMEM>>>();

    cudaFuncSetAttribute(k_attn_mma, cudaFuncAttributeMaxDynamicSharedMemorySize,
                         ATN_SMEM);
    k_attn_mma<<<dim3(8, HEADS, BATCH), 256, ATN_SMEM>>>();

    cudaFuncSetAttribute(k_conv1x1_mma, cudaFuncAttributeMaxDynamicSharedMemorySize,
                         C1_SMEM);
    k_conv1x1_mma<<<dim3(8, 8, BATCH), 256, C1_SMEM>>>();

    k_bnfinal<<<1, DIM>>>(gamma, beta);
    k_bn_relu_t<<<dim3(32, 16, BATCH), dim3(32, 8)>>>(out);
}